// round 13
// baseline (speedup 1.0000x reference)
#include <cuda_runtime.h>
#include <cuda_bf16.h>
#include <cuda_fp16.h>
#include <math.h>
#include <stdint.h>

// ---------------- problem constants ----------------
#define QLEN   4096
#define NFR    6
#define GRP    8
#define DIMC   256
#define HEADS  4
#define NKEY   48
#define R_TOT  (NFR*QLEN)
#define EPSLN  1e-5f
#define SCALE  0.125f

// ---------------- scratch ----------------
__device__ uint32_t g_qlnh[R_TOT*128], g_qlnl[R_TOT*128];
__device__ uint32_t g_qph [R_TOT*128], g_qpl [R_TOT*128];
__device__ __half   g_t   [R_TOT*1024];
__device__ uint32_t g_apreh[QLEN*512], g_aprel[QLEN*512];
__device__ float    g_zp  [QLEN*DIMC];
__device__ float    g_zln [QLEN*DIMC];
__device__ uint32_t g_zlnh[QLEN*128], g_zlnl[QLEN*128];
__device__ uint32_t g_h1h [QLEN*256], g_h1l [QLEN*256];
__device__ float    g_hp  [QLEN*DIMC];
__device__ float    g_maskf[R_TOT];
__device__ uint32_t g_pwq_h[256*128],  g_pwq_l[256*128];
__device__ uint32_t g_pwk_h[4*256*32], g_pwk_l[4*256*32];
__device__ uint32_t g_pw1_h[512*128],  g_pw1_l[512*128];
__device__ uint32_t g_pw2_h[256*256],  g_pw2_l[256*256];
// fused wv@w_proj weight (B^T layout [c][512 pairs]) + bias
__device__ uint32_t g_pvp_h[256*512],  g_pvp_l[256*512];
__device__ float    g_biasvp[256];

// ---------------- helpers ----------------
__device__ __forceinline__ void blockReduce2(float& s1, float& s2, float* red)
{
    int lane = threadIdx.x & 31, w = threadIdx.x >> 5;
#pragma unroll
    for (int o = 16; o > 0; o >>= 1) {
        s1 += __shfl_xor_sync(0xffffffffu, s1, o);
        s2 += __shfl_xor_sync(0xffffffffu, s2, o);
    }
    if (lane == 0) { red[w] = s1; red[8 + w] = s2; }
    __syncthreads();
    float a = 0.f, b = 0.f;
#pragma unroll
    for (int j = 0; j < 8; j++) { a += red[j]; b += red[8 + j]; }
    s1 = a; s2 = b;
    __syncthreads();
}

__device__ __forceinline__ uint32_t pack_hi(float x0, float x1)
{
    __nv_bfloat162 h = __floats2bfloat162_rn(x0, x1);
    return *reinterpret_cast<uint32_t*>(&h);
}
__device__ __forceinline__ uint32_t pack_lo(float x0, float x1, uint32_t hi)
{
    __nv_bfloat162 h = *reinterpret_cast<__nv_bfloat162*>(&hi);
    float r0 = x0 - __bfloat162float(h.x);
    float r1 = x1 - __bfloat162float(h.y);
    __nv_bfloat162 l = __floats2bfloat162_rn(r0, r1);
    return *reinterpret_cast<uint32_t*>(&l);
}

__device__ __forceinline__ void mma16(float* c, const uint32_t* a, const uint32_t b0, const uint32_t b1)
{
    asm volatile(
        "mma.sync.aligned.m16n8k16.row.col.f32.bf16.bf16.f32 "
        "{%0,%1,%2,%3}, {%4,%5,%6,%7}, {%8,%9}, {%0,%1,%2,%3};"
        : "+f"(c[0]), "+f"(c[1]), "+f"(c[2]), "+f"(c[3])
        : "r"(a[0]), "r"(a[1]), "r"(a[2]), "r"(a[3]), "r"(b0), "r"(b1));
}

__device__ __forceinline__ void ldsm_x4(uint32_t* r, uint32_t saddr)
{
    asm volatile("ldmatrix.sync.aligned.m8n8.x4.shared.b16 {%0,%1,%2,%3}, [%4];"
                 : "=r"(r[0]), "=r"(r[1]), "=r"(r[2]), "=r"(r[3]) : "r"(saddr));
}

__device__ __forceinline__ uint32_t smem_u32(const void* p)
{
    uint32_t a;
    asm("{ .reg .u64 t; cvta.to.shared.u64 t, %1; cvt.u32.u64 %0, t; }" : "=r"(a) : "l"(p));
    return a;
}

__device__ __forceinline__ void cp16(uint32_t dst, const void* src, bool pred)
{
    int sz = pred ? 16 : 0;
    asm volatile("cp.async.cg.shared.global [%0], [%1], 16, %2;"
                 :: "r"(dst), "l"(src), "r"(sz) : "memory");
}

// ---------------- K0: mask detect + normalize ----------------
__global__ void k_mask(const unsigned char* __restrict__ m8)
{
    __shared__ int fA, fB;
    if (threadIdx.x == 0) { fA = 0; fB = 0; }
    __syncthreads();
    for (int i = threadIdx.x; i < NFR * QLEN; i += 256) {
        unsigned char b = m8[i];
        if (b == 1) {
            if ((i & 3) == 0) fA = 1;
            else              fB = 1;
        }
    }
    __syncthreads();
    int mode = fB ? 0 : (fA ? 1 : 2);
    for (int i = threadIdx.x; i < NFR * QLEN; i += 256) {
        float r;
        if (mode == 0)      r = (m8[i] != 0) ? 1.f : 0.f;
        else if (mode == 1) r = (((const int*)m8)[i] != 0) ? 1.f : 0.f;
        else                r = (((const float*)m8)[i] != 0.f) ? 1.f : 0.f;
        g_maskf[i] = r;
    }
}

// ---------------- K1: transpose q + LayerNorm -> packed pairs ----------------
__global__ __launch_bounds__(256)
void k_q_ln(const float* __restrict__ q, const float* __restrict__ g,
            const float* __restrict__ b)
{
    __shared__ float tile[256][33];
    __shared__ float s_mu[32], s_rs[32];
    __shared__ float s_part[2][8][32];
    int n  = blockIdx.y;
    int p0 = blockIdx.x * 32;
    int t  = threadIdx.x;
    int px = t & 31, cy = t >> 5;
    const float* qn = q + (size_t)n * DIMC * QLEN;
    float s1 = 0.f, s2 = 0.f;
    for (int c = cy; c < DIMC; c += 8) {
        float v = qn[(size_t)c * QLEN + p0 + px];
        tile[c][px] = v;
        s1 += v; s2 += v * v;
    }
    s_part[0][cy][px] = s1; s_part[1][cy][px] = s2;
    __syncthreads();
    if (cy == 0) {
        float a = 0.f, bb = 0.f;
#pragma unroll
        for (int j = 0; j < 8; j++) { a += s_part[0][j][px]; bb += s_part[1][j][px]; }
        float mu = a * (1.f / 256.f);
        float var = bb * (1.f / 256.f) - mu * mu;
        s_mu[px] = mu; s_rs[px] = rsqrtf(var + EPSLN);
    }
    __syncthreads();
    float gg = g[t], bv = b[t];
    size_t rbase = (size_t)n * QLEN + p0;
#pragma unroll 4
    for (int pp = 0; pp < 32; pp++) {
        float val = (tile[t][pp] - s_mu[pp]) * s_rs[pp] * gg + bv;
        float vo = __shfl_down_sync(0xffffffffu, val, 1);
        if (!(t & 1)) {
            uint32_t h = pack_hi(val, vo);
            size_t o = (rbase + pp) * 128 + (t >> 1);
            g_qlnh[o] = h;
            g_qlnl[o] = pack_lo(val, vo, h);
        }
    }
}

// ---------------- K2: pack wq/wk/w_mlp1/w_mlp2 (196608 elems = 768 blocks) ----------------
__global__ __launch_bounds__(256)
void k_pack_all(const float* __restrict__ wq, const float* __restrict__ wk,
                const float* __restrict__ w1, const float* __restrict__ w2)
{
    long i = (long)blockIdx.x * 256 + threadIdx.x;
    if (i >= 196608) return;
    const float* src; int sn, sk; long zo; int N, Kp; uint32_t *dh, *dl; long rem;
    if (i < 32768)       { rem = i;          src = wq; sn = 1;   sk = 256; zo = 0;  N = 256; Kp = 128; dh = g_pwq_h; dl = g_pwq_l; }
    else if (i < 65536)  { rem = i - 32768;  src = wk; sn = 256; sk = 1;   zo = 64; N = 256; Kp = 32;  dh = g_pwk_h; dl = g_pwk_l; }
    else if (i < 131072) { rem = i - 65536;  src = w1; sn = 1;   sk = 512; zo = 0;  N = 512; Kp = 128; dh = g_pw1_h; dl = g_pw1_l; }
    else                 { rem = i - 131072; src = w2; sn = 1;   sk = 256; zo = 0;  N = 256; Kp = 256; dh = g_pw2_h; dl = g_pw2_l; }
    long NK = (long)N * Kp;
    long z = rem / NK, j = rem - z * NK;
    int n = (int)(j / Kp), kp = (int)(j - (long)n * Kp);
    const float* s = src + z * zo;
    float x0 = s[(size_t)n * sn + (size_t)(2 * kp) * sk];
    float x1 = s[(size_t)n * sn + (size_t)(2 * kp + 1) * sk];
    uint32_t h = pack_hi(x0, x1);
    dh[rem] = h;
    dl[rem] = pack_lo(x0, x1, h);
}

// ---------------- K2b: fuse wv @ w_proj -> packed Wvp + bias' ----------------
__global__ __launch_bounds__(256)
void k_fuse_vp(const float* __restrict__ wv, const float* __restrict__ bv,
               const float* __restrict__ wp, const float* __restrict__ bp)
{
    long i = (long)blockIdx.x * 256 + threadIdx.x;
    if (blockIdx.x == 512) {
        int c = threadIdx.x;
        float s = bp[c];
        for (int j = 0; j < 256; j++) s += bv[j] * wp[(size_t)j * 256 + c];
        g_biasvp[c] = s;
        return;
    }
    int c = (int)(i >> 9);
    int kp = (int)(i & 511);
    int m = kp >> 7;
    int k2 = (kp & 127) * 2;
    float x0 = 0.f, x1 = 0.f;
    const float* wv0 = wv + (size_t)k2 * 256 + m * 64;
    const float* wv1 = wv0 + 256;
#pragma unroll 8
    for (int e = 0; e < 64; e++) {
        float wpe = wp[(size_t)(m * 64 + e) * 256 + c];
        x0 += wv0[e] * wpe;
        x1 += wv1[e] * wpe;
    }
    uint32_t h = pack_hi(x0, x1);
    g_pvp_h[i] = h;
    g_pvp_l[i] = pack_lo(x0, x1, h);
}

// ---------------- pipelined bf16x2 tensor GEMM, tile 128x64, 2 CTA/SM ----------------
// flags: 1 fp32, 2 gelu, 4 fp16, 8 packed, 16 = 2-pass (skip B_lo fills AND mma).
#define STG_A_H 0
#define STG_A_L 16384
#define STG_B_H 32768
#define STG_B_L 40960
#define STG_SZ  49152
#define GSM     (2*STG_SZ)

__global__ __launch_bounds__(256, 2)
void bgemm3(int M, int N, int K,
            const uint32_t* __restrict__ Ah, const uint32_t* __restrict__ Al,
            int ldap, long aoz,
            const uint32_t* __restrict__ Bh, const uint32_t* __restrict__ Bl, long bzs,
            const float* __restrict__ bias, int bioz,
            float* __restrict__ Cf, __half* __restrict__ Chalf, int ldc, long coz,
            uint32_t* __restrict__ Ph, uint32_t* __restrict__ Pl, int ldp, long poz,
            int flags)
{
    extern __shared__ char smem[];
    uint32_t sbase = smem_u32(smem);
    int z = blockIdx.z;
    Ah += (size_t)z * aoz; Al += (size_t)z * aoz;
    Bh += (size_t)z * bzs; Bl += (size_t)z * bzs;
    if (bias) bias += (size_t)z * bioz;
    int Kp = K >> 1;
    const bool pass3 = !(flags & 16);

    int tid = threadIdx.x, lane = tid & 31, wid = tid >> 5;
    int wm = wid & 3, wn = wid >> 2;
    int g = lane >> 2, t = lane & 3;
    int bm = blockIdx.y * 128, bn = blockIdx.x * 64;

    float acc[2][4][4] = {};

    int frow0 = tid >> 3, fseg = tid & 7;

    auto fill = [&](int ch, int st) {
        uint32_t stb = sbase + st * STG_SZ;
        int kp0 = ch << 5;
#pragma unroll
        for (int x = 0; x < 4; x++) {
            int row = x * 32 + frow0;
            uint32_t soff = (uint32_t)(row * 128 + ((fseg ^ (row & 7)) << 4));
            size_t ga = (size_t)(bm + row) * ldap + kp0 + fseg * 4;
            cp16(stb + STG_A_H + soff, Ah + ga, true);
            cp16(stb + STG_A_L + soff, Al + ga, true);
        }
#pragma unroll
        for (int x = 0; x < 2; x++) {
            int row = x * 32 + frow0;
            uint32_t soff = (uint32_t)(row * 128 + ((fseg ^ (row & 7)) << 4));
            bool bvld = (bn + row) < N;
            size_t gb = bvld ? ((size_t)(bn + row) * Kp + kp0 + fseg * 4) : 0;
            cp16(stb + STG_B_H + soff, Bh + gb, bvld);
            if (pass3) cp16(stb + STG_B_L + soff, Bl + gb, bvld);
        }
    };

    auto compute = [&](int st) {
        uint32_t stb = sbase + st * STG_SZ;
#pragma unroll
        for (int ks = 0; ks < 4; ks++) {
            int s0 = ks * 2;
            uint32_t ah[2][4], al[2][4];
#pragma unroll
            for (int i = 0; i < 2; i++) {
                int ml = wm * 32 + i * 16 + (lane & 15);
                int seg = s0 + (lane >> 4);
                uint32_t off = (uint32_t)(ml * 128 + ((seg ^ (ml & 7)) << 4));
                ldsm_x4(ah[i], stb + STG_A_H + off);
                ldsm_x4(al[i], stb + STG_A_L + off);
            }
#pragma unroll
            for (int j2 = 0; j2 < 2; j2++) {
                int nl = wn * 32 + j2 * 16 + (lane & 15);
                int seg = s0 + (lane >> 4);
                uint32_t off = (uint32_t)(nl * 128 + ((seg ^ (nl & 7)) << 4));
                uint32_t bh[4], bl[4];
                ldsm_x4(bh, stb + STG_B_H + off);
                if (pass3) ldsm_x4(bl, stb + STG_B_L + off);
#pragma unroll
                for (int jj = 0; jj < 2; jj++) {
                    int j = j2 * 2 + jj;
                    uint32_t bh0 = jj ? bh[1] : bh[0];
                    uint32_t bh1 = jj ? bh[3] : bh[2];
#pragma unroll
                    for (int i = 0; i < 2; i++) {
                        mma16(acc[i][j], ah[i], bh0, bh1);
                        mma16(acc[i][j], al[i], bh0, bh1);
                        if (pass3) {
                            uint32_t bl0 = jj ? bl[1] : bl[0];
                            uint32_t bl1 = jj ? bl[3] : bl[2];
                            mma16(acc[i][j], ah[i], bl0, bl1);
                        }
                    }
                }
            }
        }
    };

    int nch = K >> 6;
    fill(0, 0);
    asm volatile("cp.async.commit_group;" ::: "memory");
    for (int c = 0; c < nch; c++) {
        if (c + 1 < nch) {
            fill(c + 1, (c + 1) & 1);
            asm volatile("cp.async.commit_group;" ::: "memory");
            asm volatile("cp.async.wait_group 1;" ::: "memory");
        } else {
            asm volatile("cp.async.wait_group 0;" ::: "memory");
        }
        __syncthreads();
        compute(c & 1);
        __syncthreads();
    }

    // ---- epilogue ----
#pragma unroll
    for (int i = 0; i < 2; i++) {
        int r0 = bm + wm * 32 + i * 16 + g;
#pragma unroll
        for (int j = 0; j < 4; j++) {
            int c0 = bn + wn * 32 + j * 8 + t * 2;
            if (c0 >= N) continue;
            float b0v = bias ? bias[c0] : 0.f;
            float b1v = bias ? bias[c0 + 1] : 0.f;
            float v0 = acc[i][j][0] + b0v;
            float v1 = acc[i][j][1] + b1v;
            float v2 = acc[i][j][2] + b0v;
            float v3 = acc[i][j][3] + b1v;
            if (flags & 2) {
                v0 = 0.5f * v0 * (1.f + erff(v0 * 0.70710678118654752f));
                v1 = 0.5f * v1 * (1.f + erff(v1 * 0.70710678118654752f));
                v2 = 0.5f * v2 * (1.f + erff(v2 * 0.70710678118654752f));
                v3 = 0.5f * v3 * (1.f + erff(v3 * 0.70710678118654752f));
            }
            if (flags & 1) {
                float* C = Cf + (size_t)z * coz;
                *(float2*)&C[(size_t)r0 * ldc + c0]       = make_float2(v0, v1);
                *(float2*)&C[(size_t)(r0 + 8) * ldc + c0] = make_float2(v2, v3);
            }
            if (flags & 4) {
                __half* C = Chalf + (size_t)z * coz;
                *(__half2*)&C[(size_t)r0 * ldc + c0]       = __floats2half2_rn(v0, v1);
                *(__half2*)&C[(size_t)(r0 + 8) * ldc + c0] = __floats2half2_rn(v2, v3);
            }
            if (flags & 8) {
                uint32_t* PH = Ph + (size_t)z * poz;
                uint32_t* PL = Pl + (size_t)z * poz;
                int pidx = c0 >> 1;
                uint32_t h0 = pack_hi(v0, v1);
                PH[(size_t)r0 * ldp + pidx] = h0;
                PL[(size_t)r0 * ldp + pidx] = pack_lo(v0, v1, h0);
                uint32_t h1 = pack_hi(v2, v3);
                PH[(size_t)(r0 + 8) * ldp + pidx] = h1;
                PL[(size_t)(r0 + 8) * ldp + pidx] = pack_lo(v2, v3, h1);
            }
        }
    }
}

// ---------------- K4: fused attention (scores + softmax + LN(v) accumulation) ----------------
#define ATT_DYN ((6*1024 + 8*1024)*4)
__global__ __launch_bounds__(256)
void k_attn(const float* __restrict__ kten, const float* __restrict__ vten,
            const uint32_t* __restrict__ qph, const uint32_t* __restrict__ qpl,
            const __half* __restrict__ tg, const float* __restrict__ bk,
            const float* __restrict__ lngk, const float* __restrict__ lnbk,
            const float* __restrict__ lngv, const float* __restrict__ lnbv,
            const float* __restrict__ maskf)
{
    extern __shared__ float dyn[];
    float* ts = dyn;                                  // [6][1024]
    float (*part)[1024] = (float(*)[1024])(dyn + 6 * 1024);
    __shared__ float bd[6][4];
    __shared__ float sdot[4][NKEY];
    __shared__ float sa[4][NKEY];

    int q = blockIdx.x, tid = threadIdx.x, lane = tid & 31, w = tid >> 5;

#pragma unroll
    for (int n = 0; n < NFR; n++) {
        size_t r = (size_t)n * QLEN + q;
        uint2 tu = *(const uint2*)(tg + r * 1024 + tid * 4);
        __half2 h0 = *reinterpret_cast<__half2*>(&tu.x);
        __half2 h1 = *reinterpret_cast<__half2*>(&tu.y);
        float2 f0 = __half22float2(h0);
        float2 f1 = __half22float2(h1);
        ts[n * 1024 + tid * 4 + 0] = f0.x;
        ts[n * 1024 + tid * 4 + 1] = f0.y;
        ts[n * 1024 + tid * 4 + 2] = f1.x;
        ts[n * 1024 + tid * 4 + 3] = f1.y;
    }
    if (w < 6) {
        size_t r = (size_t)w * QLEN + q;
#pragma unroll
        for (int m = 0; m < 4; m++) {
            uint32_t hh = qph[r * 128 + m * 32 + lane];
            uint32_t ll = qpl[r * 128 + m * 32 + lane];
            __nv_bfloat162 h2 = *reinterpret_cast<__nv_bfloat162*>(&hh);
            __nv_bfloat162 l2 = *reinterpret_cast<__nv_bfloat162*>(&ll);
            float a0 = __bfloat162float(h2.x) + __bfloat162float(l2.x);
            float a1 = __bfloat162float(h2.y) + __bfloat162float(l2.y);
            float p = a0 * bk[m * 64 + 2 * lane] + a1 * bk[m * 64 + 2 * lane + 1];
#pragma unroll
            for (int o = 16; o > 0; o >>= 1) p += __shfl_xor_sync(0xffffffffu, p, o);
            if (lane == 0) bd[w][m] = p;
        }
    }
    float gk[8], bkk[8], gv[8], bvv[8];
#pragma unroll
    for (int j = 0; j < 8; j++) {
        int c = lane + 32 * j;
        gk[j] = lngk[c]; bkk[j] = lnbk[c];
        gv[j] = lngv[c]; bvv[j] = lnbv[c];
    }
    __syncthreads();

    for (int n = 0; n < NFR; n++) {
        size_t r = (size_t)n * QLEN + q;
        const float* krow = kten + (r * GRP + w) * 256;
        float v[8];
        float s1 = 0.f, s2 = 0.f;
#pragma unroll
        for (int j = 0; j < 8; j++) {
            v[j] = krow[lane + 32 * j];
            s1 += v[j]; s2 += v[j] * v[j];
        }
#pragma unroll
        for (int o = 16; o > 0; o >>= 1) {
            s1 += __shfl_xor_sync(0xffffffffu, s1, o);
            s2 += __shfl_xor_sync(0xffffffffu, s2, o);
        }
        float mu = s1 * (1.f / 256.f);
        float rs = rsqrtf(s2 * (1.f / 256.f) - mu * mu + EPSLN);
        float d0 = 0.f, d1 = 0.f, d2 = 0.f, d3 = 0.f;
#pragma unroll
        for (int j = 0; j < 8; j++) {
            int c = lane + 32 * j;
            float lv = (v[j] - mu) * rs * gk[j] + bkk[j];
            d0 += lv * ts[n * 1024 + c];
            d1 += lv * ts[n * 1024 + 256 + c];
            d2 += lv * ts[n * 1024 + 512 + c];
            d3 += lv * ts[n * 1024 + 768 + c];
        }
#pragma unroll
        for (int o = 16; o > 0; o >>= 1) {
            d0 += __shfl_xor_sync(0xffffffffu, d0, o);
            d1 += __shfl_xor_sync(0xffffffffu, d1, o);
            d2 += __shfl_xor_sync(0xffffffffu, d2, o);
            d3 += __shfl_xor_sync(0xffffffffu, d3, o);
        }
        if (lane == 0) {
            bool mk = maskf[r] != 0.f;
            float dm[4] = {d0, d1, d2, d3};
#pragma unroll
            for (int m = 0; m < 4; m++)
                sdot[m][n * 8 + w] = mk ? SCALE * (dm[m] + bd[n][m]) : -1e9f;
        }
    }
    __syncthreads();
    if (w < 4) {
        float v0 = sdot[w][lane];
        float v1 = (lane < 16) ? sdot[w][32 + lane] : -3.4e38f;
        float mx = fmaxf(v0, v1);
#pragma unroll
        for (int o = 16; o > 0; o >>= 1) mx = fmaxf(mx, __shfl_xor_sync(0xffffffffu, mx, o));
        float e0 = expf(v0 - mx);
        float e1 = (lane < 16) ? expf(v1 - mx) : 0.f;
        float s = e0 + e1;
#pragma unroll
        for (int o = 16; o > 0; o >>= 1) s += __shfl_xor_sync(0xffffffffu, s, o);
        float inv = 1.f / s;
        sa[w][lane] = e0 * inv;
        if (lane < 16) sa[w][32 + lane] = e1 * inv;
    }
    __syncthreads();
    float acc[4][8] = {};
    for (int n = 0; n < NFR; n++) {
        size_t r = (size_t)n * QLEN + q;
        const float* vr = vten + (r * GRP + w) * 256;
        float vv[8];
        float s1 = 0.f, s2 = 0.f;
#pragma unroll
        for (int j = 0; j < 8; j++) {
            vv[j] = vr[lane + 32 * j];
            s1 += vv[j]; s2 += vv[j] * vv[j];
        }
#pragma unroll
        for (int o = 16; o > 0; o >>= 1) {
            s1 += __shfl_xor_sync(0xffffffffu, s1, o);
            s2 += __shfl_xor_sync(0xffffffffu, s2, o);
        }
        float mu = s1 * (1.f / 256.f);
        float rs = rsqrtf(s2 * (1.f / 256.f) - mu * mu + EPSLN);
        float aw0 = sa[0][n * 8 + w];
        float aw1 = sa[1][n * 8 + w];
        float aw2 = sa[2][n * 8 + w];
        float aw3 = sa[3][n * 8 + w];
#pragma unroll
        for (int j = 0; j < 8; j++) {
            float lv = (vv[j] - mu) * rs * gv[j] + bvv[j];
            acc[0][j] += aw0 * lv;
            acc[1][j] += aw1 * lv;
            acc[2][j] += aw2 * lv;
            acc[3][j] += aw3 * lv;
        }
    }
#pragma unroll
    for (int m = 0; m < 4; m++)
#pragma unroll
        for (int j = 0; j < 8; j++)
            part[w][m * 256 + lane + 32 * j] = acc[m][j];
    __syncthreads();
#pragma unroll
    for (int m = 0; m < 4; m++) {
        float s = 0.f;
#pragma unroll
        for (int w8 = 0; w8 < 8; w8++) s += part[w8][m * 256 + tid];
        float so = __shfl_down_sync(0xffffffffu, s, 1);
        if (!(tid & 1)) {
            uint32_t h = pack_hi(s, so);
            size_t o = (size_t)q * 512 + m * 128 + (tid >> 1);
            g_apreh[o] = h;
            g_aprel[o] = pack_lo(s, so, h);
        }
    }
}

// ---------------- K7: z = LN_pre(zp + skip^T) -> fp32 + packed ----------------
__global__ __launch_bounds__(256)
void k_ln_skip(const float* __restrict__ zp, const float* __restrict__ skip,
               const float* __restrict__ g, const float* __restrict__ b,
               float* __restrict__ zln)
{
    __shared__ float red[16];
    int q = blockIdx.x, c = threadIdx.x;
    float v = zp[(size_t)q * 256 + c] + skip[(size_t)c * QLEN + q];
    float s1 = v, s2 = v * v;
    blockReduce2(s1, s2, red);
    float mu = s1 * (1.f / 256.f);
    float rs = rsqrtf(s2 * (1.f / 256.f) - mu * mu + EPSLN);
    float val = (v - mu) * rs * g[c] + b[c];
    zln[(size_t)q * 256 + c] = val;
    float vo = __shfl_down_sync(0xffffffffu, val, 1);
    if (!(c & 1)) {
        uint32_t h = pack_hi(val, vo);
        size_t o = (size_t)q * 128 + (c >> 1);
        g_zlnh[o] = h;
        g_zlnl[o] = pack_lo(val, vo, h);
    }
}

// ---------------- K8: out = LN_post(zln + hp), transposed store ----------------
__global__ __launch_bounds__(256)
void k_ln_out(const float* __restrict__ zln, const float* __restrict__ hp,
              const float* __restrict__ g, const float* __restrict__ b,
              float* __restrict__ out)
{
    __shared__ float red[16];
    int q = blockIdx.x, c = threadIdx.x;
    float v = zln[(size_t)q * 256 + c] + hp[(size_t)q * 256 + c];
    float s1 = v, s2 = v * v;
    blockReduce2(s1, s2, red);
    float mu = s1 * (1.f / 256.f);
    float rs = rsqrtf(s2 * (1.f / 256.f) - mu * mu + EPSLN);
    out[(size_t)c * QLEN + q] = (v - mu) * rs * g[c] + b[c];
}

// ---------------- host launch ----------------
extern "C" void kernel_launch(void* const* d_in, const int* in_sizes, int n_in,
                              void* d_out, int out_size)
{
    const float* q        = (const float*)d_in[0];
    const float* k        = (const float*)d_in[1];
    const float* v        = (const float*)d_in[2];
    const float* skip     = (const float*)d_in[3];
    const void*  mask     = d_in[4];
    const float* ln_q_g   = (const float*)d_in[5];
    const float* ln_q_b   = (const float*)d_in[6];
    const float* wq       = (const float*)d_in[7];
    const float* bq       = (const float*)d_in[8];
    const float* ln_k_g   = (const float*)d_in[9];
    const float* ln_k_b   = (const float*)d_in[10];
    const float* wk       = (const float*)d_in[11];
    const float* bk       = (const float*)d_in[12];
    const float* ln_v_g   = (const float*)d_in[13];
    const float* ln_v_b   = (const float*)d_in[14];
    const float* wv       = (const float*)d_in[15];
    const float* bv       = (const float*)d_in[16];
    const float* w_proj   = (const float*)d_in[17];
    const float* b_proj   = (const float*)d_in[18];
    const float* ln_pre_g = (const float*)d_in[19];
    const float* ln_pre_b = (const float*)d_in[20];
    const float* w_mlp1   = (const float*)d_in[21];
    const float* b_mlp1   = (const float*)d_in[22];
    const float* w_mlp2   = (const float*)d_in[23];
    const float* b_mlp2   = (const float*)d_in[24];
    const float* ln_post_g= (const float*)d_in[25];
    const float* ln_post_b= (const float*)d_in[26];
    float* out = (float*)d_out;

    float *zp, *zln, *hp, *maskf, *biasvp;
    __half* t;
    uint32_t *qlnh, *qlnl, *qph, *qpl, *apreh, *aprel, *zlnh, *zlnl, *h1h, *h1l;
    uint32_t *pwq_h, *pwq_l, *pwk_h, *pwk_l, *pw1_h, *pw1_l, *pw2_h, *pw2_l;
    uint32_t *pvp_h, *pvp_l;
    cudaGetSymbolAddress((void**)&qlnh, g_qlnh); cudaGetSymbolAddress((void**)&qlnl, g_qlnl);
    cudaGetSymbolAddress((void**)&qph,  g_qph);  cudaGetSymbolAddress((void**)&qpl,  g_qpl);
    cudaGetSymbolAddress((void**)&t,    g_t);
    cudaGetSymbolAddress((void**)&apreh,g_apreh);cudaGetSymbolAddress((void**)&aprel,g_aprel);
    cudaGetSymbolAddress((void**)&zp,   g_zp);
    cudaGetSymbolAddress((void**)&zln,  g_zln);
    cudaGetSymbolAddress((void**)&zlnh, g_zlnh); cudaGetSymbolAddress((void**)&zlnl, g_zlnl);
    cudaGetSymbolAddress((void**)&h1h,  g_h1h);  cudaGetSymbolAddress((void**)&h1l,  g_h1l);
    cudaGetSymbolAddress((void**)&hp,   g_hp);
    cudaGetSymbolAddress((void**)&maskf,g_maskf);
    cudaGetSymbolAddress((void**)&pwq_h, g_pwq_h); cudaGetSymbolAddress((void**)&pwq_l, g_pwq_l);
    cudaGetSymbolAddress((void**)&pwk_h, g_pwk_h); cudaGetSymbolAddress((void**)&pwk_l, g_pwk_l);
    cudaGetSymbolAddress((void**)&pw1_h, g_pw1_h); cudaGetSymbolAddress((void**)&pw1_l, g_pw1_l);
    cudaGetSymbolAddress((void**)&pw2_h, g_pw2_h); cudaGetSymbolAddress((void**)&pw2_l, g_pw2_l);
    cudaGetSymbolAddress((void**)&pvp_h, g_pvp_h); cudaGetSymbolAddress((void**)&pvp_l, g_pvp_l);
    cudaGetSymbolAddress((void**)&biasvp,g_biasvp);

    cudaFuncSetAttribute(bgemm3, cudaFuncAttributeMaxDynamicSharedMemorySize, GSM);
    cudaFuncSetAttribute(k_attn, cudaFuncAttributeMaxDynamicSharedMemorySize, ATT_DYN);

    // 1
    k_mask<<<1, 256>>>((const unsigned char*)mask);
    // 2: q transpose + LN -> packed
    k_q_ln<<<dim3(QLEN / 32, NFR), 256>>>(q, ln_q_g, ln_q_b);
    // 3: pack weights + fuse wv@w_proj
    k_pack_all<<<768, 256>>>(wq, wk, w_mlp1, w_mlp2);
    k_fuse_vp<<<513, 256>>>(wv, bv, w_proj, b_proj);
    // 4: qp = qln @ wq + bq  -> packed only (2-pass)
    bgemm3<<<dim3(4, 192, 1), 256, GSM>>>(R_TOT, 256, 256,
                                          qlnh, qlnl, 128, 0,
                                          pwq_h, pwq_l, 0, bq, 0,
                                          nullptr, nullptr, 0, 0,
                                          qph, qpl, 128, 0, 8 | 16);
    // 5: t_m = qp_m @ wk_m^T (K=64) x4 heads -> fp16 (2-pass)
    bgemm3<<<dim3(4, 192, 4), 256, GSM>>>(R_TOT, 256, 64,
                                          qph, qpl, 128, 32,
                                          pwk_h, pwk_l, 256 * 32, nullptr, 0,
                                          nullptr, t, 1024, 256,
                                          nullptr, nullptr, 0, 0, 4 | 16);
    // 6: fused attention -> packed apre
    k_attn<<<QLEN, 256, ATT_DYN>>>(k, v, qph, qpl, t, bk,
                                   ln_k_g, ln_k_b, ln_v_g, ln_v_b, maskf);
    // 7: zp = apre @ Wvp + bias'  (K=1024, fused av+proj)
    bgemm3<<<dim3(4, 32, 1), 256, GSM>>>(QLEN, 256, 1024,
                                         apreh, aprel, 512, 0,
                                         pvp_h, pvp_l, 0, biasvp, 0,
                                         zp, nullptr, 256, 0,
                                         nullptr, nullptr, 0, 0, 1);
    // 8: zln = LN_pre(zp + skip) -> fp32 + packed
    k_ln_skip<<<QLEN, 256>>>(zp, skip, ln_pre_g, ln_pre_b, zln);
    // 9: h1 = gelu(zln @ w_mlp1 + b_mlp1) -> packed
    bgemm3<<<dim3(8, 32, 1), 256, GSM>>>(QLEN, 512, 256,
                                         zlnh, zlnl, 128, 0,
                                         pw1_h, pw1_l, 0, b_mlp1, 0,
                                         nullptr, nullptr, 0, 0,
                                         h1h, h1l, 256, 0, 10);
    // 10: hp = h1 @ w_mlp2 + b_mlp2 -> fp32
    bgemm3<<<dim3(4, 32, 1), 256, GSM>>>(QLEN, 256, 512,
                                         h1h, h1l, 256, 0,
                                         pw2_h, pw2_l, 0, b_mlp2, 0,
                                         hp, nullptr, 256, 0,
                                         nullptr, nullptr, 0, 0, 1);
    // 11
    k_ln_out<<<QLEN, 256>>>(zln, hp, ln_post_g, ln_post_b, out);
}

// round 14
// speedup vs baseline: 1.1516x; 1.1516x over previous
#include <cuda_runtime.h>
#include <cuda_bf16.h>
#include <cuda_fp16.h>
#include <math.h>
#include <stdint.h>

// ---------------- problem constants ----------------
#define QLEN   4096
#define NFR    6
#define GRP    8
#define DIMC   256
#define HEADS  4
#define NKEY   48
#define R_TOT  (NFR*QLEN)
#define EPSLN  1e-5f
#define SCALE  0.125f

// ---------------- scratch ----------------
__device__ uint32_t g_qlnh[R_TOT*128], g_qlnl[R_TOT*128];
__device__ uint32_t g_qph [R_TOT*128], g_qpl [R_TOT*128];
__device__ __half   g_t   [R_TOT*1024];
__device__ float    g_dot [QLEN*HEADS*NKEY];
__device__ uint32_t g_apreh[QLEN*512], g_aprel[QLEN*512];
__device__ float    g_zp  [QLEN*DIMC];
__device__ float    g_zln [QLEN*DIMC];
__device__ uint32_t g_zlnh[QLEN*128], g_zlnl[QLEN*128];
__device__ uint32_t g_h1h [QLEN*256], g_h1l [QLEN*256];
__device__ float    g_hp  [QLEN*DIMC];
__device__ float    g_maskf[R_TOT];
__device__ uint32_t g_pwq_h[256*128],  g_pwq_l[256*128];
__device__ uint32_t g_pwk_h[4*256*32], g_pwk_l[4*256*32];
__device__ uint32_t g_pw1_h[512*128],  g_pw1_l[512*128];
__device__ uint32_t g_pw2_h[256*256],  g_pw2_l[256*256];
// fused wv@w_proj weight (B^T layout [c][512 pairs]) + bias
__device__ uint32_t g_pvp_h[256*512],  g_pvp_l[256*512];
__device__ float    g_biasvp[256];

// ---------------- helpers ----------------
__device__ __forceinline__ void blockReduce2(float& s1, float& s2, float* red)
{
    int lane = threadIdx.x & 31, w = threadIdx.x >> 5;
#pragma unroll
    for (int o = 16; o > 0; o >>= 1) {
        s1 += __shfl_xor_sync(0xffffffffu, s1, o);
        s2 += __shfl_xor_sync(0xffffffffu, s2, o);
    }
    if (lane == 0) { red[w] = s1; red[8 + w] = s2; }
    __syncthreads();
    float a = 0.f, b = 0.f;
#pragma unroll
    for (int j = 0; j < 8; j++) { a += red[j]; b += red[8 + j]; }
    s1 = a; s2 = b;
    __syncthreads();
}

__device__ __forceinline__ uint32_t pack_hi(float x0, float x1)
{
    __nv_bfloat162 h = __floats2bfloat162_rn(x0, x1);
    return *reinterpret_cast<uint32_t*>(&h);
}
__device__ __forceinline__ uint32_t pack_lo(float x0, float x1, uint32_t hi)
{
    __nv_bfloat162 h = *reinterpret_cast<__nv_bfloat162*>(&hi);
    float r0 = x0 - __bfloat162float(h.x);
    float r1 = x1 - __bfloat162float(h.y);
    __nv_bfloat162 l = __floats2bfloat162_rn(r0, r1);
    return *reinterpret_cast<uint32_t*>(&l);
}

__device__ __forceinline__ void mma16(float* c, const uint32_t* a, const uint32_t b0, const uint32_t b1)
{
    asm volatile(
        "mma.sync.aligned.m16n8k16.row.col.f32.bf16.bf16.f32 "
        "{%0,%1,%2,%3}, {%4,%5,%6,%7}, {%8,%9}, {%0,%1,%2,%3};"
        : "+f"(c[0]), "+f"(c[1]), "+f"(c[2]), "+f"(c[3])
        : "r"(a[0]), "r"(a[1]), "r"(a[2]), "r"(a[3]), "r"(b0), "r"(b1));
}

__device__ __forceinline__ void ldsm_x4(uint32_t* r, uint32_t saddr)
{
    asm volatile("ldmatrix.sync.aligned.m8n8.x4.shared.b16 {%0,%1,%2,%3}, [%4];"
                 : "=r"(r[0]), "=r"(r[1]), "=r"(r[2]), "=r"(r[3]) : "r"(saddr));
}

__device__ __forceinline__ uint32_t smem_u32(const void* p)
{
    uint32_t a;
    asm("{ .reg .u64 t; cvta.to.shared.u64 t, %1; cvt.u32.u64 %0, t; }" : "=r"(a) : "l"(p));
    return a;
}

__device__ __forceinline__ void cp16(uint32_t dst, const void* src, bool pred)
{
    int sz = pred ? 16 : 0;
    asm volatile("cp.async.cg.shared.global [%0], [%1], 16, %2;"
                 :: "r"(dst), "l"(src), "r"(sz) : "memory");
}

// ---------------- K0: mask detect + normalize ----------------
__global__ void k_mask(const unsigned char* __restrict__ m8)
{
    __shared__ int fA, fB;
    if (threadIdx.x == 0) { fA = 0; fB = 0; }
    __syncthreads();
    for (int i = threadIdx.x; i < NFR * QLEN; i += 256) {
        unsigned char b = m8[i];
        if (b == 1) {
            if ((i & 3) == 0) fA = 1;
            else              fB = 1;
        }
    }
    __syncthreads();
    int mode = fB ? 0 : (fA ? 1 : 2);
    for (int i = threadIdx.x; i < NFR * QLEN; i += 256) {
        float r;
        if (mode == 0)      r = (m8[i] != 0) ? 1.f : 0.f;
        else if (mode == 1) r = (((const int*)m8)[i] != 0) ? 1.f : 0.f;
        else                r = (((const float*)m8)[i] != 0.f) ? 1.f : 0.f;
        g_maskf[i] = r;
    }
}

// ---------------- K1: transpose q + LayerNorm -> packed pairs ----------------
__global__ __launch_bounds__(256)
void k_q_ln(const float* __restrict__ q, const float* __restrict__ g,
            const float* __restrict__ b)
{
    __shared__ float tile[256][33];
    __shared__ float s_mu[32], s_rs[32];
    __shared__ float s_part[2][8][32];
    int n  = blockIdx.y;
    int p0 = blockIdx.x * 32;
    int t  = threadIdx.x;
    int px = t & 31, cy = t >> 5;
    const float* qn = q + (size_t)n * DIMC * QLEN;
    float s1 = 0.f, s2 = 0.f;
    for (int c = cy; c < DIMC; c += 8) {
        float v = qn[(size_t)c * QLEN + p0 + px];
        tile[c][px] = v;
        s1 += v; s2 += v * v;
    }
    s_part[0][cy][px] = s1; s_part[1][cy][px] = s2;
    __syncthreads();
    if (cy == 0) {
        float a = 0.f, bb = 0.f;
#pragma unroll
        for (int j = 0; j < 8; j++) { a += s_part[0][j][px]; bb += s_part[1][j][px]; }
        float mu = a * (1.f / 256.f);
        float var = bb * (1.f / 256.f) - mu * mu;
        s_mu[px] = mu; s_rs[px] = rsqrtf(var + EPSLN);
    }
    __syncthreads();
    float gg = g[t], bv = b[t];
    size_t rbase = (size_t)n * QLEN + p0;
#pragma unroll 4
    for (int pp = 0; pp < 32; pp++) {
        float val = (tile[t][pp] - s_mu[pp]) * s_rs[pp] * gg + bv;
        float vo = __shfl_down_sync(0xffffffffu, val, 1);
        if (!(t & 1)) {
            uint32_t h = pack_hi(val, vo);
            size_t o = (rbase + pp) * 128 + (t >> 1);
            g_qlnh[o] = h;
            g_qlnl[o] = pack_lo(val, vo, h);
        }
    }
}

// ---------------- K2: pack wq/wk/w_mlp1/w_mlp2 (196608 elems = 768 blocks) ----------------
__global__ __launch_bounds__(256)
void k_pack_all(const float* __restrict__ wq, const float* __restrict__ wk,
                const float* __restrict__ w1, const float* __restrict__ w2)
{
    long i = (long)blockIdx.x * 256 + threadIdx.x;
    if (i >= 196608) return;
    const float* src; int sn, sk; long zo; int N, Kp; uint32_t *dh, *dl; long rem;
    if (i < 32768)       { rem = i;          src = wq; sn = 1;   sk = 256; zo = 0;  N = 256; Kp = 128; dh = g_pwq_h; dl = g_pwq_l; }
    else if (i < 65536)  { rem = i - 32768;  src = wk; sn = 256; sk = 1;   zo = 64; N = 256; Kp = 32;  dh = g_pwk_h; dl = g_pwk_l; }
    else if (i < 131072) { rem = i - 65536;  src = w1; sn = 1;   sk = 512; zo = 0;  N = 512; Kp = 128; dh = g_pw1_h; dl = g_pw1_l; }
    else                 { rem = i - 131072; src = w2; sn = 1;   sk = 256; zo = 0;  N = 256; Kp = 256; dh = g_pw2_h; dl = g_pw2_l; }
    long NK = (long)N * Kp;
    long z = rem / NK, j = rem - z * NK;
    int n = (int)(j / Kp), kp = (int)(j - (long)n * Kp);
    const float* s = src + z * zo;
    float x0 = s[(size_t)n * sn + (size_t)(2 * kp) * sk];
    float x1 = s[(size_t)n * sn + (size_t)(2 * kp + 1) * sk];
    uint32_t h = pack_hi(x0, x1);
    dh[rem] = h;
    dl[rem] = pack_lo(x0, x1, h);
}

// ---------------- K2b: fuse wv @ w_proj -> packed Wvp + bias' (smem-tiled) ----------------
// Wvp[k'=m*256+k][c] = sum_e wv[k][m*64+e] * wp[m*64+e][c]; packed [c][512 pairs].
// 32 tile blocks: bid -> m(4) x kb(2) x cb(4); slab wv 128k x 64e, wp 64e x 64c.
__global__ __launch_bounds__(256)
void k_fuse_vp(const float* __restrict__ wv, const float* __restrict__ bv,
               const float* __restrict__ wp, const float* __restrict__ bp)
{
    if (blockIdx.x == 32) {
        int c = threadIdx.x;
        float s = bp[c];
        for (int j = 0; j < 256; j++) s += bv[j] * wp[(size_t)j * 256 + c];
        g_biasvp[c] = s;
        return;
    }
    __shared__ float wvs[128][64];   // 32 KB
    __shared__ float wps[64][64];    // 16 KB
    int bid = blockIdx.x;
    int m  = bid >> 3;
    int kb = (bid >> 2) & 1;
    int cb = bid & 3;
    int tid = threadIdx.x;
    // wv slab: k in [kb*128, +128), e in [0,64)
#pragma unroll
    for (int i = 0; i < 8; i++) {
        int idx = i * 256 + tid;      // float4 units
        int row = idx >> 4;
        int f4  = idx & 15;
        float4 v = *(const float4*)(wv + (size_t)(kb * 128 + row) * 256 + m * 64 + f4 * 4);
        *(float4*)&wvs[row][f4 * 4] = v;
    }
    // wp slab: e in [0,64), c in [cb*64, +64)
#pragma unroll
    for (int i = 0; i < 4; i++) {
        int idx = i * 256 + tid;
        int row = idx >> 4;
        int f4  = idx & 15;
        float4 v = *(const float4*)(wp + (size_t)(m * 64 + row) * 256 + cb * 64 + f4 * 4);
        *(float4*)&wps[row][f4 * 4] = v;
    }
    __syncthreads();
    int cl  = tid & 63;
    int kpg = tid >> 6;
#pragma unroll 4
    for (int it = 0; it < 16; it++) {
        int kpl = it * 4 + kpg;       // 0..63
        int k2l = kpl * 2;
        float x0 = 0.f, x1 = 0.f;
#pragma unroll 8
        for (int e = 0; e < 64; e++) {
            float wpe = wps[e][cl];
            x0 += wvs[k2l][e] * wpe;
            x1 += wvs[k2l + 1][e] * wpe;
        }
        long o = (long)(cb * 64 + cl) * 512 + m * 128 + kb * 64 + kpl;
        uint32_t h = pack_hi(x0, x1);
        g_pvp_h[o] = h;
        g_pvp_l[o] = pack_lo(x0, x1, h);
    }
}

// ---------------- pipelined bf16x2 tensor GEMM, tile 128x64, 2 CTA/SM ----------------
// flags: 1 fp32, 2 gelu, 4 fp16, 8 packed, 16 = 2-pass (skip B_lo fills AND mma).
#define STG_A_H 0
#define STG_A_L 16384
#define STG_B_H 32768
#define STG_B_L 40960
#define STG_SZ  49152
#define GSM     (2*STG_SZ)

__global__ __launch_bounds__(256, 2)
void bgemm3(int M, int N, int K,
            const uint32_t* __restrict__ Ah, const uint32_t* __restrict__ Al,
            int ldap, long aoz,
            const uint32_t* __restrict__ Bh, const uint32_t* __restrict__ Bl, long bzs,
            const float* __restrict__ bias, int bioz,
            float* __restrict__ Cf, __half* __restrict__ Chalf, int ldc, long coz,
            uint32_t* __restrict__ Ph, uint32_t* __restrict__ Pl, int ldp, long poz,
            int flags)
{
    extern __shared__ char smem[];
    uint32_t sbase = smem_u32(smem);
    int z = blockIdx.z;
    Ah += (size_t)z * aoz; Al += (size_t)z * aoz;
    Bh += (size_t)z * bzs; Bl += (size_t)z * bzs;
    if (bias) bias += (size_t)z * bioz;
    int Kp = K >> 1;
    const bool pass3 = !(flags & 16);

    int tid = threadIdx.x, lane = tid & 31, wid = tid >> 5;
    int wm = wid & 3, wn = wid >> 2;
    int g = lane >> 2, t = lane & 3;
    int bm = blockIdx.y * 128, bn = blockIdx.x * 64;

    float acc[2][4][4] = {};

    int frow0 = tid >> 3, fseg = tid & 7;

    auto fill = [&](int ch, int st) {
        uint32_t stb = sbase + st * STG_SZ;
        int kp0 = ch << 5;
#pragma unroll
        for (int x = 0; x < 4; x++) {
            int row = x * 32 + frow0;
            uint32_t soff = (uint32_t)(row * 128 + ((fseg ^ (row & 7)) << 4));
            size_t ga = (size_t)(bm + row) * ldap + kp0 + fseg * 4;
            cp16(stb + STG_A_H + soff, Ah + ga, true);
            cp16(stb + STG_A_L + soff, Al + ga, true);
        }
#pragma unroll
        for (int x = 0; x < 2; x++) {
            int row = x * 32 + frow0;
            uint32_t soff = (uint32_t)(row * 128 + ((fseg ^ (row & 7)) << 4));
            bool bvld = (bn + row) < N;
            size_t gb = bvld ? ((size_t)(bn + row) * Kp + kp0 + fseg * 4) : 0;
            cp16(stb + STG_B_H + soff, Bh + gb, bvld);
            if (pass3) cp16(stb + STG_B_L + soff, Bl + gb, bvld);
        }
    };

    auto compute = [&](int st) {
        uint32_t stb = sbase + st * STG_SZ;
#pragma unroll
        for (int ks = 0; ks < 4; ks++) {
            int s0 = ks * 2;
            uint32_t ah[2][4], al[2][4];
#pragma unroll
            for (int i = 0; i < 2; i++) {
                int ml = wm * 32 + i * 16 + (lane & 15);
                int seg = s0 + (lane >> 4);
                uint32_t off = (uint32_t)(ml * 128 + ((seg ^ (ml & 7)) << 4));
                ldsm_x4(ah[i], stb + STG_A_H + off);
                ldsm_x4(al[i], stb + STG_A_L + off);
            }
#pragma unroll
            for (int j2 = 0; j2 < 2; j2++) {
                int nl = wn * 32 + j2 * 16 + (lane & 15);
                int seg = s0 + (lane >> 4);
                uint32_t off = (uint32_t)(nl * 128 + ((seg ^ (nl & 7)) << 4));
                uint32_t bh[4], bl[4];
                ldsm_x4(bh, stb + STG_B_H + off);
                if (pass3) ldsm_x4(bl, stb + STG_B_L + off);
#pragma unroll
                for (int jj = 0; jj < 2; jj++) {
                    int j = j2 * 2 + jj;
                    uint32_t bh0 = jj ? bh[1] : bh[0];
                    uint32_t bh1 = jj ? bh[3] : bh[2];
#pragma unroll
                    for (int i = 0; i < 2; i++) {
                        mma16(acc[i][j], ah[i], bh0, bh1);
                        mma16(acc[i][j], al[i], bh0, bh1);
                        if (pass3) {
                            uint32_t bl0 = jj ? bl[1] : bl[0];
                            uint32_t bl1 = jj ? bl[3] : bl[2];
                            mma16(acc[i][j], ah[i], bl0, bl1);
                        }
                    }
                }
            }
        }
    };

    int nch = K >> 6;
    fill(0, 0);
    asm volatile("cp.async.commit_group;" ::: "memory");
    for (int c = 0; c < nch; c++) {
        if (c + 1 < nch) {
            fill(c + 1, (c + 1) & 1);
            asm volatile("cp.async.commit_group;" ::: "memory");
            asm volatile("cp.async.wait_group 1;" ::: "memory");
        } else {
            asm volatile("cp.async.wait_group 0;" ::: "memory");
        }
        __syncthreads();
        compute(c & 1);
        __syncthreads();
    }

    // ---- epilogue ----
#pragma unroll
    for (int i = 0; i < 2; i++) {
        int r0 = bm + wm * 32 + i * 16 + g;
#pragma unroll
        for (int j = 0; j < 4; j++) {
            int c0 = bn + wn * 32 + j * 8 + t * 2;
            if (c0 >= N) continue;
            float b0v = bias ? bias[c0] : 0.f;
            float b1v = bias ? bias[c0 + 1] : 0.f;
            float v0 = acc[i][j][0] + b0v;
            float v1 = acc[i][j][1] + b1v;
            float v2 = acc[i][j][2] + b0v;
            float v3 = acc[i][j][3] + b1v;
            if (flags & 2) {
                v0 = 0.5f * v0 * (1.f + erff(v0 * 0.70710678118654752f));
                v1 = 0.5f * v1 * (1.f + erff(v1 * 0.70710678118654752f));
                v2 = 0.5f * v2 * (1.f + erff(v2 * 0.70710678118654752f));
                v3 = 0.5f * v3 * (1.f + erff(v3 * 0.70710678118654752f));
            }
            if (flags & 1) {
                float* C = Cf + (size_t)z * coz;
                *(float2*)&C[(size_t)r0 * ldc + c0]       = make_float2(v0, v1);
                *(float2*)&C[(size_t)(r0 + 8) * ldc + c0] = make_float2(v2, v3);
            }
            if (flags & 4) {
                __half* C = Chalf + (size_t)z * coz;
                *(__half2*)&C[(size_t)r0 * ldc + c0]       = __floats2half2_rn(v0, v1);
                *(__half2*)&C[(size_t)(r0 + 8) * ldc + c0] = __floats2half2_rn(v2, v3);
            }
            if (flags & 8) {
                uint32_t* PH = Ph + (size_t)z * poz;
                uint32_t* PL = Pl + (size_t)z * poz;
                int pidx = c0 >> 1;
                uint32_t h0 = pack_hi(v0, v1);
                PH[(size_t)r0 * ldp + pidx] = h0;
                PL[(size_t)r0 * ldp + pidx] = pack_lo(v0, v1, h0);
                uint32_t h1 = pack_hi(v2, v3);
                PH[(size_t)(r0 + 8) * ldp + pidx] = h1;
                PL[(size_t)(r0 + 8) * ldp + pidx] = pack_lo(v2, v3, h1);
            }
        }
    }
}

// ---------------- K4: attention scores (smem-staged t, R11 form) ----------------
__global__ __launch_bounds__(256)
void k_dot(const float* __restrict__ kten,
           const uint32_t* __restrict__ qph, const uint32_t* __restrict__ qpl,
           const __half* __restrict__ tg, const float* __restrict__ bk,
           const float* __restrict__ lng, const float* __restrict__ lnb,
           const float* __restrict__ maskf, float* __restrict__ dotp)
{
    int r = blockIdx.x;
    int n = r >> 12, q = r & 4095;
    int tid = threadIdx.x, lane = tid & 31, w = tid >> 5;
    __shared__ float ts[1024];
    __shared__ float bd[4];
    __shared__ float sg[256], sb[256];
    const __half* trow = tg + (size_t)r * 1024;
    {
        uint2 tu = *(const uint2*)(trow + tid * 4);
        __half2 h0 = *reinterpret_cast<__half2*>(&tu.x);
        __half2 h1 = *reinterpret_cast<__half2*>(&tu.y);
        float2 f0 = __half22float2(h0);
        float2 f1 = __half22float2(h1);
        ts[tid * 4 + 0] = f0.x;
        ts[tid * 4 + 1] = f0.y;
        ts[tid * 4 + 2] = f1.x;
        ts[tid * 4 + 3] = f1.y;
    }
    sg[tid] = lng[tid]; sb[tid] = lnb[tid];
    if (w < 4) {
        uint32_t hh = qph[(size_t)r * 128 + w * 32 + lane];
        uint32_t ll = qpl[(size_t)r * 128 + w * 32 + lane];
        __nv_bfloat162 h2 = *reinterpret_cast<__nv_bfloat162*>(&hh);
        __nv_bfloat162 l2 = *reinterpret_cast<__nv_bfloat162*>(&ll);
        float a0 = __bfloat162float(h2.x) + __bfloat162float(l2.x);
        float a1 = __bfloat162float(h2.y) + __bfloat162float(l2.y);
        const float* bkr = bk + w * 64;
        float p = a0 * bkr[2 * lane] + a1 * bkr[2 * lane + 1];
#pragma unroll
        for (int o = 16; o > 0; o >>= 1) p += __shfl_xor_sync(0xffffffffu, p, o);
        if (lane == 0) bd[w] = p;
    }
    __syncthreads();
    const float* krow = kten + ((size_t)r * GRP + w) * 256;
    float v[8];
    float s1 = 0.f, s2 = 0.f;
#pragma unroll
    for (int j = 0; j < 8; j++) {
        v[j] = krow[lane + 32 * j];
        s1 += v[j]; s2 += v[j] * v[j];
    }
#pragma unroll
    for (int o = 16; o > 0; o >>= 1) {
        s1 += __shfl_xor_sync(0xffffffffu, s1, o);
        s2 += __shfl_xor_sync(0xffffffffu, s2, o);
    }
    float mu = s1 * (1.f / 256.f);
    float rs = rsqrtf(s2 * (1.f / 256.f) - mu * mu + EPSLN);
    float d0 = 0.f, d1 = 0.f, d2 = 0.f, d3 = 0.f;
#pragma unroll
    for (int j = 0; j < 8; j++) {
        int c = lane + 32 * j;
        float lv = (v[j] - mu) * rs * sg[c] + sb[c];
        d0 += lv * ts[c];
        d1 += lv * ts[256 + c];
        d2 += lv * ts[512 + c];
        d3 += lv * ts[768 + c];
    }
#pragma unroll
    for (int o = 16; o > 0; o >>= 1) {
        d0 += __shfl_xor_sync(0xffffffffu, d0, o);
        d1 += __shfl_xor_sync(0xffffffffu, d1, o);
        d2 += __shfl_xor_sync(0xffffffffu, d2, o);
        d3 += __shfl_xor_sync(0xffffffffu, d3, o);
    }
    if (lane == 0) {
        bool mk = maskf[r] != 0.f;
        float dm[4] = {d0, d1, d2, d3};
        size_t base = (size_t)q * (HEADS * NKEY) + (size_t)n * GRP + w;
#pragma unroll
        for (int m = 0; m < 4; m++)
            dotp[base + (size_t)m * NKEY] = mk ? SCALE * (dm[m] + bd[m]) : -1e9f;
    }
}

// ---------------- K6: softmax (fused) + weighted sum of LN(v) -> packed ----------------
__global__ __launch_bounds__(256)
void k_vacc(const float* __restrict__ vten, const float* __restrict__ dotp,
            const float* __restrict__ lng, const float* __restrict__ lnb)
{
    __shared__ float sa[HEADS * NKEY];
    __shared__ float part[8][1024];
    int q = blockIdx.x, tid = threadIdx.x, lane = tid & 31, w = tid >> 5;
    if (w < 4) {
        const float* p = dotp + (size_t)q * (HEADS * NKEY) + w * NKEY;
        float v0 = p[lane];
        float v1 = (lane < 16) ? p[32 + lane] : -3.4e38f;
        float mx = fmaxf(v0, v1);
#pragma unroll
        for (int o = 16; o > 0; o >>= 1) mx = fmaxf(mx, __shfl_xor_sync(0xffffffffu, mx, o));
        float e0 = expf(v0 - mx);
        float e1 = (lane < 16) ? expf(v1 - mx) : 0.f;
        float s = e0 + e1;
#pragma unroll
        for (int o = 16; o > 0; o >>= 1) s += __shfl_xor_sync(0xffffffffu, s, o);
        float inv = 1.f / s;
        sa[w * NKEY + lane] = e0 * inv;
        if (lane < 16) sa[w * NKEY + 32 + lane] = e1 * inv;
    }
    int c0 = lane * 8;
    float gv[8], bb[8];
    {
        float4 gA = *(const float4*)(lng + c0);
        float4 gB = *(const float4*)(lng + c0 + 4);
        float4 bA = *(const float4*)(lnb + c0);
        float4 bB = *(const float4*)(lnb + c0 + 4);
        gv[0]=gA.x; gv[1]=gA.y; gv[2]=gA.z; gv[3]=gA.w;
        gv[4]=gB.x; gv[5]=gB.y; gv[6]=gB.z; gv[7]=gB.w;
        bb[0]=bA.x; bb[1]=bA.y; bb[2]=bA.z; bb[3]=bA.w;
        bb[4]=bB.x; bb[5]=bB.y; bb[6]=bB.z; bb[7]=bB.w;
    }
    __syncthreads();
    float acc[4][8] = {};
    for (int n = 0; n < NFR; n++) {
        const float* vr = vten + (((size_t)n * QLEN + q) * GRP + w) * 256 + c0;
        float4 v0 = *(const float4*)vr;
        float4 v1 = *(const float4*)(vr + 4);
        float vv[8] = {v0.x, v0.y, v0.z, v0.w, v1.x, v1.y, v1.z, v1.w};
        float s1 = 0.f, s2 = 0.f;
#pragma unroll
        for (int j = 0; j < 8; j++) { s1 += vv[j]; s2 += vv[j] * vv[j]; }
#pragma unroll
        for (int o = 16; o > 0; o >>= 1) {
            s1 += __shfl_xor_sync(0xffffffffu, s1, o);
            s2 += __shfl_xor_sync(0xffffffffu, s2, o);
        }
        float mu = s1 * (1.f / 256.f);
        float rs = rsqrtf(s2 * (1.f / 256.f) - mu * mu + EPSLN);
        float aw0 = sa[0 * NKEY + n * 8 + w];
        float aw1 = sa[1 * NKEY + n * 8 + w];
        float aw2 = sa[2 * NKEY + n * 8 + w];
        float aw3 = sa[3 * NKEY + n * 8 + w];
#pragma unroll
        for (int j = 0; j < 8; j++) {
            float lv = (vv[j] - mu) * rs * gv[j] + bb[j];
            acc[0][j] += aw0 * lv;
            acc[1][j] += aw1 * lv;
            acc[2][j] += aw2 * lv;
            acc[3][j] += aw3 * lv;
        }
    }
#pragma unroll
    for (int m = 0; m < 4; m++) {
        float4 p0 = make_float4(acc[m][0], acc[m][1], acc[m][2], acc[m][3]);
        float4 p1 = make_float4(acc[m][4], acc[m][5], acc[m][6], acc[m][7]);
        *(float4*)&part[w][m * 256 + c0]     = p0;
        *(float4*)&part[w][m * 256 + c0 + 4] = p1;
    }
    __syncthreads();
#pragma unroll
    for (int m = 0; m < 4; m++) {
        float s = 0.f;
#pragma unroll
        for (int w8 = 0; w8 < 8; w8++) s += part[w8][m * 256 + tid];
        float so = __shfl_down_sync(0xffffffffu, s, 1);
        if (!(tid & 1)) {
            uint32_t h = pack_hi(s, so);
            size_t o = (size_t)q * 512 + m * 128 + (tid >> 1);
            g_apreh[o] = h;
            g_aprel[o] = pack_lo(s, so, h);
        }
    }
}

// ---------------- K7: z = LN_pre(zp + skip^T) -> fp32 + packed ----------------
__global__ __launch_bounds__(256)
void k_ln_skip(const float* __restrict__ zp, const float* __restrict__ skip,
               const float* __restrict__ g, const float* __restrict__ b,
               float* __restrict__ zln)
{
    __shared__ float red[16];
    int q = blockIdx.x, c = threadIdx.x;
    float v = zp[(size_t)q * 256 + c] + skip[(size_t)c * QLEN + q];
    float s1 = v, s2 = v * v;
    blockReduce2(s1, s2, red);
    float mu = s1 * (1.f / 256.f);
    float rs = rsqrtf(s2 * (1.f / 256.f) - mu * mu + EPSLN);
    float val = (v - mu) * rs * g[c] + b[c];
    zln[(size_t)q * 256 + c] = val;
    float vo = __shfl_down_sync(0xffffffffu, val, 1);
    if (!(c & 1)) {
        uint32_t h = pack_hi(val, vo);
        size_t o = (size_t)q * 128 + (c >> 1);
        g_zlnh[o] = h;
        g_zlnl[o] = pack_lo(val, vo, h);
    }
}

// ---------------- K8: out = LN_post(zln + hp), transposed store ----------------
__global__ __launch_bounds__(256)
void k_ln_out(const float* __restrict__ zln, const float* __restrict__ hp,
              const float* __restrict__ g, const float* __restrict__ b,
              float* __restrict__ out)
{
    __shared__ float red[16];
    int q = blockIdx.x, c = threadIdx.x;
    float v = zln[(size_t)q * 256 + c] + hp[(size_t)q * 256 + c];
    float s1 = v, s2 = v * v;
    blockReduce2(s1, s2, red);
    float mu = s1 * (1.f / 256.f);
    float rs = rsqrtf(s2 * (1.f / 256.f) - mu * mu + EPSLN);
    out[(size_t)c * QLEN + q] = (v - mu) * rs * g[c] + b[c];
}

// ---------------- host launch ----------------
extern "C" void kernel_launch(void* const* d_in, const int* in_sizes, int n_in,
                              void* d_out, int out_size)
{
    const float* q        = (const float*)d_in[0];
    const float* k        = (const float*)d_in[1];
    const float* v        = (const float*)d_in[2];
    const float* skip     = (const float*)d_in[3];
    const void*  mask     = d_in[4];
    const float* ln_q_g   = (const float*)d_in[5];
    const float* ln_q_b   = (const float*)d_in[6];
    const float* wq       = (const float*)d_in[7];
    const float* bq       = (const float*)d_in[8];
    const float* ln_k_g   = (const float*)d_in[9];
    const float* ln_k_b   = (const float*)d_in[10];
    const float* wk       = (const float*)d_in[11];
    const float* bk       = (const float*)d_in[12];
    const float* ln_v_g   = (const float*)d_in[13];
    const float* ln_v_b   = (const float*)d_in[14];
    const float* wv       = (const float*)d_in[15];
    const float* bv       = (const float*)d_in[16];
    const float* w_proj   = (const float*)d_in[17];
    const float* b_proj   = (const float*)d_in[18];
    const float* ln_pre_g = (const float*)d_in[19];
    const float* ln_pre_b = (const float*)d_in[20];
    const float* w_mlp1   = (const float*)d_in[21];
    const float* b_mlp1   = (const float*)d_in[22];
    const float* w_mlp2   = (const float*)d_in[23];
    const float* b_mlp2   = (const float*)d_in[24];
    const float* ln_post_g= (const float*)d_in[25];
    const float* ln_post_b= (const float*)d_in[26];
    float* out = (float*)d_out;

    float *dot, *zp, *zln, *hp, *maskf, *biasvp;
    __half* t;
    uint32_t *qlnh, *qlnl, *qph, *qpl, *apreh, *aprel, *zlnh, *zlnl, *h1h, *h1l;
    uint32_t *pwq_h, *pwq_l, *pwk_h, *pwk_l, *pw1_h, *pw1_l, *pw2_h, *pw2_l;
    uint32_t *pvp_h, *pvp_l;
    cudaGetSymbolAddress((void**)&qlnh, g_qlnh); cudaGetSymbolAddress((void**)&qlnl, g_qlnl);
    cudaGetSymbolAddress((void**)&qph,  g_qph);  cudaGetSymbolAddress((void**)&qpl,  g_qpl);
    cudaGetSymbolAddress((void**)&t,    g_t);
    cudaGetSymbolAddress((void**)&dot,  g_dot);
    cudaGetSymbolAddress((void**)&apreh,g_apreh);cudaGetSymbolAddress((void**)&aprel,g_aprel);
    cudaGetSymbolAddress((void**)&zp,   g_zp);
    cudaGetSymbolAddress((void**)&zln,  g_zln);
    cudaGetSymbolAddress((void**)&zlnh, g_zlnh); cudaGetSymbolAddress((void**)&zlnl, g_zlnl);
    cudaGetSymbolAddress((void**)&h1h,  g_h1h);  cudaGetSymbolAddress((void**)&h1l,  g_h1l);
    cudaGetSymbolAddress((void**)&hp,   g_hp);
    cudaGetSymbolAddress((void**)&maskf,g_maskf);
    cudaGetSymbolAddress((void**)&pwq_h, g_pwq_h); cudaGetSymbolAddress((void**)&pwq_l, g_pwq_l);
    cudaGetSymbolAddress((void**)&pwk_h, g_pwk_h); cudaGetSymbolAddress((void**)&pwk_l, g_pwk_l);
    cudaGetSymbolAddress((void**)&pw1_h, g_pw1_h); cudaGetSymbolAddress((void**)&pw1_l, g_pw1_l);
    cudaGetSymbolAddress((void**)&pw2_h, g_pw2_h); cudaGetSymbolAddress((void**)&pw2_l, g_pw2_l);
    cudaGetSymbolAddress((void**)&pvp_h, g_pvp_h); cudaGetSymbolAddress((void**)&pvp_l, g_pvp_l);
    cudaGetSymbolAddress((void**)&biasvp,g_biasvp);

    cudaFuncSetAttribute(bgemm3, cudaFuncAttributeMaxDynamicSharedMemorySize, GSM);

    // 1
    k_mask<<<1, 256>>>((const unsigned char*)mask);
    // 2: q transpose + LN -> packed
    k_q_ln<<<dim3(QLEN / 32, NFR), 256>>>(q, ln_q_g, ln_q_b);
    // 3: pack weights + fused wv@w_proj (tiled)
    k_pack_all<<<768, 256>>>(wq, wk, w_mlp1, w_mlp2);
    k_fuse_vp<<<33, 256>>>(wv, bv, w_proj, b_proj);
    // 4: qp = qln @ wq + bq  -> packed only (2-pass)
    bgemm3<<<dim3(4, 192, 1), 256, GSM>>>(R_TOT, 256, 256,
                                          qlnh, qlnl, 128, 0,
                                          pwq_h, pwq_l, 0, bq, 0,
                                          nullptr, nullptr, 0, 0,
                                          qph, qpl, 128, 0, 8 | 16);
    // 5: t_m = qp_m @ wk_m^T (K=64) x4 heads -> fp16 (2-pass)
    bgemm3<<<dim3(4, 192, 4), 256, GSM>>>(R_TOT, 256, 64,
                                          qph, qpl, 128, 32,
                                          pwk_h, pwk_l, 256 * 32, nullptr, 0,
                                          nullptr, t, 1024, 256,
                                          nullptr, nullptr, 0, 0, 4 | 16);
    // 6: attention scores
    k_dot<<<R_TOT, 256>>>(k, qph, qpl, t, bk, ln_k_g, ln_k_b, maskf, dot);
    // 7: softmax + weighted LN(v) sums -> packed apre
    k_vacc<<<QLEN, 256>>>(v, dot, ln_v_g, ln_v_b);
    // 8: zp = apre @ Wvp + bias'  (K=1024, fused av+proj)
    bgemm3<<<dim3(4, 32, 1), 256, GSM>>>(QLEN, 256, 1024,
                                         apreh, aprel, 512, 0,
                                         pvp_h, pvp_l, 0, biasvp, 0,
                                         zp, nullptr, 256, 0,
                                         nullptr, nullptr, 0, 0, 1);
    // 9: zln = LN_pre(zp + skip) -> fp32 + packed
    k_ln_skip<<<QLEN, 256>>>(zp, skip, ln_pre_g, ln_pre_b, zln);
    // 10: h1 = gelu(zln @ w_mlp1 + b_mlp1) -> packed
    bgemm3<<<dim3(8, 32, 1), 256, GSM>>>(QLEN, 512, 256,
                                         zlnh, zlnl, 128, 0,
                                         pw1_h, pw1_l, 0, b_mlp1, 0,
                                         nullptr, nullptr, 0, 0,
                                         h1h, h1l, 256, 0, 10);
    // 11: hp = h1 @ w_mlp2 + b_mlp2 -> fp32
    bgemm3<<<dim3(4, 32, 1), 256, GSM>>>(QLEN, 256, 512,
                                         h1h, h1l, 256, 0,
                                         pw2_h, pw2_l, 0, b_mlp2, 0,
                                         hp, nullptr, 256, 0,
                                         nullptr, nullptr, 0, 0, 1);
    // 12
    k_ln_out<<<QLEN, 256>>>(zln, hp, ln_post_g, ln_post_b, out);
}

// round 15
// speedup vs baseline: 1.2300x; 1.0681x over previous
#include <cuda_runtime.h>
#include <cuda_bf16.h>
#include <cuda_fp16.h>
#include <math.h>
#include <stdint.h>

// ---------------- problem constants ----------------
#define QLEN   4096
#define NFR    6
#define GRP    8
#define DIMC   256
#define HEADS  4
#define NKEY   48
#define R_TOT  (NFR*QLEN)
#define EPSLN  1e-5f
#define SCALE  0.125f

// ---------------- scratch ----------------
__device__ uint32_t g_qlnh[R_TOT*128], g_qlnl[R_TOT*128];
__device__ uint32_t g_qph [R_TOT*128], g_qpl [R_TOT*128];
__device__ __half   g_t   [R_TOT*1024];
__device__ float    g_dot [QLEN*HEADS*NKEY];
__device__ uint32_t g_apreh[QLEN*512], g_aprel[QLEN*512];
__device__ uint32_t g_avh [QLEN*128], g_avl [QLEN*128];
__device__ float    g_zp  [QLEN*DIMC];
__device__ float    g_zln [QLEN*DIMC];
__device__ uint32_t g_zlnh[QLEN*128], g_zlnl[QLEN*128];
__device__ uint32_t g_h1h [QLEN*256], g_h1l [QLEN*256];
__device__ float    g_hp  [QLEN*DIMC];
__device__ float    g_maskf[R_TOT];
__device__ uint32_t g_pwq_h[256*128],  g_pwq_l[256*128];
__device__ uint32_t g_pwk_h[4*256*32], g_pwk_l[4*256*32];
__device__ uint32_t g_pwv_h[4*64*128], g_pwv_l[4*64*128];
__device__ uint32_t g_pwp_h[256*128],  g_pwp_l[256*128];
__device__ uint32_t g_pw1_h[512*128],  g_pw1_l[512*128];
__device__ uint32_t g_pw2_h[256*256],  g_pw2_l[256*256];

// ---------------- helpers ----------------
__device__ __forceinline__ void blockReduce2(float& s1, float& s2, float* red)
{
    int lane = threadIdx.x & 31, w = threadIdx.x >> 5;
#pragma unroll
    for (int o = 16; o > 0; o >>= 1) {
        s1 += __shfl_xor_sync(0xffffffffu, s1, o);
        s2 += __shfl_xor_sync(0xffffffffu, s2, o);
    }
    if (lane == 0) { red[w] = s1; red[8 + w] = s2; }
    __syncthreads();
    float a = 0.f, b = 0.f;
#pragma unroll
    for (int j = 0; j < 8; j++) { a += red[j]; b += red[8 + j]; }
    s1 = a; s2 = b;
    __syncthreads();
}

__device__ __forceinline__ uint32_t pack_hi(float x0, float x1)
{
    __nv_bfloat162 h = __floats2bfloat162_rn(x0, x1);
    return *reinterpret_cast<uint32_t*>(&h);
}
__device__ __forceinline__ uint32_t pack_lo(float x0, float x1, uint32_t hi)
{
    __nv_bfloat162 h = *reinterpret_cast<__nv_bfloat162*>(&hi);
    float r0 = x0 - __bfloat162float(h.x);
    float r1 = x1 - __bfloat162float(h.y);
    __nv_bfloat162 l = __floats2bfloat162_rn(r0, r1);
    return *reinterpret_cast<uint32_t*>(&l);
}

__device__ __forceinline__ void mma16(float* c, const uint32_t* a, const uint32_t b0, const uint32_t b1)
{
    asm volatile(
        "mma.sync.aligned.m16n8k16.row.col.f32.bf16.bf16.f32 "
        "{%0,%1,%2,%3}, {%4,%5,%6,%7}, {%8,%9}, {%0,%1,%2,%3};"
        : "+f"(c[0]), "+f"(c[1]), "+f"(c[2]), "+f"(c[3])
        : "r"(a[0]), "r"(a[1]), "r"(a[2]), "r"(a[3]), "r"(b0), "r"(b1));
}

__device__ __forceinline__ void ldsm_x4(uint32_t* r, uint32_t saddr)
{
    asm volatile("ldmatrix.sync.aligned.m8n8.x4.shared.b16 {%0,%1,%2,%3}, [%4];"
                 : "=r"(r[0]), "=r"(r[1]), "=r"(r[2]), "=r"(r[3]) : "r"(saddr));
}

__device__ __forceinline__ uint32_t smem_u32(const void* p)
{
    uint32_t a;
    asm("{ .reg .u64 t; cvta.to.shared.u64 t, %1; cvt.u32.u64 %0, t; }" : "=r"(a) : "l"(p));
    return a;
}

__device__ __forceinline__ void cp16(uint32_t dst, const void* src, bool pred)
{
    int sz = pred ? 16 : 0;
    asm volatile("cp.async.cg.shared.global [%0], [%1], 16, %2;"
                 :: "r"(dst), "l"(src), "r"(sz) : "memory");
}

// ---------------- K0: mask detect + normalize ----------------
__global__ void k_mask(const unsigned char* __restrict__ m8)
{
    __shared__ int fA, fB;
    if (threadIdx.x == 0) { fA = 0; fB = 0; }
    __syncthreads();
    for (int i = threadIdx.x; i < NFR * QLEN; i += 256) {
        unsigned char b = m8[i];
        if (b == 1) {
            if ((i & 3) == 0) fA = 1;
            else              fB = 1;
        }
    }
    __syncthreads();
    int mode = fB ? 0 : (fA ? 1 : 2);
    for (int i = threadIdx.x; i < NFR * QLEN; i += 256) {
        float r;
        if (mode == 0)      r = (m8[i] != 0) ? 1.f : 0.f;
        else if (mode == 1) r = (((const int*)m8)[i] != 0) ? 1.f : 0.f;
        else                r = (((const float*)m8)[i] != 0.f) ? 1.f : 0.f;
        g_maskf[i] = r;
    }
}

// ---------------- K1: transpose q + LayerNorm -> packed pairs ----------------
__global__ __launch_bounds__(256)
void k_q_ln(const float* __restrict__ q, const float* __restrict__ g,
            const float* __restrict__ b)
{
    __shared__ float tile[256][33];
    __shared__ float s_mu[32], s_rs[32];
    __shared__ float s_part[2][8][32];
    int n  = blockIdx.y;
    int p0 = blockIdx.x * 32;
    int t  = threadIdx.x;
    int px = t & 31, cy = t >> 5;
    const float* qn = q + (size_t)n * DIMC * QLEN;
    float s1 = 0.f, s2 = 0.f;
    for (int c = cy; c < DIMC; c += 8) {
        float v = qn[(size_t)c * QLEN + p0 + px];
        tile[c][px] = v;
        s1 += v; s2 += v * v;
    }
    s_part[0][cy][px] = s1; s_part[1][cy][px] = s2;
    __syncthreads();
    if (cy == 0) {
        float a = 0.f, bb = 0.f;
#pragma unroll
        for (int j = 0; j < 8; j++) { a += s_part[0][j][px]; bb += s_part[1][j][px]; }
        float mu = a * (1.f / 256.f);
        float var = bb * (1.f / 256.f) - mu * mu;
        s_mu[px] = mu; s_rs[px] = rsqrtf(var + EPSLN);
    }
    __syncthreads();
    float gg = g[t], bv = b[t];
    size_t rbase = (size_t)n * QLEN + p0;
#pragma unroll 4
    for (int pp = 0; pp < 32; pp++) {
        float val = (tile[t][pp] - s_mu[pp]) * s_rs[pp] * gg + bv;
        float vo = __shfl_down_sync(0xffffffffu, val, 1);
        if (!(t & 1)) {
            uint32_t h = pack_hi(val, vo);
            size_t o = (rbase + pp) * 128 + (t >> 1);
            g_qlnh[o] = h;
            g_qlnl[o] = pack_lo(val, vo, h);
        }
    }
}

// ---------------- K2: pack ALL 6 weights (262144 elems = 1024 blocks) ----------------
__global__ __launch_bounds__(256)
void k_pack_all(const float* __restrict__ wq, const float* __restrict__ wk,
                const float* __restrict__ wv, const float* __restrict__ wp,
                const float* __restrict__ w1, const float* __restrict__ w2)
{
    long i = (long)blockIdx.x * 256 + threadIdx.x;
    if (i >= 262144) return;
    const float* src; int sn, sk; long zo; int N, Kp; uint32_t *dh, *dl; long rem;
    if (i < 32768)       { rem = i;          src = wq; sn = 1;   sk = 256; zo = 0;  N = 256; Kp = 128; dh = g_pwq_h; dl = g_pwq_l; }
    else if (i < 65536)  { rem = i - 32768;  src = wk; sn = 256; sk = 1;   zo = 64; N = 256; Kp = 32;  dh = g_pwk_h; dl = g_pwk_l; }
    else if (i < 98304)  { rem = i - 65536;  src = wv; sn = 1;   sk = 256; zo = 64; N = 64;  Kp = 128; dh = g_pwv_h; dl = g_pwv_l; }
    else if (i < 131072) { rem = i - 98304;  src = wp; sn = 1;   sk = 256; zo = 0;  N = 256; Kp = 128; dh = g_pwp_h; dl = g_pwp_l; }
    else if (i < 196608) { rem = i - 131072; src = w1; sn = 1;   sk = 512; zo = 0;  N = 512; Kp = 128; dh = g_pw1_h; dl = g_pw1_l; }
    else                 { rem = i - 196608; src = w2; sn = 1;   sk = 256; zo = 0;  N = 256; Kp = 256; dh = g_pw2_h; dl = g_pw2_l; }
    long NK = (long)N * Kp;
    long z = rem / NK, j = rem - z * NK;
    int n = (int)(j / Kp), kp = (int)(j - (long)n * Kp);
    const float* s = src + z * zo;
    float x0 = s[(size_t)n * sn + (size_t)(2 * kp) * sk];
    float x1 = s[(size_t)n * sn + (size_t)(2 * kp + 1) * sk];
    uint32_t h = pack_hi(x0, x1);
    dh[rem] = h;
    dl[rem] = pack_lo(x0, x1, h);
}

// ---------------- pipelined bf16x2 tensor GEMM, tile 128x64, 2 CTA/SM ----------------
// flags: 1 fp32, 2 gelu, 4 fp16, 8 packed, 16 = 2-pass (skip B_lo fills AND mma).
#define STG_A_H 0
#define STG_A_L 16384
#define STG_B_H 32768
#define STG_B_L 40960
#define STG_SZ  49152
#define GSM     (2*STG_SZ)

__global__ __launch_bounds__(256, 2)
void bgemm3(int M, int N, int K,
            const uint32_t* __restrict__ Ah, const uint32_t* __restrict__ Al,
            int ldap, long aoz,
            const uint32_t* __restrict__ Bh, const uint32_t* __restrict__ Bl, long bzs,
            const float* __restrict__ bias, int bioz,
            float* __restrict__ Cf, __half* __restrict__ Chalf, int ldc, long coz,
            uint32_t* __restrict__ Ph, uint32_t* __restrict__ Pl, int ldp, long poz,
            int flags)
{
    extern __shared__ char smem[];
    uint32_t sbase = smem_u32(smem);
    int z = blockIdx.z;
    Ah += (size_t)z * aoz; Al += (size_t)z * aoz;
    Bh += (size_t)z * bzs; Bl += (size_t)z * bzs;
    if (bias) bias += (size_t)z * bioz;
    int Kp = K >> 1;
    const bool pass3 = !(flags & 16);

    int tid = threadIdx.x, lane = tid & 31, wid = tid >> 5;
    int wm = wid & 3, wn = wid >> 2;
    int g = lane >> 2, t = lane & 3;
    int bm = blockIdx.y * 128, bn = blockIdx.x * 64;

    float acc[2][4][4] = {};

    int frow0 = tid >> 3, fseg = tid & 7;

    auto fill = [&](int ch, int st) {
        uint32_t stb = sbase + st * STG_SZ;
        int kp0 = ch << 5;
#pragma unroll
        for (int x = 0; x < 4; x++) {
            int row = x * 32 + frow0;
            uint32_t soff = (uint32_t)(row * 128 + ((fseg ^ (row & 7)) << 4));
            size_t ga = (size_t)(bm + row) * ldap + kp0 + fseg * 4;
            cp16(stb + STG_A_H + soff, Ah + ga, true);
            cp16(stb + STG_A_L + soff, Al + ga, true);
        }
#pragma unroll
        for (int x = 0; x < 2; x++) {
            int row = x * 32 + frow0;
            uint32_t soff = (uint32_t)(row * 128 + ((fseg ^ (row & 7)) << 4));
            bool bvld = (bn + row) < N;
            size_t gb = bvld ? ((size_t)(bn + row) * Kp + kp0 + fseg * 4) : 0;
            cp16(stb + STG_B_H + soff, Bh + gb, bvld);
            if (pass3) cp16(stb + STG_B_L + soff, Bl + gb, bvld);
        }
    };

    auto compute = [&](int st) {
        uint32_t stb = sbase + st * STG_SZ;
#pragma unroll
        for (int ks = 0; ks < 4; ks++) {
            int s0 = ks * 2;
            uint32_t ah[2][4], al[2][4];
#pragma unroll
            for (int i = 0; i < 2; i++) {
                int ml = wm * 32 + i * 16 + (lane & 15);
                int seg = s0 + (lane >> 4);
                uint32_t off = (uint32_t)(ml * 128 + ((seg ^ (ml & 7)) << 4));
                ldsm_x4(ah[i], stb + STG_A_H + off);
                ldsm_x4(al[i], stb + STG_A_L + off);
            }
#pragma unroll
            for (int j2 = 0; j2 < 2; j2++) {
                int nl = wn * 32 + j2 * 16 + (lane & 15);
                int seg = s0 + (lane >> 4);
                uint32_t off = (uint32_t)(nl * 128 + ((seg ^ (nl & 7)) << 4));
                uint32_t bh[4], bl[4];
                ldsm_x4(bh, stb + STG_B_H + off);
                if (pass3) ldsm_x4(bl, stb + STG_B_L + off);
#pragma unroll
                for (int jj = 0; jj < 2; jj++) {
                    int j = j2 * 2 + jj;
                    uint32_t bh0 = jj ? bh[1] : bh[0];
                    uint32_t bh1 = jj ? bh[3] : bh[2];
#pragma unroll
                    for (int i = 0; i < 2; i++) {
                        mma16(acc[i][j], ah[i], bh0, bh1);
                        mma16(acc[i][j], al[i], bh0, bh1);
                        if (pass3) {
                            uint32_t bl0 = jj ? bl[1] : bl[0];
                            uint32_t bl1 = jj ? bl[3] : bl[2];
                            mma16(acc[i][j], ah[i], bl0, bl1);
                        }
                    }
                }
            }
        }
    };

    int nch = K >> 6;
    fill(0, 0);
    asm volatile("cp.async.commit_group;" ::: "memory");
    for (int c = 0; c < nch; c++) {
        if (c + 1 < nch) {
            fill(c + 1, (c + 1) & 1);
            asm volatile("cp.async.commit_group;" ::: "memory");
            asm volatile("cp.async.wait_group 1;" ::: "memory");
        } else {
            asm volatile("cp.async.wait_group 0;" ::: "memory");
        }
        __syncthreads();
        compute(c & 1);
        __syncthreads();
    }

    // ---- epilogue ----
#pragma unroll
    for (int i = 0; i < 2; i++) {
        int r0 = bm + wm * 32 + i * 16 + g;
#pragma unroll
        for (int j = 0; j < 4; j++) {
            int c0 = bn + wn * 32 + j * 8 + t * 2;
            if (c0 >= N) continue;
            float b0v = bias ? bias[c0] : 0.f;
            float b1v = bias ? bias[c0 + 1] : 0.f;
            float v0 = acc[i][j][0] + b0v;
            float v1 = acc[i][j][1] + b1v;
            float v2 = acc[i][j][2] + b0v;
            float v3 = acc[i][j][3] + b1v;
            if (flags & 2) {
                v0 = 0.5f * v0 * (1.f + erff(v0 * 0.70710678118654752f));
                v1 = 0.5f * v1 * (1.f + erff(v1 * 0.70710678118654752f));
                v2 = 0.5f * v2 * (1.f + erff(v2 * 0.70710678118654752f));
                v3 = 0.5f * v3 * (1.f + erff(v3 * 0.70710678118654752f));
            }
            if (flags & 1) {
                float* C = Cf + (size_t)z * coz;
                *(float2*)&C[(size_t)r0 * ldc + c0]       = make_float2(v0, v1);
                *(float2*)&C[(size_t)(r0 + 8) * ldc + c0] = make_float2(v2, v3);
            }
            if (flags & 4) {
                __half* C = Chalf + (size_t)z * coz;
                *(__half2*)&C[(size_t)r0 * ldc + c0]       = __floats2half2_rn(v0, v1);
                *(__half2*)&C[(size_t)(r0 + 8) * ldc + c0] = __floats2half2_rn(v2, v3);
            }
            if (flags & 8) {
                uint32_t* PH = Ph + (size_t)z * poz;
                uint32_t* PL = Pl + (size_t)z * poz;
                int pidx = c0 >> 1;
                uint32_t h0 = pack_hi(v0, v1);
                PH[(size_t)r0 * ldp + pidx] = h0;
                PL[(size_t)r0 * ldp + pidx] = pack_lo(v0, v1, h0);
                uint32_t h1 = pack_hi(v2, v3);
                PH[(size_t)(r0 + 8) * ldp + pidx] = h1;
                PL[(size_t)(r0 + 8) * ldp + pidx] = pack_lo(v2, v3, h1);
            }
        }
    }
}

// ---------------- specialized t-GEMM: K=64, B reused across 4 M-blocks, pipelined ----------------
// t_m = qp_m @ wk_m^T, 2-pass bf16x2, fp16 out. grid (4, 48, 4heads).
#define T_AH  0
#define T_AL  16384
#define T_STG 32768
#define T_B   65536
#define TGSM  (65536 + 8192)

__global__ __launch_bounds__(256, 2)
void tgemm_t(const uint32_t* __restrict__ Ah, const uint32_t* __restrict__ Al,
             const uint32_t* __restrict__ Bh, __half* __restrict__ C)
{
    extern __shared__ char smem[];
    uint32_t sbase = smem_u32(smem);
    int z = blockIdx.z;
    Ah += (size_t)z * 32; Al += (size_t)z * 32;      // head column slice of qp (pairs)
    Bh += (size_t)z * (256 * 32);                    // wk head slice
    C  += (size_t)z * 256;

    int tid = threadIdx.x, lane = tid & 31, wid = tid >> 5;
    int wm = wid & 3, wn = wid >> 2;
    int g = lane >> 2, t = lane & 3;
    int bn = blockIdx.x * 64;
    int bm0 = blockIdx.y * 512;

    // B fill once (hi only; 2-pass drops B_lo)
#pragma unroll
    for (int i = 0; i < 2; i++) {
        int u = i * 256 + tid;
        int row = u >> 3, seg = u & 7;
        uint32_t soff = (uint32_t)(row * 128 + ((seg ^ (row & 7)) << 4));
        cp16(sbase + T_B + soff, Bh + (size_t)(bn + row) * 32 + seg * 4, true);
    }
    auto fillA = [&](int rb, int st) {
        uint32_t stb = sbase + st * T_STG;
        int bm = bm0 + rb * 128;
#pragma unroll
        for (int i = 0; i < 4; i++) {
            int u = i * 256 + tid;
            int row = u >> 3, seg = u & 7;
            uint32_t soff = (uint32_t)(row * 128 + ((seg ^ (row & 7)) << 4));
            size_t ga = (size_t)(bm + row) * 128 + seg * 4;
            cp16(stb + T_AH + soff, Ah + ga, true);
            cp16(stb + T_AL + soff, Al + ga, true);
        }
    };

    float acc[2][4][4] = {};
    fillA(0, 0);
    asm volatile("cp.async.commit_group;" ::: "memory");
    for (int rb = 0; rb < 4; rb++) {
        if (rb < 3) {
            fillA(rb + 1, (rb + 1) & 1);
            asm volatile("cp.async.commit_group;" ::: "memory");
            asm volatile("cp.async.wait_group 1;" ::: "memory");
        } else {
            asm volatile("cp.async.wait_group 0;" ::: "memory");
        }
        __syncthreads();
        uint32_t stb = sbase + (rb & 1) * T_STG;
#pragma unroll
        for (int ks = 0; ks < 4; ks++) {
            int s0 = ks * 2;
            uint32_t ah[2][4], al[2][4];
#pragma unroll
            for (int i = 0; i < 2; i++) {
                int ml = wm * 32 + i * 16 + (lane & 15);
                int seg = s0 + (lane >> 4);
                uint32_t off = (uint32_t)(ml * 128 + ((seg ^ (ml & 7)) << 4));
                ldsm_x4(ah[i], stb + T_AH + off);
                ldsm_x4(al[i], stb + T_AL + off);
            }
#pragma unroll
            for (int j2 = 0; j2 < 2; j2++) {
                int nl = wn * 32 + j2 * 16 + (lane & 15);
                int seg = s0 + (lane >> 4);
                uint32_t off = (uint32_t)(nl * 128 + ((seg ^ (nl & 7)) << 4));
                uint32_t bh[4];
                ldsm_x4(bh, sbase + T_B + off);
#pragma unroll
                for (int jj = 0; jj < 2; jj++) {
                    int j = j2 * 2 + jj;
                    uint32_t bh0 = jj ? bh[1] : bh[0];
                    uint32_t bh1 = jj ? bh[3] : bh[2];
#pragma unroll
                    for (int i = 0; i < 2; i++) {
                        mma16(acc[i][j], ah[i], bh0, bh1);
                        mma16(acc[i][j], al[i], bh0, bh1);
                    }
                }
            }
        }
        int bm = bm0 + rb * 128;
#pragma unroll
        for (int i = 0; i < 2; i++) {
            int r0 = bm + wm * 32 + i * 16 + g;
#pragma unroll
            for (int j = 0; j < 4; j++) {
                int c0 = bn + wn * 32 + j * 8 + t * 2;
                *(__half2*)&C[(size_t)r0 * 1024 + c0]       = __floats2half2_rn(acc[i][j][0], acc[i][j][1]);
                *(__half2*)&C[(size_t)(r0 + 8) * 1024 + c0] = __floats2half2_rn(acc[i][j][2], acc[i][j][3]);
                acc[i][j][0] = acc[i][j][1] = acc[i][j][2] = acc[i][j][3] = 0.f;
            }
        }
        __syncthreads();
    }
}

// ---------------- K4: attention scores (smem-staged t) ----------------
__global__ __launch_bounds__(256)
void k_dot(const float* __restrict__ kten,
           const uint32_t* __restrict__ qph, const uint32_t* __restrict__ qpl,
           const __half* __restrict__ tg, const float* __restrict__ bk,
           const float* __restrict__ lng, const float* __restrict__ lnb,
           const float* __restrict__ maskf, float* __restrict__ dotp)
{
    int r = blockIdx.x;
    int n = r >> 12, q = r & 4095;
    int tid = threadIdx.x, lane = tid & 31, w = tid >> 5;
    __shared__ float ts[1024];
    __shared__ float bd[4];
    __shared__ float sg[256], sb[256];
    const __half* trow = tg + (size_t)r * 1024;
    {
        uint2 tu = *(const uint2*)(trow + tid * 4);
        __half2 h0 = *reinterpret_cast<__half2*>(&tu.x);
        __half2 h1 = *reinterpret_cast<__half2*>(&tu.y);
        float2 f0 = __half22float2(h0);
        float2 f1 = __half22float2(h1);
        ts[tid * 4 + 0] = f0.x;
        ts[tid * 4 + 1] = f0.y;
        ts[tid * 4 + 2] = f1.x;
        ts[tid * 4 + 3] = f1.y;
    }
    sg[tid] = lng[tid]; sb[tid] = lnb[tid];
    if (w < 4) {
        uint32_t hh = qph[(size_t)r * 128 + w * 32 + lane];
        uint32_t ll = qpl[(size_t)r * 128 + w * 32 + lane];
        __nv_bfloat162 h2 = *reinterpret_cast<__nv_bfloat162*>(&hh);
        __nv_bfloat162 l2 = *reinterpret_cast<__nv_bfloat162*>(&ll);
        float a0 = __bfloat162float(h2.x) + __bfloat162float(l2.x);
        float a1 = __bfloat162float(h2.y) + __bfloat162float(l2.y);
        const float* bkr = bk + w * 64;
        float p = a0 * bkr[2 * lane] + a1 * bkr[2 * lane + 1];
#pragma unroll
        for (int o = 16; o > 0; o >>= 1) p += __shfl_xor_sync(0xffffffffu, p, o);
        if (lane == 0) bd[w] = p;
    }
    __syncthreads();
    const float* krow = kten + ((size_t)r * GRP + w) * 256;
    float v[8];
    float s1 = 0.f, s2 = 0.f;
#pragma unroll
    for (int j = 0; j < 8; j++) {
        v[j] = krow[lane + 32 * j];
        s1 += v[j]; s2 += v[j] * v[j];
    }
#pragma unroll
    for (int o = 16; o > 0; o >>= 1) {
        s1 += __shfl_xor_sync(0xffffffffu, s1, o);
        s2 += __shfl_xor_sync(0xffffffffu, s2, o);
    }
    float mu = s1 * (1.f / 256.f);
    float rs = rsqrtf(s2 * (1.f / 256.f) - mu * mu + EPSLN);
    float d0 = 0.f, d1 = 0.f, d2 = 0.f, d3 = 0.f;
#pragma unroll
    for (int j = 0; j < 8; j++) {
        int c = lane + 32 * j;
        float lv = (v[j] - mu) * rs * sg[c] + sb[c];
        d0 += lv * ts[c];
        d1 += lv * ts[256 + c];
        d2 += lv * ts[512 + c];
        d3 += lv * ts[768 + c];
    }
#pragma unroll
    for (int o = 16; o > 0; o >>= 1) {
        d0 += __shfl_xor_sync(0xffffffffu, d0, o);
        d1 += __shfl_xor_sync(0xffffffffu, d1, o);
        d2 += __shfl_xor_sync(0xffffffffu, d2, o);
        d3 += __shfl_xor_sync(0xffffffffu, d3, o);
    }
    if (lane == 0) {
        bool mk = maskf[r] != 0.f;
        float dm[4] = {d0, d1, d2, d3};
        size_t base = (size_t)q * (HEADS * NKEY) + (size_t)n * GRP + w;
#pragma unroll
        for (int m = 0; m < 4; m++)
            dotp[base + (size_t)m * NKEY] = mk ? SCALE * (dm[m] + bd[m]) : -1e9f;
    }
}

// ---------------- K6: softmax (fused) + weighted sum of LN(v) -> packed ----------------
__global__ __launch_bounds__(256)
void k_vacc(const float* __restrict__ vten, const float* __restrict__ dotp,
            const float* __restrict__ lng, const float* __restrict__ lnb)
{
    __shared__ float sa[HEADS * NKEY];
    __shared__ float part[8][1024];
    int q = blockIdx.x, tid = threadIdx.x, lane = tid & 31, w = tid >> 5;
    if (w < 4) {
        const float* p = dotp + (size_t)q * (HEADS * NKEY) + w * NKEY;
        float v0 = p[lane];
        float v1 = (lane < 16) ? p[32 + lane] : -3.4e38f;
        float mx = fmaxf(v0, v1);
#pragma unroll
        for (int o = 16; o > 0; o >>= 1) mx = fmaxf(mx, __shfl_xor_sync(0xffffffffu, mx, o));
        float e0 = expf(v0 - mx);
        float e1 = (lane < 16) ? expf(v1 - mx) : 0.f;
        float s = e0 + e1;
#pragma unroll
        for (int o = 16; o > 0; o >>= 1) s += __shfl_xor_sync(0xffffffffu, s, o);
        float inv = 1.f / s;
        sa[w * NKEY + lane] = e0 * inv;
        if (lane < 16) sa[w * NKEY + 32 + lane] = e1 * inv;
    }
    int c0 = lane * 8;
    float gv[8], bb[8];
    {
        float4 gA = *(const float4*)(lng + c0);
        float4 gB = *(const float4*)(lng + c0 + 4);
        float4 bA = *(const float4*)(lnb + c0);
        float4 bB = *(const float4*)(lnb + c0 + 4);
        gv[0]=gA.x; gv[1]=gA.y; gv[2]=gA.z; gv[3]=gA.w;
        gv[4]=gB.x; gv[5]=gB.y; gv[6]=gB.z; gv[7]=gB.w;
        bb[0]=bA.x; bb[1]=bA.y; bb[2]=bA.z; bb[3]=bA.w;
        bb[4]=bB.x; bb[5]=bB.y; bb[6]=bB.z; bb[7]=bB.w;
    }
    __syncthreads();
    float acc[4][8] = {};
    for (int n = 0; n < NFR; n++) {
        const float* vr = vten + (((size_t)n * QLEN + q) * GRP + w) * 256 + c0;
        float4 v0 = *(const float4*)vr;
        float4 v1 = *(const float4*)(vr + 4);
        float vv[8] = {v0.x, v0.y, v0.z, v0.w, v1.x, v1.y, v1.z, v1.w};
        float s1 = 0.f, s2 = 0.f;
#pragma unroll
        for (int j = 0; j < 8; j++) { s1 += vv[j]; s2 += vv[j] * vv[j]; }
#pragma unroll
        for (int o = 16; o > 0; o >>= 1) {
            s1 += __shfl_xor_sync(0xffffffffu, s1, o);
            s2 += __shfl_xor_sync(0xffffffffu, s2, o);
        }
        float mu = s1 * (1.f / 256.f);
        float rs = rsqrtf(s2 * (1.f / 256.f) - mu * mu + EPSLN);
        float aw0 = sa[0 * NKEY + n * 8 + w];
        float aw1 = sa[1 * NKEY + n * 8 + w];
        float aw2 = sa[2 * NKEY + n * 8 + w];
        float aw3 = sa[3 * NKEY + n * 8 + w];
#pragma unroll
        for (int j = 0; j < 8; j++) {
            float lv = (vv[j] - mu) * rs * gv[j] + bb[j];
            acc[0][j] += aw0 * lv;
            acc[1][j] += aw1 * lv;
            acc[2][j] += aw2 * lv;
            acc[3][j] += aw3 * lv;
        }
    }
#pragma unroll
    for (int m = 0; m < 4; m++) {
        float4 p0 = make_float4(acc[m][0], acc[m][1], acc[m][2], acc[m][3]);
        float4 p1 = make_float4(acc[m][4], acc[m][5], acc[m][6], acc[m][7]);
        *(float4*)&part[w][m * 256 + c0]     = p0;
        *(float4*)&part[w][m * 256 + c0 + 4] = p1;
    }
    __syncthreads();
#pragma unroll
    for (int m = 0; m < 4; m++) {
        float s = 0.f;
#pragma unroll
        for (int w8 = 0; w8 < 8; w8++) s += part[w8][m * 256 + tid];
        float so = __shfl_down_sync(0xffffffffu, s, 1);
        if (!(tid & 1)) {
            uint32_t h = pack_hi(s, so);
            size_t o = (size_t)q * 512 + m * 128 + (tid >> 1);
            g_apreh[o] = h;
            g_aprel[o] = pack_lo(s, so, h);
        }
    }
}

// ---------------- K7: z = LN_pre(zp + skip^T) -> fp32 + packed ----------------
__global__ __launch_bounds__(256)
void k_ln_skip(const float* __restrict__ zp, const float* __restrict__ skip,
               const float* __restrict__ g, const float* __restrict__ b,
               float* __restrict__ zln)
{
    __shared__ float red[16];
    int q = blockIdx.x, c = threadIdx.x;
    float v = zp[(size_t)q * 256 + c] + skip[(size_t)c * QLEN + q];
    float s1 = v, s2 = v * v;
    blockReduce2(s1, s2, red);
    float mu = s1 * (1.f / 256.f);
    float rs = rsqrtf(s2 * (1.f / 256.f) - mu * mu + EPSLN);
    float val = (v - mu) * rs * g[c] + b[c];
    zln[(size_t)q * 256 + c] = val;
    float vo = __shfl_down_sync(0xffffffffu, val, 1);
    if (!(c & 1)) {
        uint32_t h = pack_hi(val, vo);
        size_t o = (size_t)q * 128 + (c >> 1);
        g_zlnh[o] = h;
        g_zlnl[o] = pack_lo(val, vo, h);
    }
}

// ---------------- K8: out = LN_post(zln + hp), transposed store ----------------
__global__ __launch_bounds__(256)
void k_ln_out(const float* __restrict__ zln, const float* __restrict__ hp,
              const float* __restrict__ g, const float* __restrict__ b,
              float* __restrict__ out)
{
    __shared__ float red[16];
    int q = blockIdx.x, c = threadIdx.x;
    float v = zln[(size_t)q * 256 + c] + hp[(size_t)q * 256 + c];
    float s1 = v, s2 = v * v;
    blockReduce2(s1, s2, red);
    float mu = s1 * (1.f / 256.f);
    float rs = rsqrtf(s2 * (1.f / 256.f) - mu * mu + EPSLN);
    out[(size_t)c * QLEN + q] = (v - mu) * rs * g[c] + b[c];
}

// ---------------- host launch ----------------
extern "C" void kernel_launch(void* const* d_in, const int* in_sizes, int n_in,
                              void* d_out, int out_size)
{
    const float* q        = (const float*)d_in[0];
    const float* k        = (const float*)d_in[1];
    const float* v        = (const float*)d_in[2];
    const float* skip     = (const float*)d_in[3];
    const void*  mask     = d_in[4];
    const float* ln_q_g   = (const float*)d_in[5];
    const float* ln_q_b   = (const float*)d_in[6];
    const float* wq       = (const float*)d_in[7];
    const float* bq       = (const float*)d_in[8];
    const float* ln_k_g   = (const float*)d_in[9];
    const float* ln_k_b   = (const float*)d_in[10];
    const float* wk       = (const float*)d_in[11];
    const float* bk       = (const float*)d_in[12];
    const float* ln_v_g   = (const float*)d_in[13];
    const float* ln_v_b   = (const float*)d_in[14];
    const float* wv       = (const float*)d_in[15];
    const float* bv       = (const float*)d_in[16];
    const float* w_proj   = (const float*)d_in[17];
    const float* b_proj   = (const float*)d_in[18];
    const float* ln_pre_g = (const float*)d_in[19];
    const float* ln_pre_b = (const float*)d_in[20];
    const float* w_mlp1   = (const float*)d_in[21];
    const float* b_mlp1   = (const float*)d_in[22];
    const float* w_mlp2   = (const float*)d_in[23];
    const float* b_mlp2   = (const float*)d_in[24];
    const float* ln_post_g= (const float*)d_in[25];
    const float* ln_post_b= (const float*)d_in[26];
    float* out = (float*)d_out;

    float *dot, *zp, *zln, *hp, *maskf;
    __half* t;
    uint32_t *qlnh, *qlnl, *qph, *qpl, *apreh, *aprel, *avh, *avl, *zlnh, *zlnl, *h1h, *h1l;
    uint32_t *pwq_h, *pwq_l, *pwk_h, *pwk_l, *pwv_h, *pwv_l;
    uint32_t *pwp_h, *pwp_l, *pw1_h, *pw1_l, *pw2_h, *pw2_l;
    cudaGetSymbolAddress((void**)&qlnh, g_qlnh); cudaGetSymbolAddress((void**)&qlnl, g_qlnl);
    cudaGetSymbolAddress((void**)&qph,  g_qph);  cudaGetSymbolAddress((void**)&qpl,  g_qpl);
    cudaGetSymbolAddress((void**)&t,    g_t);
    cudaGetSymbolAddress((void**)&dot,  g_dot);
    cudaGetSymbolAddress((void**)&apreh,g_apreh);cudaGetSymbolAddress((void**)&aprel,g_aprel);
    cudaGetSymbolAddress((void**)&avh,  g_avh);  cudaGetSymbolAddress((void**)&avl,  g_avl);
    cudaGetSymbolAddress((void**)&zp,   g_zp);
    cudaGetSymbolAddress((void**)&zln,  g_zln);
    cudaGetSymbolAddress((void**)&zlnh, g_zlnh); cudaGetSymbolAddress((void**)&zlnl, g_zlnl);
    cudaGetSymbolAddress((void**)&h1h,  g_h1h);  cudaGetSymbolAddress((void**)&h1l,  g_h1l);
    cudaGetSymbolAddress((void**)&hp,   g_hp);
    cudaGetSymbolAddress((void**)&maskf,g_maskf);
    cudaGetSymbolAddress((void**)&pwq_h, g_pwq_h); cudaGetSymbolAddress((void**)&pwq_l, g_pwq_l);
    cudaGetSymbolAddress((void**)&pwk_h, g_pwk_h); cudaGetSymbolAddress((void**)&pwk_l, g_pwk_l);
    cudaGetSymbolAddress((void**)&pwv_h, g_pwv_h); cudaGetSymbolAddress((void**)&pwv_l, g_pwv_l);
    cudaGetSymbolAddress((void**)&pwp_h, g_pwp_h); cudaGetSymbolAddress((void**)&pwp_l, g_pwp_l);
    cudaGetSymbolAddress((void**)&pw1_h, g_pw1_h); cudaGetSymbolAddress((void**)&pw1_l, g_pw1_l);
    cudaGetSymbolAddress((void**)&pw2_h, g_pw2_h); cudaGetSymbolAddress((void**)&pw2_l, g_pw2_l);

    cudaFuncSetAttribute(bgemm3, cudaFuncAttributeMaxDynamicSharedMemorySize, GSM);
    cudaFuncSetAttribute(tgemm_t, cudaFuncAttributeMaxDynamicSharedMemorySize, TGSM);

    // 1
    k_mask<<<1, 256>>>((const unsigned char*)mask);
    // 2: q transpose + LN -> packed
    k_q_ln<<<dim3(QLEN / 32, NFR), 256>>>(q, ln_q_g, ln_q_b);
    // 3: pack weights
    k_pack_all<<<1024, 256>>>(wq, wk, wv, w_proj, w_mlp1, w_mlp2);
    // 4: qp = qln @ wq + bq  -> packed only (2-pass)
    bgemm3<<<dim3(4, 192, 1), 256, GSM>>>(R_TOT, 256, 256,
                                          qlnh, qlnl, 128, 0,
                                          pwq_h, pwq_l, 0, bq, 0,
                                          nullptr, nullptr, 0, 0,
                                          qph, qpl, 128, 0, 8 | 16);
    // 5: t_m = qp_m @ wk_m^T (K=64) x4 heads -> fp16 (specialized, B reused, pipelined M-loop)
    tgemm_t<<<dim3(4, 48, 4), 256, TGSM>>>(qph, qpl, pwk_h, t);
    // 6: attention scores
    k_dot<<<R_TOT, 256>>>(k, qph, qpl, t, bk, ln_k_g, ln_k_b, maskf, dot);
    // 7: softmax + weighted LN(v) sums -> packed apre
    k_vacc<<<QLEN, 256>>>(v, dot, ln_v_g, ln_v_b);
    // 8: a_m = apre_m @ wv_m + bv_m (N=64, K=256) x4 heads -> packed av
    bgemm3<<<dim3(1, 32, 4), 256, GSM>>>(QLEN, 64, 256,
                                         apreh, aprel, 512, 128,
                                         pwv_h, pwv_l, 64 * 128, bv, 64,
                                         nullptr, nullptr, 0, 0,
                                         avh, avl, 128, 32, 8);
    // 9: zp = av @ w_proj + b_proj -> fp32
    bgemm3<<<dim3(4, 32, 1), 256, GSM>>>(QLEN, 256, 256,
                                         avh, avl, 128, 0,
                                         pwp_h, pwp_l, 0, b_proj, 0,
                                         zp, nullptr, 256, 0,
                                         nullptr, nullptr, 0, 0, 1);
    // 10: zln = LN_pre(zp + skip) -> fp32 + packed
    k_ln_skip<<<QLEN, 256>>>(zp, skip, ln_pre_g, ln_pre_b, zln);
    // 11: h1 = gelu(zln @ w_mlp1 + b_mlp1) -> packed
    bgemm3<<<dim3(8, 32, 1), 256, GSM>>>(QLEN, 512, 256,
                                         zlnh, zlnl, 128, 0,
                                         pw1_h, pw1_l, 0, b_mlp1, 0,
                                         nullptr, nullptr, 0, 0,
                                         h1h, h1l, 256, 0, 10);
    // 12: hp = h1 @ w_mlp2 + b_mlp2 -> fp32
    bgemm3<<<dim3(4, 32, 1), 256, GSM>>>(QLEN, 256, 512,
                                         h1h, h1l, 256, 0,
                                         pw2_h, pw2_l, 0, b_mlp2, 0,
                                         hp, nullptr, 256, 0,
                                         nullptr, nullptr, 0, 0, 1);
    // 13
    k_ln_out<<<QLEN, 256>>>(zln, hp, ln_post_g, ln_post_b, out);
}

// round 16
// speedup vs baseline: 1.2525x; 1.0183x over previous
#include <cuda_runtime.h>
#include <cuda_bf16.h>
#include <cuda_fp16.h>
#include <math.h>
#include <stdint.h>

// ---------------- problem constants ----------------
#define QLEN   4096
#define NFR    6
#define GRP    8
#define DIMC   256
#define HEADS  4
#define NKEY   48
#define R_TOT  (NFR*QLEN)
#define EPSLN  1e-5f
#define SCALE  0.125f

// ---------------- scratch ----------------
__device__ uint32_t g_qlnh[R_TOT*128], g_qlnl[R_TOT*128];
__device__ uint32_t g_qph [R_TOT*128], g_qpl [R_TOT*128];
__device__ __half   g_t   [R_TOT*1024];
__device__ float    g_dot [QLEN*HEADS*NKEY];
__device__ uint32_t g_apreh[QLEN*512], g_aprel[QLEN*512];
__device__ uint32_t g_avh [QLEN*128], g_avl [QLEN*128];
__device__ float    g_zp  [QLEN*DIMC];
__device__ float    g_zln [QLEN*DIMC];
__device__ uint32_t g_zlnh[QLEN*128], g_zlnl[QLEN*128];
__device__ uint32_t g_h1h [QLEN*256], g_h1l [QLEN*256];
__device__ float    g_hp  [QLEN*DIMC];
__device__ float    g_maskf[R_TOT];
__device__ uint32_t g_pwq_h[256*128],  g_pwq_l[256*128];
__device__ uint32_t g_pwk_h[4*256*32], g_pwk_l[4*256*32];
__device__ uint32_t g_pwv_h[4*64*128], g_pwv_l[4*64*128];
__device__ uint32_t g_pwp_h[256*128],  g_pwp_l[256*128];
__device__ uint32_t g_pw1_h[512*128],  g_pw1_l[512*128];
__device__ uint32_t g_pw2_h[256*256],  g_pw2_l[256*256];

// ---------------- helpers ----------------
__device__ __forceinline__ void blockReduce2(float& s1, float& s2, float* red)
{
    int lane = threadIdx.x & 31, w = threadIdx.x >> 5;
#pragma unroll
    for (int o = 16; o > 0; o >>= 1) {
        s1 += __shfl_xor_sync(0xffffffffu, s1, o);
        s2 += __shfl_xor_sync(0xffffffffu, s2, o);
    }
    if (lane == 0) { red[w] = s1; red[8 + w] = s2; }
    __syncthreads();
    float a = 0.f, b = 0.f;
#pragma unroll
    for (int j = 0; j < 8; j++) { a += red[j]; b += red[8 + j]; }
    s1 = a; s2 = b;
    __syncthreads();
}

__device__ __forceinline__ uint32_t pack_hi(float x0, float x1)
{
    __nv_bfloat162 h = __floats2bfloat162_rn(x0, x1);
    return *reinterpret_cast<uint32_t*>(&h);
}
__device__ __forceinline__ uint32_t pack_lo(float x0, float x1, uint32_t hi)
{
    __nv_bfloat162 h = *reinterpret_cast<__nv_bfloat162*>(&hi);
    float r0 = x0 - __bfloat162float(h.x);
    float r1 = x1 - __bfloat162float(h.y);
    __nv_bfloat162 l = __floats2bfloat162_rn(r0, r1);
    return *reinterpret_cast<uint32_t*>(&l);
}

__device__ __forceinline__ void mma16(float* c, const uint32_t* a, const uint32_t b0, const uint32_t b1)
{
    asm volatile(
        "mma.sync.aligned.m16n8k16.row.col.f32.bf16.bf16.f32 "
        "{%0,%1,%2,%3}, {%4,%5,%6,%7}, {%8,%9}, {%0,%1,%2,%3};"
        : "+f"(c[0]), "+f"(c[1]), "+f"(c[2]), "+f"(c[3])
        : "r"(a[0]), "r"(a[1]), "r"(a[2]), "r"(a[3]), "r"(b0), "r"(b1));
}

__device__ __forceinline__ void ldsm_x4(uint32_t* r, uint32_t saddr)
{
    asm volatile("ldmatrix.sync.aligned.m8n8.x4.shared.b16 {%0,%1,%2,%3}, [%4];"
                 : "=r"(r[0]), "=r"(r[1]), "=r"(r[2]), "=r"(r[3]) : "r"(saddr));
}

__device__ __forceinline__ uint32_t smem_u32(const void* p)
{
    uint32_t a;
    asm("{ .reg .u64 t; cvta.to.shared.u64 t, %1; cvt.u32.u64 %0, t; }" : "=r"(a) : "l"(p));
    return a;
}

__device__ __forceinline__ void cp16(uint32_t dst, const void* src, bool pred)
{
    int sz = pred ? 16 : 0;
    asm volatile("cp.async.cg.shared.global [%0], [%1], 16, %2;"
                 :: "r"(dst), "l"(src), "r"(sz) : "memory");
}

// ---------------- K0: mask detect + normalize ----------------
__global__ void k_mask(const unsigned char* __restrict__ m8)
{
    __shared__ int fA, fB;
    if (threadIdx.x == 0) { fA = 0; fB = 0; }
    __syncthreads();
    for (int i = threadIdx.x; i < NFR * QLEN; i += 256) {
        unsigned char b = m8[i];
        if (b == 1) {
            if ((i & 3) == 0) fA = 1;
            else              fB = 1;
        }
    }
    __syncthreads();
    int mode = fB ? 0 : (fA ? 1 : 2);
    for (int i = threadIdx.x; i < NFR * QLEN; i += 256) {
        float r;
        if (mode == 0)      r = (m8[i] != 0) ? 1.f : 0.f;
        else if (mode == 1) r = (((const int*)m8)[i] != 0) ? 1.f : 0.f;
        else                r = (((const float*)m8)[i] != 0.f) ? 1.f : 0.f;
        g_maskf[i] = r;
    }
}

// ---------------- K1: transpose q + LayerNorm -> packed pairs ----------------
__global__ __launch_bounds__(256)
void k_q_ln(const float* __restrict__ q, const float* __restrict__ g,
            const float* __restrict__ b)
{
    __shared__ float tile[256][33];
    __shared__ float s_mu[32], s_rs[32];
    __shared__ float s_part[2][8][32];
    int n  = blockIdx.y;
    int p0 = blockIdx.x * 32;
    int t  = threadIdx.x;
    int px = t & 31, cy = t >> 5;
    const float* qn = q + (size_t)n * DIMC * QLEN;
    float s1 = 0.f, s2 = 0.f;
    for (int c = cy; c < DIMC; c += 8) {
        float v = qn[(size_t)c * QLEN + p0 + px];
        tile[c][px] = v;
        s1 += v; s2 += v * v;
    }
    s_part[0][cy][px] = s1; s_part[1][cy][px] = s2;
    __syncthreads();
    if (cy == 0) {
        float a = 0.f, bb = 0.f;
#pragma unroll
        for (int j = 0; j < 8; j++) { a += s_part[0][j][px]; bb += s_part[1][j][px]; }
        float mu = a * (1.f / 256.f);
        float var = bb * (1.f / 256.f) - mu * mu;
        s_mu[px] = mu; s_rs[px] = rsqrtf(var + EPSLN);
    }
    __syncthreads();
    float gg = g[t], bv = b[t];
    size_t rbase = (size_t)n * QLEN + p0;
#pragma unroll 4
    for (int pp = 0; pp < 32; pp++) {
        float val = (tile[t][pp] - s_mu[pp]) * s_rs[pp] * gg + bv;
        float vo = __shfl_down_sync(0xffffffffu, val, 1);
        if (!(t & 1)) {
            uint32_t h = pack_hi(val, vo);
            size_t o = (rbase + pp) * 128 + (t >> 1);
            g_qlnh[o] = h;
            g_qlnl[o] = pack_lo(val, vo, h);
        }
    }
}

// ---------------- K2: pack ALL 6 weights (262144 elems = 1024 blocks) ----------------
__global__ __launch_bounds__(256)
void k_pack_all(const float* __restrict__ wq, const float* __restrict__ wk,
                const float* __restrict__ wv, const float* __restrict__ wp,
                const float* __restrict__ w1, const float* __restrict__ w2)
{
    long i = (long)blockIdx.x * 256 + threadIdx.x;
    if (i >= 262144) return;
    const float* src; int sn, sk; long zo; int N, Kp; uint32_t *dh, *dl; long rem;
    if (i < 32768)       { rem = i;          src = wq; sn = 1;   sk = 256; zo = 0;  N = 256; Kp = 128; dh = g_pwq_h; dl = g_pwq_l; }
    else if (i < 65536)  { rem = i - 32768;  src = wk; sn = 256; sk = 1;   zo = 64; N = 256; Kp = 32;  dh = g_pwk_h; dl = g_pwk_l; }
    else if (i < 98304)  { rem = i - 65536;  src = wv; sn = 1;   sk = 256; zo = 64; N = 64;  Kp = 128; dh = g_pwv_h; dl = g_pwv_l; }
    else if (i < 131072) { rem = i - 98304;  src = wp; sn = 1;   sk = 256; zo = 0;  N = 256; Kp = 128; dh = g_pwp_h; dl = g_pwp_l; }
    else if (i < 196608) { rem = i - 131072; src = w1; sn = 1;   sk = 512; zo = 0;  N = 512; Kp = 128; dh = g_pw1_h; dl = g_pw1_l; }
    else                 { rem = i - 196608; src = w2; sn = 1;   sk = 256; zo = 0;  N = 256; Kp = 256; dh = g_pw2_h; dl = g_pw2_l; }
    long NK = (long)N * Kp;
    long z = rem / NK, j = rem - z * NK;
    int n = (int)(j / Kp), kp = (int)(j - (long)n * Kp);
    const float* s = src + z * zo;
    float x0 = s[(size_t)n * sn + (size_t)(2 * kp) * sk];
    float x1 = s[(size_t)n * sn + (size_t)(2 * kp + 1) * sk];
    uint32_t h = pack_hi(x0, x1);
    dh[rem] = h;
    dl[rem] = pack_lo(x0, x1, h);
}

// ---------------- pipelined bf16x2 tensor GEMM, tile 128x64, 2 CTA/SM ----------------
// flags: 1 fp32, 2 gelu, 4 fp16, 8 packed, 16 = 2-pass (skip B_lo fills AND mma).
#define STG_A_H 0
#define STG_A_L 16384
#define STG_B_H 32768
#define STG_B_L 40960
#define STG_SZ  49152
#define GSM     (2*STG_SZ)

__global__ __launch_bounds__(256, 2)
void bgemm3(int M, int N, int K,
            const uint32_t* __restrict__ Ah, const uint32_t* __restrict__ Al,
            int ldap, long aoz,
            const uint32_t* __restrict__ Bh, const uint32_t* __restrict__ Bl, long bzs,
            const float* __restrict__ bias, int bioz,
            float* __restrict__ Cf, __half* __restrict__ Chalf, int ldc, long coz,
            uint32_t* __restrict__ Ph, uint32_t* __restrict__ Pl, int ldp, long poz,
            int flags)
{
    extern __shared__ char smem[];
    uint32_t sbase = smem_u32(smem);
    int z = blockIdx.z;
    Ah += (size_t)z * aoz; Al += (size_t)z * aoz;
    Bh += (size_t)z * bzs; Bl += (size_t)z * bzs;
    if (bias) bias += (size_t)z * bioz;
    int Kp = K >> 1;
    const bool pass3 = !(flags & 16);

    int tid = threadIdx.x, lane = tid & 31, wid = tid >> 5;
    int wm = wid & 3, wn = wid >> 2;
    int g = lane >> 2, t = lane & 3;
    int bm = blockIdx.y * 128, bn = blockIdx.x * 64;

    float acc[2][4][4] = {};

    int frow0 = tid >> 3, fseg = tid & 7;

    auto fill = [&](int ch, int st) {
        uint32_t stb = sbase + st * STG_SZ;
        int kp0 = ch << 5;
#pragma unroll
        for (int x = 0; x < 4; x++) {
            int row = x * 32 + frow0;
            uint32_t soff = (uint32_t)(row * 128 + ((fseg ^ (row & 7)) << 4));
            size_t ga = (size_t)(bm + row) * ldap + kp0 + fseg * 4;
            cp16(stb + STG_A_H + soff, Ah + ga, true);
            cp16(stb + STG_A_L + soff, Al + ga, true);
        }
#pragma unroll
        for (int x = 0; x < 2; x++) {
            int row = x * 32 + frow0;
            uint32_t soff = (uint32_t)(row * 128 + ((fseg ^ (row & 7)) << 4));
            bool bvld = (bn + row) < N;
            size_t gb = bvld ? ((size_t)(bn + row) * Kp + kp0 + fseg * 4) : 0;
            cp16(stb + STG_B_H + soff, Bh + gb, bvld);
            if (pass3) cp16(stb + STG_B_L + soff, Bl + gb, bvld);
        }
    };

    auto compute = [&](int st) {
        uint32_t stb = sbase + st * STG_SZ;
#pragma unroll
        for (int ks = 0; ks < 4; ks++) {
            int s0 = ks * 2;
            uint32_t ah[2][4], al[2][4];
#pragma unroll
            for (int i = 0; i < 2; i++) {
                int ml = wm * 32 + i * 16 + (lane & 15);
                int seg = s0 + (lane >> 4);
                uint32_t off = (uint32_t)(ml * 128 + ((seg ^ (ml & 7)) << 4));
                ldsm_x4(ah[i], stb + STG_A_H + off);
                ldsm_x4(al[i], stb + STG_A_L + off);
            }
#pragma unroll
            for (int j2 = 0; j2 < 2; j2++) {
                int nl = wn * 32 + j2 * 16 + (lane & 15);
                int seg = s0 + (lane >> 4);
                uint32_t off = (uint32_t)(nl * 128 + ((seg ^ (nl & 7)) << 4));
                uint32_t bh[4], bl[4];
                ldsm_x4(bh, stb + STG_B_H + off);
                if (pass3) ldsm_x4(bl, stb + STG_B_L + off);
#pragma unroll
                for (int jj = 0; jj < 2; jj++) {
                    int j = j2 * 2 + jj;
                    uint32_t bh0 = jj ? bh[1] : bh[0];
                    uint32_t bh1 = jj ? bh[3] : bh[2];
#pragma unroll
                    for (int i = 0; i < 2; i++) {
                        mma16(acc[i][j], ah[i], bh0, bh1);
                        mma16(acc[i][j], al[i], bh0, bh1);
                        if (pass3) {
                            uint32_t bl0 = jj ? bl[1] : bl[0];
                            uint32_t bl1 = jj ? bl[3] : bl[2];
                            mma16(acc[i][j], ah[i], bl0, bl1);
                        }
                    }
                }
            }
        }
    };

    int nch = K >> 6;
    fill(0, 0);
    asm volatile("cp.async.commit_group;" ::: "memory");
    for (int c = 0; c < nch; c++) {
        if (c + 1 < nch) {
            fill(c + 1, (c + 1) & 1);
            asm volatile("cp.async.commit_group;" ::: "memory");
            asm volatile("cp.async.wait_group 1;" ::: "memory");
        } else {
            asm volatile("cp.async.wait_group 0;" ::: "memory");
        }
        __syncthreads();
        compute(c & 1);
        __syncthreads();
    }

    // ---- epilogue ----
#pragma unroll
    for (int i = 0; i < 2; i++) {
        int r0 = bm + wm * 32 + i * 16 + g;
#pragma unroll
        for (int j = 0; j < 4; j++) {
            int c0 = bn + wn * 32 + j * 8 + t * 2;
            if (c0 >= N) continue;
            float b0v = bias ? bias[c0] : 0.f;
            float b1v = bias ? bias[c0 + 1] : 0.f;
            float v0 = acc[i][j][0] + b0v;
            float v1 = acc[i][j][1] + b1v;
            float v2 = acc[i][j][2] + b0v;
            float v3 = acc[i][j][3] + b1v;
            if (flags & 2) {
                v0 = 0.5f * v0 * (1.f + erff(v0 * 0.70710678118654752f));
                v1 = 0.5f * v1 * (1.f + erff(v1 * 0.70710678118654752f));
                v2 = 0.5f * v2 * (1.f + erff(v2 * 0.70710678118654752f));
                v3 = 0.5f * v3 * (1.f + erff(v3 * 0.70710678118654752f));
            }
            if (flags & 1) {
                float* C = Cf + (size_t)z * coz;
                *(float2*)&C[(size_t)r0 * ldc + c0]       = make_float2(v0, v1);
                *(float2*)&C[(size_t)(r0 + 8) * ldc + c0] = make_float2(v2, v3);
            }
            if (flags & 4) {
                __half* C = Chalf + (size_t)z * coz;
                *(__half2*)&C[(size_t)r0 * ldc + c0]       = __floats2half2_rn(v0, v1);
                *(__half2*)&C[(size_t)(r0 + 8) * ldc + c0] = __floats2half2_rn(v2, v3);
            }
            if (flags & 8) {
                uint32_t* PH = Ph + (size_t)z * poz;
                uint32_t* PL = Pl + (size_t)z * poz;
                int pidx = c0 >> 1;
                uint32_t h0 = pack_hi(v0, v1);
                PH[(size_t)r0 * ldp + pidx] = h0;
                PL[(size_t)r0 * ldp + pidx] = pack_lo(v0, v1, h0);
                uint32_t h1 = pack_hi(v2, v3);
                PH[(size_t)(r0 + 8) * ldp + pidx] = h1;
                PL[(size_t)(r0 + 8) * ldp + pidx] = pack_lo(v2, v3, h1);
            }
        }
    }
}

// ---------------- specialized qp GEMM: B resident (hi only), 2 M-blocks/CTA ----------------
// qp = qln @ wq + bq, 2-pass bf16x2, packed out. grid (4, 96).
#define Q_AH  0
#define Q_AL  16384
#define Q_STG 32768
#define Q_B   65536
#define QGSM  (65536 + 32768)

__global__ __launch_bounds__(256, 2)
void qgemm(const uint32_t* __restrict__ Ah, const uint32_t* __restrict__ Al,
           const uint32_t* __restrict__ Bh, const float* __restrict__ bias,
           uint32_t* __restrict__ Ph, uint32_t* __restrict__ Pl)
{
    extern __shared__ char smem[];
    uint32_t sbase = smem_u32(smem);
    int tid = threadIdx.x, lane = tid & 31, wid = tid >> 5;
    int wm = wid & 3, wn = wid >> 2;
    int g = lane >> 2, t = lane & 3;
    int bn = blockIdx.x * 64;
    int bm0 = blockIdx.y * 256;

    // B fill once: 64 rows x 128 pairs, stored as 4 chunks of [64 rows][128 B]
#pragma unroll
    for (int i = 0; i < 8; i++) {
        int u = i * 256 + tid;          // 0..2047
        int kc = u >> 9;
        int rem = u & 511;
        int row = rem >> 3, seg = rem & 7;
        uint32_t soff = (uint32_t)(kc * 8192 + row * 128 + ((seg ^ (row & 7)) << 4));
        cp16(sbase + Q_B + soff, Bh + (size_t)(bn + row) * 128 + kc * 32 + seg * 4, true);
    }
    int frow0 = tid >> 3, fseg = tid & 7;
    auto fillA = [&](int s, int st) {
        uint32_t stb = sbase + st * Q_STG;
        int bm = bm0 + (s >> 2) * 128;
        int kp0 = (s & 3) << 5;
#pragma unroll
        for (int x = 0; x < 4; x++) {
            int row = x * 32 + frow0;
            uint32_t soff = (uint32_t)(row * 128 + ((fseg ^ (row & 7)) << 4));
            size_t ga = (size_t)(bm + row) * 128 + kp0 + fseg * 4;
            cp16(stb + Q_AH + soff, Ah + ga, true);
            cp16(stb + Q_AL + soff, Al + ga, true);
        }
    };

    float acc[2][4][4] = {};
    fillA(0, 0);
    asm volatile("cp.async.commit_group;" ::: "memory");
    for (int s = 0; s < 8; s++) {
        if (s < 7) {
            fillA(s + 1, (s + 1) & 1);
            asm volatile("cp.async.commit_group;" ::: "memory");
            asm volatile("cp.async.wait_group 1;" ::: "memory");
        } else {
            asm volatile("cp.async.wait_group 0;" ::: "memory");
        }
        __syncthreads();
        uint32_t stb = sbase + (s & 1) * Q_STG;
        uint32_t bbase = sbase + Q_B + (uint32_t)((s & 3) * 8192);
#pragma unroll
        for (int ks = 0; ks < 4; ks++) {
            int s0 = ks * 2;
            uint32_t ah[2][4], al[2][4];
#pragma unroll
            for (int i = 0; i < 2; i++) {
                int ml = wm * 32 + i * 16 + (lane & 15);
                int seg = s0 + (lane >> 4);
                uint32_t off = (uint32_t)(ml * 128 + ((seg ^ (ml & 7)) << 4));
                ldsm_x4(ah[i], stb + Q_AH + off);
                ldsm_x4(al[i], stb + Q_AL + off);
            }
#pragma unroll
            for (int j2 = 0; j2 < 2; j2++) {
                int nl = wn * 32 + j2 * 16 + (lane & 15);
                int seg = s0 + (lane >> 4);
                uint32_t off = (uint32_t)(nl * 128 + ((seg ^ (nl & 7)) << 4));
                uint32_t bh[4];
                ldsm_x4(bh, bbase + off);
#pragma unroll
                for (int jj = 0; jj < 2; jj++) {
                    int j = j2 * 2 + jj;
                    uint32_t bh0 = jj ? bh[1] : bh[0];
                    uint32_t bh1 = jj ? bh[3] : bh[2];
#pragma unroll
                    for (int i = 0; i < 2; i++) {
                        mma16(acc[i][j], ah[i], bh0, bh1);
                        mma16(acc[i][j], al[i], bh0, bh1);
                    }
                }
            }
        }
        __syncthreads();
        if ((s & 3) == 3) {
            int bm = bm0 + (s >> 2) * 128;
#pragma unroll
            for (int i = 0; i < 2; i++) {
                int r0 = bm + wm * 32 + i * 16 + g;
#pragma unroll
                for (int j = 0; j < 4; j++) {
                    int c0 = bn + wn * 32 + j * 8 + t * 2;
                    float v0 = acc[i][j][0] + bias[c0];
                    float v1 = acc[i][j][1] + bias[c0 + 1];
                    float v2 = acc[i][j][2] + bias[c0];
                    float v3 = acc[i][j][3] + bias[c0 + 1];
                    int pidx = c0 >> 1;
                    uint32_t h0 = pack_hi(v0, v1);
                    Ph[(size_t)r0 * 128 + pidx] = h0;
                    Pl[(size_t)r0 * 128 + pidx] = pack_lo(v0, v1, h0);
                    uint32_t h1 = pack_hi(v2, v3);
                    Ph[(size_t)(r0 + 8) * 128 + pidx] = h1;
                    Pl[(size_t)(r0 + 8) * 128 + pidx] = pack_lo(v2, v3, h1);
                    acc[i][j][0] = acc[i][j][1] = acc[i][j][2] = acc[i][j][3] = 0.f;
                }
            }
        }
    }
}

// ---------------- specialized t-GEMM: K=64, B reused across 4 M-blocks, pipelined ----------------
#define T_AH  0
#define T_AL  16384
#define T_STG 32768
#define T_B   65536
#define TGSM  (65536 + 8192)

__global__ __launch_bounds__(256, 2)
void tgemm_t(const uint32_t* __restrict__ Ah, const uint32_t* __restrict__ Al,
             const uint32_t* __restrict__ Bh, __half* __restrict__ C)
{
    extern __shared__ char smem[];
    uint32_t sbase = smem_u32(smem);
    int z = blockIdx.z;
    Ah += (size_t)z * 32; Al += (size_t)z * 32;
    Bh += (size_t)z * (256 * 32);
    C  += (size_t)z * 256;

    int tid = threadIdx.x, lane = tid & 31, wid = tid >> 5;
    int wm = wid & 3, wn = wid >> 2;
    int g = lane >> 2, t = lane & 3;
    int bn = blockIdx.x * 64;
    int bm0 = blockIdx.y * 512;

#pragma unroll
    for (int i = 0; i < 2; i++) {
        int u = i * 256 + tid;
        int row = u >> 3, seg = u & 7;
        uint32_t soff = (uint32_t)(row * 128 + ((seg ^ (row & 7)) << 4));
        cp16(sbase + T_B + soff, Bh + (size_t)(bn + row) * 32 + seg * 4, true);
    }
    auto fillA = [&](int rb, int st) {
        uint32_t stb = sbase + st * T_STG;
        int bm = bm0 + rb * 128;
#pragma unroll
        for (int i = 0; i < 4; i++) {
            int u = i * 256 + tid;
            int row = u >> 3, seg = u & 7;
            uint32_t soff = (uint32_t)(row * 128 + ((seg ^ (row & 7)) << 4));
            size_t ga = (size_t)(bm + row) * 128 + seg * 4;
            cp16(stb + T_AH + soff, Ah + ga, true);
            cp16(stb + T_AL + soff, Al + ga, true);
        }
    };

    float acc[2][4][4] = {};
    fillA(0, 0);
    asm volatile("cp.async.commit_group;" ::: "memory");
    for (int rb = 0; rb < 4; rb++) {
        if (rb < 3) {
            fillA(rb + 1, (rb + 1) & 1);
            asm volatile("cp.async.commit_group;" ::: "memory");
            asm volatile("cp.async.wait_group 1;" ::: "memory");
        } else {
            asm volatile("cp.async.wait_group 0;" ::: "memory");
        }
        __syncthreads();
        uint32_t stb = sbase + (rb & 1) * T_STG;
#pragma unroll
        for (int ks = 0; ks < 4; ks++) {
            int s0 = ks * 2;
            uint32_t ah[2][4], al[2][4];
#pragma unroll
            for (int i = 0; i < 2; i++) {
                int ml = wm * 32 + i * 16 + (lane & 15);
                int seg = s0 + (lane >> 4);
                uint32_t off = (uint32_t)(ml * 128 + ((seg ^ (ml & 7)) << 4));
                ldsm_x4(ah[i], stb + T_AH + off);
                ldsm_x4(al[i], stb + T_AL + off);
            }
#pragma unroll
            for (int j2 = 0; j2 < 2; j2++) {
                int nl = wn * 32 + j2 * 16 + (lane & 15);
                int seg = s0 + (lane >> 4);
                uint32_t off = (uint32_t)(nl * 128 + ((seg ^ (nl & 7)) << 4));
                uint32_t bh[4];
                ldsm_x4(bh, sbase + T_B + off);
#pragma unroll
                for (int jj = 0; jj < 2; jj++) {
                    int j = j2 * 2 + jj;
                    uint32_t bh0 = jj ? bh[1] : bh[0];
                    uint32_t bh1 = jj ? bh[3] : bh[2];
#pragma unroll
                    for (int i = 0; i < 2; i++) {
                        mma16(acc[i][j], ah[i], bh0, bh1);
                        mma16(acc[i][j], al[i], bh0, bh1);
                    }
                }
            }
        }
        int bm = bm0 + rb * 128;
#pragma unroll
        for (int i = 0; i < 2; i++) {
            int r0 = bm + wm * 32 + i * 16 + g;
#pragma unroll
            for (int j = 0; j < 4; j++) {
                int c0 = bn + wn * 32 + j * 8 + t * 2;
                *(__half2*)&C[(size_t)r0 * 1024 + c0]       = __floats2half2_rn(acc[i][j][0], acc[i][j][1]);
                *(__half2*)&C[(size_t)(r0 + 8) * 1024 + c0] = __floats2half2_rn(acc[i][j][2], acc[i][j][3]);
                acc[i][j][0] = acc[i][j][1] = acc[i][j][2] = acc[i][j][3] = 0.f;
            }
        }
        __syncthreads();
    }
}

// ---------------- K4: attention scores (smem-staged t) ----------------
__global__ __launch_bounds__(256)
void k_dot(const float* __restrict__ kten,
           const uint32_t* __restrict__ qph, const uint32_t* __restrict__ qpl,
           const __half* __restrict__ tg, const float* __restrict__ bk,
           const float* __restrict__ lng, const float* __restrict__ lnb,
           const float* __restrict__ maskf, float* __restrict__ dotp)
{
    int r = blockIdx.x;
    int n = r >> 12, q = r & 4095;
    int tid = threadIdx.x, lane = tid & 31, w = tid >> 5;
    __shared__ float ts[1024];
    __shared__ float bd[4];
    __shared__ float sg[256], sb[256];
    const __half* trow = tg + (size_t)r * 1024;
    {
        uint2 tu = *(const uint2*)(trow + tid * 4);
        __half2 h0 = *reinterpret_cast<__half2*>(&tu.x);
        __half2 h1 = *reinterpret_cast<__half2*>(&tu.y);
        float2 f0 = __half22float2(h0);
        float2 f1 = __half22float2(h1);
        ts[tid * 4 + 0] = f0.x;
        ts[tid * 4 + 1] = f0.y;
        ts[tid * 4 + 2] = f1.x;
        ts[tid * 4 + 3] = f1.y;
    }
    sg[tid] = lng[tid]; sb[tid] = lnb[tid];
    if (w < 4) {
        uint32_t hh = qph[(size_t)r * 128 + w * 32 + lane];
        uint32_t ll = qpl[(size_t)r * 128 + w * 32 + lane];
        __nv_bfloat162 h2 = *reinterpret_cast<__nv_bfloat162*>(&hh);
        __nv_bfloat162 l2 = *reinterpret_cast<__nv_bfloat162*>(&ll);
        float a0 = __bfloat162float(h2.x) + __bfloat162float(l2.x);
        float a1 = __bfloat162float(h2.y) + __bfloat162float(l2.y);
        const float* bkr = bk + w * 64;
        float p = a0 * bkr[2 * lane] + a1 * bkr[2 * lane + 1];
#pragma unroll
        for (int o = 16; o > 0; o >>= 1) p += __shfl_xor_sync(0xffffffffu, p, o);
        if (lane == 0) bd[w] = p;
    }
    __syncthreads();
    const float* krow = kten + ((size_t)r * GRP + w) * 256;
    float v[8];
    float s1 = 0.f, s2 = 0.f;
#pragma unroll
    for (int j = 0; j < 8; j++) {
        v[j] = krow[lane + 32 * j];
        s1 += v[j]; s2 += v[j] * v[j];
    }
#pragma unroll
    for (int o = 16; o > 0; o >>= 1) {
        s1 += __shfl_xor_sync(0xffffffffu, s1, o);
        s2 += __shfl_xor_sync(0xffffffffu, s2, o);
    }
    float mu = s1 * (1.f / 256.f);
    float rs = rsqrtf(s2 * (1.f / 256.f) - mu * mu + EPSLN);
    float d0 = 0.f, d1 = 0.f, d2 = 0.f, d3 = 0.f;
#pragma unroll
    for (int j = 0; j < 8; j++) {
        int c = lane + 32 * j;
        float lv = (v[j] - mu) * rs * sg[c] + sb[c];
        d0 += lv * ts[c];
        d1 += lv * ts[256 + c];
        d2 += lv * ts[512 + c];
        d3 += lv * ts[768 + c];
    }
#pragma unroll
    for (int o = 16; o > 0; o >>= 1) {
        d0 += __shfl_xor_sync(0xffffffffu, d0, o);
        d1 += __shfl_xor_sync(0xffffffffu, d1, o);
        d2 += __shfl_xor_sync(0xffffffffu, d2, o);
        d3 += __shfl_xor_sync(0xffffffffu, d3, o);
    }
    if (lane == 0) {
        bool mk = maskf[r] != 0.f;
        float dm[4] = {d0, d1, d2, d3};
        size_t base = (size_t)q * (HEADS * NKEY) + (size_t)n * GRP + w;
#pragma unroll
        for (int m = 0; m < 4; m++)
            dotp[base + (size_t)m * NKEY] = mk ? SCALE * (dm[m] + bd[m]) : -1e9f;
    }
}

// ---------------- K6: softmax (fused) + weighted sum of LN(v) -> packed ----------------
__global__ __launch_bounds__(256)
void k_vacc(const float* __restrict__ vten, const float* __restrict__ dotp,
            const float* __restrict__ lng, const float* __restrict__ lnb)
{
    __shared__ float sa[HEADS * NKEY];
    __shared__ float part[8][1024];
    int q = blockIdx.x, tid = threadIdx.x, lane = tid & 31, w = tid >> 5;
    if (w < 4) {
        const float* p = dotp + (size_t)q * (HEADS * NKEY) + w * NKEY;
        float v0 = p[lane];
        float v1 = (lane < 16) ? p[32 + lane] : -3.4e38f;
        float mx = fmaxf(v0, v1);
#pragma unroll
        for (int o = 16; o > 0; o >>= 1) mx = fmaxf(mx, __shfl_xor_sync(0xffffffffu, mx, o));
        float e0 = expf(v0 - mx);
        float e1 = (lane < 16) ? expf(v1 - mx) : 0.f;
        float s = e0 + e1;
#pragma unroll
        for (int o = 16; o > 0; o >>= 1) s += __shfl_xor_sync(0xffffffffu, s, o);
        float inv = 1.f / s;
        sa[w * NKEY + lane] = e0 * inv;
        if (lane < 16) sa[w * NKEY + 32 + lane] = e1 * inv;
    }
    int c0 = lane * 8;
    float gv[8], bb[8];
    {
        float4 gA = *(const float4*)(lng + c0);
        float4 gB = *(const float4*)(lng + c0 + 4);
        float4 bA = *(const float4*)(lnb + c0);
        float4 bB = *(const float4*)(lnb + c0 + 4);
        gv[0]=gA.x; gv[1]=gA.y; gv[2]=gA.z; gv[3]=gA.w;
        gv[4]=gB.x; gv[5]=gB.y; gv[6]=gB.z; gv[7]=gB.w;
        bb[0]=bA.x; bb[1]=bA.y; bb[2]=bA.z; bb[3]=bA.w;
        bb[4]=bB.x; bb[5]=bB.y; bb[6]=bB.z; bb[7]=bB.w;
    }
    __syncthreads();
    float acc[4][8] = {};
    for (int n = 0; n < NFR; n++) {
        const float* vr = vten + (((size_t)n * QLEN + q) * GRP + w) * 256 + c0;
        float4 v0 = *(const float4*)vr;
        float4 v1 = *(const float4*)(vr + 4);
        float vv[8] = {v0.x, v0.y, v0.z, v0.w, v1.x, v1.y, v1.z, v1.w};
        float s1 = 0.f, s2 = 0.f;
#pragma unroll
        for (int j = 0; j < 8; j++) { s1 += vv[j]; s2 += vv[j] * vv[j]; }
#pragma unroll
        for (int o = 16; o > 0; o >>= 1) {
            s1 += __shfl_xor_sync(0xffffffffu, s1, o);
            s2 += __shfl_xor_sync(0xffffffffu, s2, o);
        }
        float mu = s1 * (1.f / 256.f);
        float rs = rsqrtf(s2 * (1.f / 256.f) - mu * mu + EPSLN);
        float aw0 = sa[0 * NKEY + n * 8 + w];
        float aw1 = sa[1 * NKEY + n * 8 + w];
        float aw2 = sa[2 * NKEY + n * 8 + w];
        float aw3 = sa[3 * NKEY + n * 8 + w];
#pragma unroll
        for (int j = 0; j < 8; j++) {
            float lv = (vv[j] - mu) * rs * gv[j] + bb[j];
            acc[0][j] += aw0 * lv;
            acc[1][j] += aw1 * lv;
            acc[2][j] += aw2 * lv;
            acc[3][j] += aw3 * lv;
        }
    }
#pragma unroll
    for (int m = 0; m < 4; m++) {
        float4 p0 = make_float4(acc[m][0], acc[m][1], acc[m][2], acc[m][3]);
        float4 p1 = make_float4(acc[m][4], acc[m][5], acc[m][6], acc[m][7]);
        *(float4*)&part[w][m * 256 + c0]     = p0;
        *(float4*)&part[w][m * 256 + c0 + 4] = p1;
    }
    __syncthreads();
#pragma unroll
    for (int m = 0; m < 4; m++) {
        float s = 0.f;
#pragma unroll
        for (int w8 = 0; w8 < 8; w8++) s += part[w8][m * 256 + tid];
        float so = __shfl_down_sync(0xffffffffu, s, 1);
        if (!(tid & 1)) {
            uint32_t h = pack_hi(s, so);
            size_t o = (size_t)q * 512 + m * 128 + (tid >> 1);
            g_apreh[o] = h;
            g_aprel[o] = pack_lo(s, so, h);
        }
    }
}

// ---------------- K7: z = LN_pre(zp + skip^T) -> fp32 + packed ----------------
__global__ __launch_bounds__(256)
void k_ln_skip(const float* __restrict__ zp, const float* __restrict__ skip,
               const float* __restrict__ g, const float* __restrict__ b,
               float* __restrict__ zln)
{
    __shared__ float red[16];
    int q = blockIdx.x, c = threadIdx.x;
    float v = zp[(size_t)q * 256 + c] + skip[(size_t)c * QLEN + q];
    float s1 = v, s2 = v * v;
    blockReduce2(s1, s2, red);
    float mu = s1 * (1.f / 256.f);
    float rs = rsqrtf(s2 * (1.f / 256.f) - mu * mu + EPSLN);
    float val = (v - mu) * rs * g[c] + b[c];
    zln[(size_t)q * 256 + c] = val;
    float vo = __shfl_down_sync(0xffffffffu, val, 1);
    if (!(c & 1)) {
        uint32_t h = pack_hi(val, vo);
        size_t o = (size_t)q * 128 + (c >> 1);
        g_zlnh[o] = h;
        g_zlnl[o] = pack_lo(val, vo, h);
    }
}

// ---------------- K8: out = LN_post(zln + hp), transposed store ----------------
__global__ __launch_bounds__(256)
void k_ln_out(const float* __restrict__ zln, const float* __restrict__ hp,
              const float* __restrict__ g, const float* __restrict__ b,
              float* __restrict__ out)
{
    __shared__ float red[16];
    int q = blockIdx.x, c = threadIdx.x;
    float v = zln[(size_t)q * 256 + c] + hp[(size_t)q * 256 + c];
    float s1 = v, s2 = v * v;
    blockReduce2(s1, s2, red);
    float mu = s1 * (1.f / 256.f);
    float rs = rsqrtf(s2 * (1.f / 256.f) - mu * mu + EPSLN);
    out[(size_t)c * QLEN + q] = (v - mu) * rs * g[c] + b[c];
}

// ---------------- host launch ----------------
extern "C" void kernel_launch(void* const* d_in, const int* in_sizes, int n_in,
                              void* d_out, int out_size)
{
    const float* q        = (const float*)d_in[0];
    const float* k        = (const float*)d_in[1];
    const float* v        = (const float*)d_in[2];
    const float* skip     = (const float*)d_in[3];
    const void*  mask     = d_in[4];
    const float* ln_q_g   = (const float*)d_in[5];
    const float* ln_q_b   = (const float*)d_in[6];
    const float* wq       = (const float*)d_in[7];
    const float* bq       = (const float*)d_in[8];
    const float* ln_k_g   = (const float*)d_in[9];
    const float* ln_k_b   = (const float*)d_in[10];
    const float* wk       = (const float*)d_in[11];
    const float* bk       = (const float*)d_in[12];
    const float* ln_v_g   = (const float*)d_in[13];
    const float* ln_v_b   = (const float*)d_in[14];
    const float* wv       = (const float*)d_in[15];
    const float* bv       = (const float*)d_in[16];
    const float* w_proj   = (const float*)d_in[17];
    const float* b_proj   = (const float*)d_in[18];
    const float* ln_pre_g = (const float*)d_in[19];
    const float* ln_pre_b = (const float*)d_in[20];
    const float* w_mlp1   = (const float*)d_in[21];
    const float* b_mlp1   = (const float*)d_in[22];
    const float* w_mlp2   = (const float*)d_in[23];
    const float* b_mlp2   = (const float*)d_in[24];
    const float* ln_post_g= (const float*)d_in[25];
    const float* ln_post_b= (const float*)d_in[26];
    float* out = (float*)d_out;

    float *dot, *zp, *zln, *hp, *maskf;
    __half* t;
    uint32_t *qlnh, *qlnl, *qph, *qpl, *apreh, *aprel, *avh, *avl, *zlnh, *zlnl, *h1h, *h1l;
    uint32_t *pwq_h, *pwq_l, *pwk_h, *pwk_l, *pwv_h, *pwv_l;
    uint32_t *pwp_h, *pwp_l, *pw1_h, *pw1_l, *pw2_h, *pw2_l;
    cudaGetSymbolAddress((void**)&qlnh, g_qlnh); cudaGetSymbolAddress((void**)&qlnl, g_qlnl);
    cudaGetSymbolAddress((void**)&qph,  g_qph);  cudaGetSymbolAddress((void**)&qpl,  g_qpl);
    cudaGetSymbolAddress((void**)&t,    g_t);
    cudaGetSymbolAddress((void**)&dot,  g_dot);
    cudaGetSymbolAddress((void**)&apreh,g_apreh);cudaGetSymbolAddress((void**)&aprel,g_aprel);
    cudaGetSymbolAddress((void**)&avh,  g_avh);  cudaGetSymbolAddress((void**)&avl,  g_avl);
    cudaGetSymbolAddress((void**)&zp,   g_zp);
    cudaGetSymbolAddress((void**)&zln,  g_zln);
    cudaGetSymbolAddress((void**)&zlnh, g_zlnh); cudaGetSymbolAddress((void**)&zlnl, g_zlnl);
    cudaGetSymbolAddress((void**)&h1h,  g_h1h);  cudaGetSymbolAddress((void**)&h1l,  g_h1l);
    cudaGetSymbolAddress((void**)&hp,   g_hp);
    cudaGetSymbolAddress((void**)&maskf,g_maskf);
    cudaGetSymbolAddress((void**)&pwq_h, g_pwq_h); cudaGetSymbolAddress((void**)&pwq_l, g_pwq_l);
    cudaGetSymbolAddress((void**)&pwk_h, g_pwk_h); cudaGetSymbolAddress((void**)&pwk_l, g_pwk_l);
    cudaGetSymbolAddress((void**)&pwv_h, g_pwv_h); cudaGetSymbolAddress((void**)&pwv_l, g_pwv_l);
    cudaGetSymbolAddress((void**)&pwp_h, g_pwp_h); cudaGetSymbolAddress((void**)&pwp_l, g_pwp_l);
    cudaGetSymbolAddress((void**)&pw1_h, g_pw1_h); cudaGetSymbolAddress((void**)&pw1_l, g_pw1_l);
    cudaGetSymbolAddress((void**)&pw2_h, g_pw2_h); cudaGetSymbolAddress((void**)&pw2_l, g_pw2_l);

    cudaFuncSetAttribute(bgemm3, cudaFuncAttributeMaxDynamicSharedMemorySize, GSM);
    cudaFuncSetAttribute(tgemm_t, cudaFuncAttributeMaxDynamicSharedMemorySize, TGSM);
    cudaFuncSetAttribute(qgemm,  cudaFuncAttributeMaxDynamicSharedMemorySize, QGSM);

    // 1
    k_mask<<<1, 256>>>((const unsigned char*)mask);
    // 2: q transpose + LN -> packed
    k_q_ln<<<dim3(QLEN / 32, NFR), 256>>>(q, ln_q_g, ln_q_b);
    // 3: pack weights
    k_pack_all<<<1024, 256>>>(wq, wk, wv, w_proj, w_mlp1, w_mlp2);
    // 4: qp = qln @ wq + bq (specialized: B resident, 2 M-blocks/CTA)
    qgemm<<<dim3(4, 96), 256, QGSM>>>(qlnh, qlnl, pwq_h, bq, qph, qpl);
    // 5: t_m = qp_m @ wk_m^T (K=64) x4 heads -> fp16 (specialized)
    tgemm_t<<<dim3(4, 48, 4), 256, TGSM>>>(qph, qpl, pwk_h, t);
    // 6: attention scores
    k_dot<<<R_TOT, 256>>>(k, qph, qpl, t, bk, ln_k_g, ln_k_b, maskf, dot);
    // 7: softmax + weighted LN(v) sums -> packed apre
    k_vacc<<<QLEN, 256>>>(v, dot, ln_v_g, ln_v_b);
    // 8: a_m = apre_m @ wv_m + bv_m (N=64, K=256) x4 heads -> packed av
    bgemm3<<<dim3(1, 32, 4), 256, GSM>>>(QLEN, 64, 256,
                                         apreh, aprel, 512, 128,
                                         pwv_h, pwv_l, 64 * 128, bv, 64,
                                         nullptr, nullptr, 0, 0,
                                         avh, avl, 128, 32, 8);
    // 9: zp = av @ w_proj + b_proj -> fp32
    bgemm3<<<dim3(4, 32, 1), 256, GSM>>>(QLEN, 256, 256,
                                         avh, avl, 128, 0,
                                         pwp_h, pwp_l, 0, b_proj, 0,
                                         zp, nullptr, 256, 0,
                                         nullptr, nullptr, 0, 0, 1);
    // 10: zln = LN_pre(zp + skip) -> fp32 + packed
    k_ln_skip<<<QLEN, 256>>>(zp, skip, ln_pre_g, ln_pre_b, zln);
    // 11: h1 = gelu(zln @ w_mlp1 + b_mlp1) -> packed
    bgemm3<<<dim3(8, 32, 1), 256, GSM>>>(QLEN, 512, 256,
                                         zlnh, zlnl, 128, 0,
                                         pw1_h, pw1_l, 0, b_mlp1, 0,
                                         nullptr, nullptr, 0, 0,
                                         h1h, h1l, 256, 0, 10);
    // 12: hp = h1 @ w_mlp2 + b_mlp2 -> fp32
    bgemm3<<<dim3(4, 32, 1), 256, GSM>>>(QLEN, 256, 512,
                                         h1h, h1l, 256, 0,
                                         pw2_h, pw2_l, 0, b_mlp2, 0,
                                         hp, nullptr, 256, 0,
                                         nullptr, nullptr, 0, 0, 1);
    // 13
    k_ln_out<<<QLEN, 256>>>(zln, hp, ln_post_g, ln_post_b, out);
}

// round 17
// speedup vs baseline: 1.3126x; 1.0480x over previous
#include <cuda_runtime.h>
#include <cuda_bf16.h>
#include <cuda_fp16.h>
#include <math.h>
#include <stdint.h>

// ---------------- problem constants ----------------
#define QLEN   4096
#define NFR    6
#define GRP    8
#define DIMC   256
#define HEADS  4
#define NKEY   48
#define R_TOT  (NFR*QLEN)
#define EPSLN  1e-5f
#define SCALE  0.125f

// ---------------- scratch ----------------
__device__ uint32_t g_qlnh[R_TOT*128], g_qlnl[R_TOT*128];
__device__ uint32_t g_qph [R_TOT*128], g_qpl [R_TOT*128];
__device__ __half   g_t   [R_TOT*1024];
__device__ float    g_dot [QLEN*HEADS*NKEY];
__device__ uint32_t g_apreh[QLEN*512], g_aprel[QLEN*512];
__device__ uint32_t g_avh [QLEN*128], g_avl [QLEN*128];
__device__ float    g_zp  [QLEN*DIMC];
__device__ float    g_zln [QLEN*DIMC];
__device__ uint32_t g_zlnh[QLEN*128], g_zlnl[QLEN*128];
__device__ uint32_t g_h1h [QLEN*256], g_h1l [QLEN*256];
__device__ float    g_hp  [QLEN*DIMC];
__device__ float    g_maskf[R_TOT];
__device__ uint32_t g_pwq_h[256*128],  g_pwq_l[256*128];
__device__ uint32_t g_pwk_h[4*256*32], g_pwk_l[4*256*32];
__device__ uint32_t g_pwv_h[4*64*128], g_pwv_l[4*64*128];
__device__ uint32_t g_pwp_h[256*128],  g_pwp_l[256*128];
__device__ uint32_t g_pw1_h[512*128],  g_pw1_l[512*128];
__device__ uint32_t g_pw2_h[256*256],  g_pw2_l[256*256];

// ---------------- helpers ----------------
__device__ __forceinline__ void blockReduce2(float& s1, float& s2, float* red)
{
    int lane = threadIdx.x & 31, w = threadIdx.x >> 5;
#pragma unroll
    for (int o = 16; o > 0; o >>= 1) {
        s1 += __shfl_xor_sync(0xffffffffu, s1, o);
        s2 += __shfl_xor_sync(0xffffffffu, s2, o);
    }
    if (lane == 0) { red[w] = s1; red[8 + w] = s2; }
    __syncthreads();
    float a = 0.f, b = 0.f;
#pragma unroll
    for (int j = 0; j < 8; j++) { a += red[j]; b += red[8 + j]; }
    s1 = a; s2 = b;
    __syncthreads();
}

__device__ __forceinline__ uint32_t pack_hi(float x0, float x1)
{
    __nv_bfloat162 h = __floats2bfloat162_rn(x0, x1);
    return *reinterpret_cast<uint32_t*>(&h);
}
__device__ __forceinline__ uint32_t pack_lo(float x0, float x1, uint32_t hi)
{
    __nv_bfloat162 h = *reinterpret_cast<__nv_bfloat162*>(&hi);
    float r0 = x0 - __bfloat162float(h.x);
    float r1 = x1 - __bfloat162float(h.y);
    __nv_bfloat162 l = __floats2bfloat162_rn(r0, r1);
    return *reinterpret_cast<uint32_t*>(&l);
}

__device__ __forceinline__ void mma16(float* c, const uint32_t* a, const uint32_t b0, const uint32_t b1)
{
    asm volatile(
        "mma.sync.aligned.m16n8k16.row.col.f32.bf16.bf16.f32 "
        "{%0,%1,%2,%3}, {%4,%5,%6,%7}, {%8,%9}, {%0,%1,%2,%3};"
        : "+f"(c[0]), "+f"(c[1]), "+f"(c[2]), "+f"(c[3])
        : "r"(a[0]), "r"(a[1]), "r"(a[2]), "r"(a[3]), "r"(b0), "r"(b1));
}

__device__ __forceinline__ void ldsm_x4(uint32_t* r, uint32_t saddr)
{
    asm volatile("ldmatrix.sync.aligned.m8n8.x4.shared.b16 {%0,%1,%2,%3}, [%4];"
                 : "=r"(r[0]), "=r"(r[1]), "=r"(r[2]), "=r"(r[3]) : "r"(saddr));
}

__device__ __forceinline__ uint32_t smem_u32(const void* p)
{
    uint32_t a;
    asm("{ .reg .u64 t; cvta.to.shared.u64 t, %1; cvt.u32.u64 %0, t; }" : "=r"(a) : "l"(p));
    return a;
}

__device__ __forceinline__ void cp16(uint32_t dst, const void* src, bool pred)
{
    int sz = pred ? 16 : 0;
    asm volatile("cp.async.cg.shared.global [%0], [%1], 16, %2;"
                 :: "r"(dst), "l"(src), "r"(sz) : "memory");
}

// ---------------- K0: mask detect + normalize ----------------
__global__ void k_mask(const unsigned char* __restrict__ m8)
{
    __shared__ int fA, fB;
    if (threadIdx.x == 0) { fA = 0; fB = 0; }
    __syncthreads();
    for (int i = threadIdx.x; i < NFR * QLEN; i += 256) {
        unsigned char b = m8[i];
        if (b == 1) {
            if ((i & 3) == 0) fA = 1;
            else              fB = 1;
        }
    }
    __syncthreads();
    int mode = fB ? 0 : (fA ? 1 : 2);
    for (int i = threadIdx.x; i < NFR * QLEN; i += 256) {
        float r;
        if (mode == 0)      r = (m8[i] != 0) ? 1.f : 0.f;
        else if (mode == 1) r = (((const int*)m8)[i] != 0) ? 1.f : 0.f;
        else                r = (((const float*)m8)[i] != 0.f) ? 1.f : 0.f;
        g_maskf[i] = r;
    }
}

// ---------------- K1: transpose q + LayerNorm -> packed pairs ----------------
__global__ __launch_bounds__(256)
void k_q_ln(const float* __restrict__ q, const float* __restrict__ g,
            const float* __restrict__ b)
{
    __shared__ float tile[256][33];
    __shared__ float s_mu[32], s_rs[32];
    __shared__ float s_part[2][8][32];
    int n  = blockIdx.y;
    int p0 = blockIdx.x * 32;
    int t  = threadIdx.x;
    int px = t & 31, cy = t >> 5;
    const float* qn = q + (size_t)n * DIMC * QLEN;
    float s1 = 0.f, s2 = 0.f;
    for (int c = cy; c < DIMC; c += 8) {
        float v = qn[(size_t)c * QLEN + p0 + px];
        tile[c][px] = v;
        s1 += v; s2 += v * v;
    }
    s_part[0][cy][px] = s1; s_part[1][cy][px] = s2;
    __syncthreads();
    if (cy == 0) {
        float a = 0.f, bb = 0.f;
#pragma unroll
        for (int j = 0; j < 8; j++) { a += s_part[0][j][px]; bb += s_part[1][j][px]; }
        float mu = a * (1.f / 256.f);
        float var = bb * (1.f / 256.f) - mu * mu;
        s_mu[px] = mu; s_rs[px] = rsqrtf(var + EPSLN);
    }
    __syncthreads();
    float gg = g[t], bv = b[t];
    size_t rbase = (size_t)n * QLEN + p0;
#pragma unroll 4
    for (int pp = 0; pp < 32; pp++) {
        float val = (tile[t][pp] - s_mu[pp]) * s_rs[pp] * gg + bv;
        float vo = __shfl_down_sync(0xffffffffu, val, 1);
        if (!(t & 1)) {
            uint32_t h = pack_hi(val, vo);
            size_t o = (rbase + pp) * 128 + (t >> 1);
            g_qlnh[o] = h;
            g_qlnl[o] = pack_lo(val, vo, h);
        }
    }
}

// ---------------- K2: pack ALL 6 weights (262144 elems = 1024 blocks) ----------------
__global__ __launch_bounds__(256)
void k_pack_all(const float* __restrict__ wq, const float* __restrict__ wk,
                const float* __restrict__ wv, const float* __restrict__ wp,
                const float* __restrict__ w1, const float* __restrict__ w2)
{
    long i = (long)blockIdx.x * 256 + threadIdx.x;
    if (i >= 262144) return;
    const float* src; int sn, sk; long zo; int N, Kp; uint32_t *dh, *dl; long rem;
    if (i < 32768)       { rem = i;          src = wq; sn = 1;   sk = 256; zo = 0;  N = 256; Kp = 128; dh = g_pwq_h; dl = g_pwq_l; }
    else if (i < 65536)  { rem = i - 32768;  src = wk; sn = 256; sk = 1;   zo = 64; N = 256; Kp = 32;  dh = g_pwk_h; dl = g_pwk_l; }
    else if (i < 98304)  { rem = i - 65536;  src = wv; sn = 1;   sk = 256; zo = 64; N = 64;  Kp = 128; dh = g_pwv_h; dl = g_pwv_l; }
    else if (i < 131072) { rem = i - 98304;  src = wp; sn = 1;   sk = 256; zo = 0;  N = 256; Kp = 128; dh = g_pwp_h; dl = g_pwp_l; }
    else if (i < 196608) { rem = i - 131072; src = w1; sn = 1;   sk = 512; zo = 0;  N = 512; Kp = 128; dh = g_pw1_h; dl = g_pw1_l; }
    else                 { rem = i - 196608; src = w2; sn = 1;   sk = 256; zo = 0;  N = 256; Kp = 256; dh = g_pw2_h; dl = g_pw2_l; }
    long NK = (long)N * Kp;
    long z = rem / NK, j = rem - z * NK;
    int n = (int)(j / Kp), kp = (int)(j - (long)n * Kp);
    const float* s = src + z * zo;
    float x0 = s[(size_t)n * sn + (size_t)(2 * kp) * sk];
    float x1 = s[(size_t)n * sn + (size_t)(2 * kp + 1) * sk];
    uint32_t h = pack_hi(x0, x1);
    dh[rem] = h;
    dl[rem] = pack_lo(x0, x1, h);
}

// ---------------- pipelined bf16x2 tensor GEMM, tile 128x64, 2 CTA/SM ----------------
// flags: 1 fp32, 2 gelu, 4 fp16, 8 packed, 16 = 2-pass (skip B_lo fills AND mma).
#define STG_A_H 0
#define STG_A_L 16384
#define STG_B_H 32768
#define STG_B_L 40960
#define STG_SZ  49152
#define GSM     (2*STG_SZ)

__global__ __launch_bounds__(256, 2)
void bgemm3(int M, int N, int K,
            const uint32_t* __restrict__ Ah, const uint32_t* __restrict__ Al,
            int ldap, long aoz,
            const uint32_t* __restrict__ Bh, const uint32_t* __restrict__ Bl, long bzs,
            const float* __restrict__ bias, int bioz,
            float* __restrict__ Cf, __half* __restrict__ Chalf, int ldc, long coz,
            uint32_t* __restrict__ Ph, uint32_t* __restrict__ Pl, int ldp, long poz,
            int flags)
{
    extern __shared__ char smem[];
    uint32_t sbase = smem_u32(smem);
    int z = blockIdx.z;
    Ah += (size_t)z * aoz; Al += (size_t)z * aoz;
    Bh += (size_t)z * bzs; Bl += (size_t)z * bzs;
    if (bias) bias += (size_t)z * bioz;
    int Kp = K >> 1;
    const bool pass3 = !(flags & 16);

    int tid = threadIdx.x, lane = tid & 31, wid = tid >> 5;
    int wm = wid & 3, wn = wid >> 2;
    int g = lane >> 2, t = lane & 3;
    int bm = blockIdx.y * 128, bn = blockIdx.x * 64;

    float acc[2][4][4] = {};

    int frow0 = tid >> 3, fseg = tid & 7;

    auto fill = [&](int ch, int st) {
        uint32_t stb = sbase + st * STG_SZ;
        int kp0 = ch << 5;
#pragma unroll
        for (int x = 0; x < 4; x++) {
            int row = x * 32 + frow0;
            uint32_t soff = (uint32_t)(row * 128 + ((fseg ^ (row & 7)) << 4));
            size_t ga = (size_t)(bm + row) * ldap + kp0 + fseg * 4;
            cp16(stb + STG_A_H + soff, Ah + ga, true);
            cp16(stb + STG_A_L + soff, Al + ga, true);
        }
#pragma unroll
        for (int x = 0; x < 2; x++) {
            int row = x * 32 + frow0;
            uint32_t soff = (uint32_t)(row * 128 + ((fseg ^ (row & 7)) << 4));
            bool bvld = (bn + row) < N;
            size_t gb = bvld ? ((size_t)(bn + row) * Kp + kp0 + fseg * 4) : 0;
            cp16(stb + STG_B_H + soff, Bh + gb, bvld);
            if (pass3) cp16(stb + STG_B_L + soff, Bl + gb, bvld);
        }
    };

    auto compute = [&](int st) {
        uint32_t stb = sbase + st * STG_SZ;
#pragma unroll
        for (int ks = 0; ks < 4; ks++) {
            int s0 = ks * 2;
            uint32_t ah[2][4], al[2][4];
#pragma unroll
            for (int i = 0; i < 2; i++) {
                int ml = wm * 32 + i * 16 + (lane & 15);
                int seg = s0 + (lane >> 4);
                uint32_t off = (uint32_t)(ml * 128 + ((seg ^ (ml & 7)) << 4));
                ldsm_x4(ah[i], stb + STG_A_H + off);
                ldsm_x4(al[i], stb + STG_A_L + off);
            }
#pragma unroll
            for (int j2 = 0; j2 < 2; j2++) {
                int nl = wn * 32 + j2 * 16 + (lane & 15);
                int seg = s0 + (lane >> 4);
                uint32_t off = (uint32_t)(nl * 128 + ((seg ^ (nl & 7)) << 4));
                uint32_t bh[4], bl[4];
                ldsm_x4(bh, stb + STG_B_H + off);
                if (pass3) ldsm_x4(bl, stb + STG_B_L + off);
#pragma unroll
                for (int jj = 0; jj < 2; jj++) {
                    int j = j2 * 2 + jj;
                    uint32_t bh0 = jj ? bh[1] : bh[0];
                    uint32_t bh1 = jj ? bh[3] : bh[2];
#pragma unroll
                    for (int i = 0; i < 2; i++) {
                        mma16(acc[i][j], ah[i], bh0, bh1);
                        mma16(acc[i][j], al[i], bh0, bh1);
                        if (pass3) {
                            uint32_t bl0 = jj ? bl[1] : bl[0];
                            uint32_t bl1 = jj ? bl[3] : bl[2];
                            mma16(acc[i][j], ah[i], bl0, bl1);
                        }
                    }
                }
            }
        }
    };

    int nch = K >> 6;
    fill(0, 0);
    asm volatile("cp.async.commit_group;" ::: "memory");
    for (int c = 0; c < nch; c++) {
        if (c + 1 < nch) {
            fill(c + 1, (c + 1) & 1);
            asm volatile("cp.async.commit_group;" ::: "memory");
            asm volatile("cp.async.wait_group 1;" ::: "memory");
        } else {
            asm volatile("cp.async.wait_group 0;" ::: "memory");
        }
        __syncthreads();
        compute(c & 1);
        __syncthreads();
    }

    // ---- epilogue ----
#pragma unroll
    for (int i = 0; i < 2; i++) {
        int r0 = bm + wm * 32 + i * 16 + g;
#pragma unroll
        for (int j = 0; j < 4; j++) {
            int c0 = bn + wn * 32 + j * 8 + t * 2;
            if (c0 >= N) continue;
            float b0v = bias ? bias[c0] : 0.f;
            float b1v = bias ? bias[c0 + 1] : 0.f;
            float v0 = acc[i][j][0] + b0v;
            float v1 = acc[i][j][1] + b1v;
            float v2 = acc[i][j][2] + b0v;
            float v3 = acc[i][j][3] + b1v;
            if (flags & 2) {
                v0 = 0.5f * v0 * (1.f + erff(v0 * 0.70710678118654752f));
                v1 = 0.5f * v1 * (1.f + erff(v1 * 0.70710678118654752f));
                v2 = 0.5f * v2 * (1.f + erff(v2 * 0.70710678118654752f));
                v3 = 0.5f * v3 * (1.f + erff(v3 * 0.70710678118654752f));
            }
            if (flags & 1) {
                float* C = Cf + (size_t)z * coz;
                *(float2*)&C[(size_t)r0 * ldc + c0]       = make_float2(v0, v1);
                *(float2*)&C[(size_t)(r0 + 8) * ldc + c0] = make_float2(v2, v3);
            }
            if (flags & 4) {
                __half* C = Chalf + (size_t)z * coz;
                *(__half2*)&C[(size_t)r0 * ldc + c0]       = __floats2half2_rn(v0, v1);
                *(__half2*)&C[(size_t)(r0 + 8) * ldc + c0] = __floats2half2_rn(v2, v3);
            }
            if (flags & 8) {
                uint32_t* PH = Ph + (size_t)z * poz;
                uint32_t* PL = Pl + (size_t)z * poz;
                int pidx = c0 >> 1;
                uint32_t h0 = pack_hi(v0, v1);
                PH[(size_t)r0 * ldp + pidx] = h0;
                PL[(size_t)r0 * ldp + pidx] = pack_lo(v0, v1, h0);
                uint32_t h1 = pack_hi(v2, v3);
                PH[(size_t)(r0 + 8) * ldp + pidx] = h1;
                PL[(size_t)(r0 + 8) * ldp + pidx] = pack_lo(v2, v3, h1);
            }
        }
    }
}

// ---------------- specialized qp GEMM: B resident (hi only), 2 M-blocks/CTA ----------------
#define Q_AH  0
#define Q_AL  16384
#define Q_STG 32768
#define Q_B   65536
#define QGSM  (65536 + 32768)

__global__ __launch_bounds__(256, 2)
void qgemm(const uint32_t* __restrict__ Ah, const uint32_t* __restrict__ Al,
           const uint32_t* __restrict__ Bh, const float* __restrict__ bias,
           uint32_t* __restrict__ Ph, uint32_t* __restrict__ Pl)
{
    extern __shared__ char smem[];
    uint32_t sbase = smem_u32(smem);
    int tid = threadIdx.x, lane = tid & 31, wid = tid >> 5;
    int wm = wid & 3, wn = wid >> 2;
    int g = lane >> 2, t = lane & 3;
    int bn = blockIdx.x * 64;
    int bm0 = blockIdx.y * 256;

#pragma unroll
    for (int i = 0; i < 8; i++) {
        int u = i * 256 + tid;
        int kc = u >> 9;
        int rem = u & 511;
        int row = rem >> 3, seg = rem & 7;
        uint32_t soff = (uint32_t)(kc * 8192 + row * 128 + ((seg ^ (row & 7)) << 4));
        cp16(sbase + Q_B + soff, Bh + (size_t)(bn + row) * 128 + kc * 32 + seg * 4, true);
    }
    int frow0 = tid >> 3, fseg = tid & 7;
    auto fillA = [&](int s, int st) {
        uint32_t stb = sbase + st * Q_STG;
        int bm = bm0 + (s >> 2) * 128;
        int kp0 = (s & 3) << 5;
#pragma unroll
        for (int x = 0; x < 4; x++) {
            int row = x * 32 + frow0;
            uint32_t soff = (uint32_t)(row * 128 + ((fseg ^ (row & 7)) << 4));
            size_t ga = (size_t)(bm + row) * 128 + kp0 + fseg * 4;
            cp16(stb + Q_AH + soff, Ah + ga, true);
            cp16(stb + Q_AL + soff, Al + ga, true);
        }
    };

    float acc[2][4][4] = {};
    fillA(0, 0);
    asm volatile("cp.async.commit_group;" ::: "memory");
    for (int s = 0; s < 8; s++) {
        if (s < 7) {
            fillA(s + 1, (s + 1) & 1);
            asm volatile("cp.async.commit_group;" ::: "memory");
            asm volatile("cp.async.wait_group 1;" ::: "memory");
        } else {
            asm volatile("cp.async.wait_group 0;" ::: "memory");
        }
        __syncthreads();
        uint32_t stb = sbase + (s & 1) * Q_STG;
        uint32_t bbase = sbase + Q_B + (uint32_t)((s & 3) * 8192);
#pragma unroll
        for (int ks = 0; ks < 4; ks++) {
            int s0 = ks * 2;
            uint32_t ah[2][4], al[2][4];
#pragma unroll
            for (int i = 0; i < 2; i++) {
                int ml = wm * 32 + i * 16 + (lane & 15);
                int seg = s0 + (lane >> 4);
                uint32_t off = (uint32_t)(ml * 128 + ((seg ^ (ml & 7)) << 4));
                ldsm_x4(ah[i], stb + Q_AH + off);
                ldsm_x4(al[i], stb + Q_AL + off);
            }
#pragma unroll
            for (int j2 = 0; j2 < 2; j2++) {
                int nl = wn * 32 + j2 * 16 + (lane & 15);
                int seg = s0 + (lane >> 4);
                uint32_t off = (uint32_t)(nl * 128 + ((seg ^ (nl & 7)) << 4));
                uint32_t bh[4];
                ldsm_x4(bh, bbase + off);
#pragma unroll
                for (int jj = 0; jj < 2; jj++) {
                    int j = j2 * 2 + jj;
                    uint32_t bh0 = jj ? bh[1] : bh[0];
                    uint32_t bh1 = jj ? bh[3] : bh[2];
#pragma unroll
                    for (int i = 0; i < 2; i++) {
                        mma16(acc[i][j], ah[i], bh0, bh1);
                        mma16(acc[i][j], al[i], bh0, bh1);
                    }
                }
            }
        }
        __syncthreads();
        if ((s & 3) == 3) {
            int bm = bm0 + (s >> 2) * 128;
#pragma unroll
            for (int i = 0; i < 2; i++) {
                int r0 = bm + wm * 32 + i * 16 + g;
#pragma unroll
                for (int j = 0; j < 4; j++) {
                    int c0 = bn + wn * 32 + j * 8 + t * 2;
                    float v0 = acc[i][j][0] + bias[c0];
                    float v1 = acc[i][j][1] + bias[c0 + 1];
                    float v2 = acc[i][j][2] + bias[c0];
                    float v3 = acc[i][j][3] + bias[c0 + 1];
                    int pidx = c0 >> 1;
                    uint32_t h0 = pack_hi(v0, v1);
                    Ph[(size_t)r0 * 128 + pidx] = h0;
                    Pl[(size_t)r0 * 128 + pidx] = pack_lo(v0, v1, h0);
                    uint32_t h1 = pack_hi(v2, v3);
                    Ph[(size_t)(r0 + 8) * 128 + pidx] = h1;
                    Pl[(size_t)(r0 + 8) * 128 + pidx] = pack_lo(v2, v3, h1);
                    acc[i][j][0] = acc[i][j][1] = acc[i][j][2] = acc[i][j][3] = 0.f;
                }
            }
        }
    }
}

// ---------------- specialized t-GEMM: K=64, B reused across 4 M-blocks, pipelined ----------------
#define T_AH  0
#define T_AL  16384
#define T_STG 32768
#define T_B   65536
#define TGSM  (65536 + 8192)

__global__ __launch_bounds__(256, 2)
void tgemm_t(const uint32_t* __restrict__ Ah, const uint32_t* __restrict__ Al,
             const uint32_t* __restrict__ Bh, __half* __restrict__ C)
{
    extern __shared__ char smem[];
    uint32_t sbase = smem_u32(smem);
    int z = blockIdx.z;
    Ah += (size_t)z * 32; Al += (size_t)z * 32;
    Bh += (size_t)z * (256 * 32);
    C  += (size_t)z * 256;

    int tid = threadIdx.x, lane = tid & 31, wid = tid >> 5;
    int wm = wid & 3, wn = wid >> 2;
    int g = lane >> 2, t = lane & 3;
    int bn = blockIdx.x * 64;
    int bm0 = blockIdx.y * 512;

#pragma unroll
    for (int i = 0; i < 2; i++) {
        int u = i * 256 + tid;
        int row = u >> 3, seg = u & 7;
        uint32_t soff = (uint32_t)(row * 128 + ((seg ^ (row & 7)) << 4));
        cp16(sbase + T_B + soff, Bh + (size_t)(bn + row) * 32 + seg * 4, true);
    }
    auto fillA = [&](int rb, int st) {
        uint32_t stb = sbase + st * T_STG;
        int bm = bm0 + rb * 128;
#pragma unroll
        for (int i = 0; i < 4; i++) {
            int u = i * 256 + tid;
            int row = u >> 3, seg = u & 7;
            uint32_t soff = (uint32_t)(row * 128 + ((seg ^ (row & 7)) << 4));
            size_t ga = (size_t)(bm + row) * 128 + seg * 4;
            cp16(stb + T_AH + soff, Ah + ga, true);
            cp16(stb + T_AL + soff, Al + ga, true);
        }
    };

    float acc[2][4][4] = {};
    fillA(0, 0);
    asm volatile("cp.async.commit_group;" ::: "memory");
    for (int rb = 0; rb < 4; rb++) {
        if (rb < 3) {
            fillA(rb + 1, (rb + 1) & 1);
            asm volatile("cp.async.commit_group;" ::: "memory");
            asm volatile("cp.async.wait_group 1;" ::: "memory");
        } else {
            asm volatile("cp.async.wait_group 0;" ::: "memory");
        }
        __syncthreads();
        uint32_t stb = sbase + (rb & 1) * T_STG;
#pragma unroll
        for (int ks = 0; ks < 4; ks++) {
            int s0 = ks * 2;
            uint32_t ah[2][4], al[2][4];
#pragma unroll
            for (int i = 0; i < 2; i++) {
                int ml = wm * 32 + i * 16 + (lane & 15);
                int seg = s0 + (lane >> 4);
                uint32_t off = (uint32_t)(ml * 128 + ((seg ^ (ml & 7)) << 4));
                ldsm_x4(ah[i], stb + T_AH + off);
                ldsm_x4(al[i], stb + T_AL + off);
            }
#pragma unroll
            for (int j2 = 0; j2 < 2; j2++) {
                int nl = wn * 32 + j2 * 16 + (lane & 15);
                int seg = s0 + (lane >> 4);
                uint32_t off = (uint32_t)(nl * 128 + ((seg ^ (nl & 7)) << 4));
                uint32_t bh[4];
                ldsm_x4(bh, sbase + T_B + off);
#pragma unroll
                for (int jj = 0; jj < 2; jj++) {
                    int j = j2 * 2 + jj;
                    uint32_t bh0 = jj ? bh[1] : bh[0];
                    uint32_t bh1 = jj ? bh[3] : bh[2];
#pragma unroll
                    for (int i = 0; i < 2; i++) {
                        mma16(acc[i][j], ah[i], bh0, bh1);
                        mma16(acc[i][j], al[i], bh0, bh1);
                    }
                }
            }
        }
        int bm = bm0 + rb * 128;
#pragma unroll
        for (int i = 0; i < 2; i++) {
            int r0 = bm + wm * 32 + i * 16 + g;
#pragma unroll
            for (int j = 0; j < 4; j++) {
                int c0 = bn + wn * 32 + j * 8 + t * 2;
                *(__half2*)&C[(size_t)r0 * 1024 + c0]       = __floats2half2_rn(acc[i][j][0], acc[i][j][1]);
                *(__half2*)&C[(size_t)(r0 + 8) * 1024 + c0] = __floats2half2_rn(acc[i][j][2], acc[i][j][3]);
                acc[i][j][0] = acc[i][j][1] = acc[i][j][2] = acc[i][j][3] = 0.f;
            }
        }
        __syncthreads();
    }
}

// ---------------- K4: attention scores, 2 rows per CTA ----------------
__global__ __launch_bounds__(256)
void k_dot2(const float* __restrict__ kten,
            const uint32_t* __restrict__ qph, const uint32_t* __restrict__ qpl,
            const __half* __restrict__ tg, const float* __restrict__ bk,
            const float* __restrict__ lng, const float* __restrict__ lnb,
            const float* __restrict__ maskf, float* __restrict__ dotp)
{
    int i = blockIdx.x;                     // 0..12287
    int rr[2] = {i, i + 12288};
    int tid = threadIdx.x, lane = tid & 31, w = tid >> 5;
    __shared__ float ts[2][1024];
    __shared__ float bd[2][4];
    __shared__ float sg[256], sb[256];
    // stage both t rows
#pragma unroll
    for (int p = 0; p < 2; p++) {
        uint2 tu = *(const uint2*)(tg + (size_t)rr[p] * 1024 + tid * 4);
        __half2 h0 = *reinterpret_cast<__half2*>(&tu.x);
        __half2 h1 = *reinterpret_cast<__half2*>(&tu.y);
        float2 f0 = __half22float2(h0);
        float2 f1 = __half22float2(h1);
        ts[p][tid * 4 + 0] = f0.x;
        ts[p][tid * 4 + 1] = f0.y;
        ts[p][tid * 4 + 2] = f1.x;
        ts[p][tid * 4 + 3] = f1.y;
    }
    sg[tid] = lng[tid]; sb[tid] = lnb[tid];
    // bias dots: all 8 warps busy — warp w: row p=w>>2, head m=w&3
    {
        int p = w >> 2, m = w & 3;
        uint32_t hh = qph[(size_t)rr[p] * 128 + m * 32 + lane];
        uint32_t ll = qpl[(size_t)rr[p] * 128 + m * 32 + lane];
        __nv_bfloat162 h2 = *reinterpret_cast<__nv_bfloat162*>(&hh);
        __nv_bfloat162 l2 = *reinterpret_cast<__nv_bfloat162*>(&ll);
        float a0 = __bfloat162float(h2.x) + __bfloat162float(l2.x);
        float a1 = __bfloat162float(h2.y) + __bfloat162float(l2.y);
        const float* bkr = bk + m * 64;
        float p1 = a0 * bkr[2 * lane] + a1 * bkr[2 * lane + 1];
#pragma unroll
        for (int o = 16; o > 0; o >>= 1) p1 += __shfl_xor_sync(0xffffffffu, p1, o);
        if (lane == 0) bd[p][m] = p1;
    }
    __syncthreads();
    // k rows: warp w = group w for BOTH rows, interleaved loads
    const float* krA = kten + ((size_t)rr[0] * GRP + w) * 256;
    const float* krB = kten + ((size_t)rr[1] * GRP + w) * 256;
    float vA[8], vB[8];
    float sA1 = 0.f, sA2 = 0.f, sB1 = 0.f, sB2 = 0.f;
#pragma unroll
    for (int j = 0; j < 8; j++) {
        vA[j] = krA[lane + 32 * j];
        vB[j] = krB[lane + 32 * j];
    }
#pragma unroll
    for (int j = 0; j < 8; j++) {
        sA1 += vA[j]; sA2 += vA[j] * vA[j];
        sB1 += vB[j]; sB2 += vB[j] * vB[j];
    }
#pragma unroll
    for (int o = 16; o > 0; o >>= 1) {
        sA1 += __shfl_xor_sync(0xffffffffu, sA1, o);
        sA2 += __shfl_xor_sync(0xffffffffu, sA2, o);
        sB1 += __shfl_xor_sync(0xffffffffu, sB1, o);
        sB2 += __shfl_xor_sync(0xffffffffu, sB2, o);
    }
    float muA = sA1 * (1.f / 256.f);
    float rsA = rsqrtf(sA2 * (1.f / 256.f) - muA * muA + EPSLN);
    float muB = sB1 * (1.f / 256.f);
    float rsB = rsqrtf(sB2 * (1.f / 256.f) - muB * muB + EPSLN);
    float dA[4] = {}, dB[4] = {};
#pragma unroll
    for (int j = 0; j < 8; j++) {
        int c = lane + 32 * j;
        float gA = sg[c], bA2 = sb[c];
        float lvA = (vA[j] - muA) * rsA * gA + bA2;
        float lvB = (vB[j] - muB) * rsB * gA + bA2;
#pragma unroll
        for (int m = 0; m < 4; m++) {
            dA[m] += lvA * ts[0][m * 256 + c];
            dB[m] += lvB * ts[1][m * 256 + c];
        }
    }
#pragma unroll
    for (int o = 16; o > 0; o >>= 1) {
#pragma unroll
        for (int m = 0; m < 4; m++) {
            dA[m] += __shfl_xor_sync(0xffffffffu, dA[m], o);
            dB[m] += __shfl_xor_sync(0xffffffffu, dB[m], o);
        }
    }
    if (lane == 0) {
#pragma unroll
        for (int p = 0; p < 2; p++) {
            int r = rr[p];
            int n = r >> 12, q = r & 4095;
            bool mk = maskf[r] != 0.f;
            size_t base = (size_t)q * (HEADS * NKEY) + (size_t)n * GRP + w;
            float* dm = p ? dB : dA;
#pragma unroll
            for (int m = 0; m < 4; m++)
                dotp[base + (size_t)m * NKEY] = mk ? SCALE * (dm[m] + bd[p][m]) : -1e9f;
        }
    }
}

// ---------------- K6: softmax (fused) + weighted sum of LN(v) -> packed ----------------
__global__ __launch_bounds__(256)
void k_vacc(const float* __restrict__ vten, const float* __restrict__ dotp,
            const float* __restrict__ lng, const float* __restrict__ lnb)
{
    __shared__ float sa[HEADS * NKEY];
    __shared__ float part[8][1024];
    int q = blockIdx.x, tid = threadIdx.x, lane = tid & 31, w = tid >> 5;
    if (w < 4) {
        const float* p = dotp + (size_t)q * (HEADS * NKEY) + w * NKEY;
        float v0 = p[lane];
        float v1 = (lane < 16) ? p[32 + lane] : -3.4e38f;
        float mx = fmaxf(v0, v1);
#pragma unroll
        for (int o = 16; o > 0; o >>= 1) mx = fmaxf(mx, __shfl_xor_sync(0xffffffffu, mx, o));
        float e0 = expf(v0 - mx);
        float e1 = (lane < 16) ? expf(v1 - mx) : 0.f;
        float s = e0 + e1;
#pragma unroll
        for (int o = 16; o > 0; o >>= 1) s += __shfl_xor_sync(0xffffffffu, s, o);
        float inv = 1.f / s;
        sa[w * NKEY + lane] = e0 * inv;
        if (lane < 16) sa[w * NKEY + 32 + lane] = e1 * inv;
    }
    int c0 = lane * 8;
    float gv[8], bb[8];
    {
        float4 gA = *(const float4*)(lng + c0);
        float4 gB = *(const float4*)(lng + c0 + 4);
        float4 bA = *(const float4*)(lnb + c0);
        float4 bB = *(const float4*)(lnb + c0 + 4);
        gv[0]=gA.x; gv[1]=gA.y; gv[2]=gA.z; gv[3]=gA.w;
        gv[4]=gB.x; gv[5]=gB.y; gv[6]=gB.z; gv[7]=gB.w;
        bb[0]=bA.x; bb[1]=bA.y; bb[2]=bA.z; bb[3]=bA.w;
        bb[4]=bB.x; bb[5]=bB.y; bb[6]=bB.z; bb[7]=bB.w;
    }
    __syncthreads();
    float acc[4][8] = {};
#pragma unroll
    for (int n = 0; n < NFR; n++) {
        const float* vr = vten + (((size_t)n * QLEN + q) * GRP + w) * 256 + c0;
        float4 v0 = *(const float4*)vr;
        float4 v1 = *(const float4*)(vr + 4);
        float vv[8] = {v0.x, v0.y, v0.z, v0.w, v1.x, v1.y, v1.z, v1.w};
        float s1 = 0.f, s2 = 0.f;
#pragma unroll
        for (int j = 0; j < 8; j++) { s1 += vv[j]; s2 += vv[j] * vv[j]; }
#pragma unroll
        for (int o = 16; o > 0; o >>= 1) {
            s1 += __shfl_xor_sync(0xffffffffu, s1, o);
            s2 += __shfl_xor_sync(0xffffffffu, s2, o);
        }
        float mu = s1 * (1.f / 256.f);
        float rs = rsqrtf(s2 * (1.f / 256.f) - mu * mu + EPSLN);
        float aw0 = sa[0 * NKEY + n * 8 + w];
        float aw1 = sa[1 * NKEY + n * 8 + w];
        float aw2 = sa[2 * NKEY + n * 8 + w];
        float aw3 = sa[3 * NKEY + n * 8 + w];
#pragma unroll
        for (int j = 0; j < 8; j++) {
            float lv = (vv[j] - mu) * rs * gv[j] + bb[j];
            acc[0][j] += aw0 * lv;
            acc[1][j] += aw1 * lv;
            acc[2][j] += aw2 * lv;
            acc[3][j] += aw3 * lv;
        }
    }
#pragma unroll
    for (int m = 0; m < 4; m++) {
        float4 p0 = make_float4(acc[m][0], acc[m][1], acc[m][2], acc[m][3]);
        float4 p1 = make_float4(acc[m][4], acc[m][5], acc[m][6], acc[m][7]);
        *(float4*)&part[w][m * 256 + c0]     = p0;
        *(float4*)&part[w][m * 256 + c0 + 4] = p1;
    }
    __syncthreads();
#pragma unroll
    for (int m = 0; m < 4; m++) {
        float s = 0.f;
#pragma unroll
        for (int w8 = 0; w8 < 8; w8++) s += part[w8][m * 256 + tid];
        float so = __shfl_down_sync(0xffffffffu, s, 1);
        if (!(tid & 1)) {
            uint32_t h = pack_hi(s, so);
            size_t o = (size_t)q * 512 + m * 128 + (tid >> 1);
            g_apreh[o] = h;
            g_aprel[o] = pack_lo(s, so, h);
        }
    }
}

// ---------------- K7: z = LN_pre(zp + skip^T) -> fp32 + packed ----------------
__global__ __launch_bounds__(256)
void k_ln_skip(const float* __restrict__ zp, const float* __restrict__ skip,
               const float* __restrict__ g, const float* __restrict__ b,
               float* __restrict__ zln)
{
    __shared__ float red[16];
    int q = blockIdx.x, c = threadIdx.x;
    float v = zp[(size_t)q * 256 + c] + skip[(size_t)c * QLEN + q];
    float s1 = v, s2 = v * v;
    blockReduce2(s1, s2, red);
    float mu = s1 * (1.f / 256.f);
    float rs = rsqrtf(s2 * (1.f / 256.f) - mu * mu + EPSLN);
    float val = (v - mu) * rs * g[c] + b[c];
    zln[(size_t)q * 256 + c] = val;
    float vo = __shfl_down_sync(0xffffffffu, val, 1);
    if (!(c & 1)) {
        uint32_t h = pack_hi(val, vo);
        size_t o = (size_t)q * 128 + (c >> 1);
        g_zlnh[o] = h;
        g_zlnl[o] = pack_lo(val, vo, h);
    }
}

// ---------------- K8: out = LN_post(zln + hp), transposed store ----------------
__global__ __launch_bounds__(256)
void k_ln_out(const float* __restrict__ zln, const float* __restrict__ hp,
              const float* __restrict__ g, const float* __restrict__ b,
              float* __restrict__ out)
{
    __shared__ float red[16];
    int q = blockIdx.x, c = threadIdx.x;
    float v = zln[(size_t)q * 256 + c] + hp[(size_t)q * 256 + c];
    float s1 = v, s2 = v * v;
    blockReduce2(s1, s2, red);
    float mu = s1 * (1.f / 256.f);
    float rs = rsqrtf(s2 * (1.f / 256.f) - mu * mu + EPSLN);
    out[(size_t)c * QLEN + q] = (v - mu) * rs * g[c] + b[c];
}

// ---------------- host launch ----------------
extern "C" void kernel_launch(void* const* d_in, const int* in_sizes, int n_in,
                              void* d_out, int out_size)
{
    const float* q        = (const float*)d_in[0];
    const float* k        = (const float*)d_in[1];
    const float* v        = (const float*)d_in[2];
    const float* skip     = (const float*)d_in[3];
    const void*  mask     = d_in[4];
    const float* ln_q_g   = (const float*)d_in[5];
    const float* ln_q_b   = (const float*)d_in[6];
    const float* wq       = (const float*)d_in[7];
    const float* bq       = (const float*)d_in[8];
    const float* ln_k_g   = (const float*)d_in[9];
    const float* ln_k_b   = (const float*)d_in[10];
    const float* wk       = (const float*)d_in[11];
    const float* bk       = (const float*)d_in[12];
    const float* ln_v_g   = (const float*)d_in[13];
    const float* ln_v_b   = (const float*)d_in[14];
    const float* wv       = (const float*)d_in[15];
    const float* bv       = (const float*)d_in[16];
    const float* w_proj   = (const float*)d_in[17];
    const float* b_proj   = (const float*)d_in[18];
    const float* ln_pre_g = (const float*)d_in[19];
    const float* ln_pre_b = (const float*)d_in[20];
    const float* w_mlp1   = (const float*)d_in[21];
    const float* b_mlp1   = (const float*)d_in[22];
    const float* w_mlp2   = (const float*)d_in[23];
    const float* b_mlp2   = (const float*)d_in[24];
    const float* ln_post_g= (const float*)d_in[25];
    const float* ln_post_b= (const float*)d_in[26];
    float* out = (float*)d_out;

    float *dot, *zp, *zln, *hp, *maskf;
    __half* t;
    uint32_t *qlnh, *qlnl, *qph, *qpl, *apreh, *aprel, *avh, *avl, *zlnh, *zlnl, *h1h, *h1l;
    uint32_t *pwq_h, *pwq_l, *pwk_h, *pwk_l, *pwv_h, *pwv_l;
    uint32_t *pwp_h, *pwp_l, *pw1_h, *pw1_l, *pw2_h, *pw2_l;
    cudaGetSymbolAddress((void**)&qlnh, g_qlnh); cudaGetSymbolAddress((void**)&qlnl, g_qlnl);
    cudaGetSymbolAddress((void**)&qph,  g_qph);  cudaGetSymbolAddress((void**)&qpl,  g_qpl);
    cudaGetSymbolAddress((void**)&t,    g_t);
    cudaGetSymbolAddress((void**)&dot,  g_dot);
    cudaGetSymbolAddress((void**)&apreh,g_apreh);cudaGetSymbolAddress((void**)&aprel,g_aprel);
    cudaGetSymbolAddress((void**)&avh,  g_avh);  cudaGetSymbolAddress((void**)&avl,  g_avl);
    cudaGetSymbolAddress((void**)&zp,   g_zp);
    cudaGetSymbolAddress((void**)&zln,  g_zln);
    cudaGetSymbolAddress((void**)&zlnh, g_zlnh); cudaGetSymbolAddress((void**)&zlnl, g_zlnl);
    cudaGetSymbolAddress((void**)&h1h,  g_h1h);  cudaGetSymbolAddress((void**)&h1l,  g_h1l);
    cudaGetSymbolAddress((void**)&hp,   g_hp);
    cudaGetSymbolAddress((void**)&maskf,g_maskf);
    cudaGetSymbolAddress((void**)&pwq_h, g_pwq_h); cudaGetSymbolAddress((void**)&pwq_l, g_pwq_l);
    cudaGetSymbolAddress((void**)&pwk_h, g_pwk_h); cudaGetSymbolAddress((void**)&pwk_l, g_pwk_l);
    cudaGetSymbolAddress((void**)&pwv_h, g_pwv_h); cudaGetSymbolAddress((void**)&pwv_l, g_pwv_l);
    cudaGetSymbolAddress((void**)&pwp_h, g_pwp_h); cudaGetSymbolAddress((void**)&pwp_l, g_pwp_l);
    cudaGetSymbolAddress((void**)&pw1_h, g_pw1_h); cudaGetSymbolAddress((void**)&pw1_l, g_pw1_l);
    cudaGetSymbolAddress((void**)&pw2_h, g_pw2_h); cudaGetSymbolAddress((void**)&pw2_l, g_pw2_l);

    cudaFuncSetAttribute(bgemm3, cudaFuncAttributeMaxDynamicSharedMemorySize, GSM);
    cudaFuncSetAttribute(tgemm_t, cudaFuncAttributeMaxDynamicSharedMemorySize, TGSM);
    cudaFuncSetAttribute(qgemm,  cudaFuncAttributeMaxDynamicSharedMemorySize, QGSM);

    // 1
    k_mask<<<1, 256>>>((const unsigned char*)mask);
    // 2: q transpose + LN -> packed
    k_q_ln<<<dim3(QLEN / 32, NFR), 256>>>(q, ln_q_g, ln_q_b);
    // 3: pack weights
    k_pack_all<<<1024, 256>>>(wq, wk, wv, w_proj, w_mlp1, w_mlp2);
    // 4: qp = qln @ wq + bq (specialized)
    qgemm<<<dim3(4, 96), 256, QGSM>>>(qlnh, qlnl, pwq_h, bq, qph, qpl);
    // 5: t_m = qp_m @ wk_m^T x4 heads -> fp16 (specialized)
    tgemm_t<<<dim3(4, 48, 4), 256, TGSM>>>(qph, qpl, pwk_h, t);
    // 6: attention scores, 2 rows per CTA
    k_dot2<<<R_TOT / 2, 256>>>(k, qph, qpl, t, bk, ln_k_g, ln_k_b, maskf, dot);
    // 7: softmax + weighted LN(v) sums -> packed apre
    k_vacc<<<QLEN, 256>>>(v, dot, ln_v_g, ln_v_b);
    // 8: a_m = apre_m @ wv_m + bv_m (N=64, K=256) x4 heads -> packed av
    bgemm3<<<dim3(1, 32, 4), 256, GSM>>>(QLEN, 64, 256,
                                         apreh, aprel, 512, 128,
                                         pwv_h, pwv_l, 64 * 128, bv, 64,
                                         nullptr, nullptr, 0, 0,
                                         avh, avl, 128, 32, 8);
    // 9: zp = av @ w_proj + b_proj -> fp32
    bgemm3<<<dim3(4, 32, 1), 256, GSM>>>(QLEN, 256, 256,
                                         avh, avl, 128, 0,
                                         pwp_h, pwp_l, 0, b_proj, 0,
                                         zp, nullptr, 256, 0,
                                         nullptr, nullptr, 0, 0, 1);
    // 10: zln = LN_pre(zp + skip) -> fp32 + packed
    k_ln_skip<<<QLEN, 256>>>(zp, skip, ln_pre_g, ln_pre_b, zln);
    // 11: h1 = gelu(zln @ w_mlp1 + b_mlp1) -> packed
    bgemm3<<<dim3(8, 32, 1), 256, GSM>>>(QLEN, 512, 256,
                                         zlnh, zlnl, 128, 0,
                                         pw1_h, pw1_l, 0, b_mlp1, 0,
                                         nullptr, nullptr, 0, 0,
                                         h1h, h1l, 256, 0, 10);
    // 12: hp = h1 @ w_mlp2 + b_mlp2 -> fp32
    bgemm3<<<dim3(4, 32, 1), 256, GSM>>>(QLEN, 256, 512,
                                         h1h, h1l, 256, 0,
                                         pw2_h, pw2_l, 0, b_mlp2, 0,
                                         hp, nullptr, 256, 0,
                                         nullptr, nullptr, 0, 0, 1);
    // 13
    k_ln_out<<<QLEN, 256>>>(zln, hp, ln_post_g, ln_post_b, out);
}